// round 1
// baseline (speedup 1.0000x reference)
#include <cuda_runtime.h>
#include <cuda_bf16.h>
#include <math_constants.h>

// Problem constants
#define NB 16
#define LQ 4096          // L = 64*64
#define DD 512           // D
#define CC 512           // 2*Cin
#define UU 450           // u = top-k count = sample count
#define UP 512           // padded U
#define PER_BATCH (LQ*DD)   // 2097152

// ---------------- device scratch (static, no allocation) ----------------
__device__ float g_q[(size_t)NB*PER_BATCH];
__device__ float g_k[(size_t)NB*PER_BATCH];
__device__ float g_v[(size_t)NB*PER_BATCH];
__device__ float g_S[(size_t)NB*PER_BATCH];        // reused: QKs [l][512] then scores/attn [u][4096]
__device__ float g_ksamp[(size_t)NB*UP*DD];
__device__ float g_qr[(size_t)NB*UP*DD];
__device__ float g_upd[(size_t)NB*UP*DD];
__device__ float g_M[NB*LQ];
__device__ int   g_topk[NB*UP];
__device__ float g_vpart[NB*16*DD];
__device__ float g_vmean[NB*DD];

// ---------------- 1) projections: Y = W @ X + b  (per batch, per matrix) ----------------
// Y stored [o][s] row-major == Q/K/V [l][d] row-major (aliasing, see analysis)
__global__ __launch_bounds__(256) void k_proj(
    const float* __restrict__ in1, const float* __restrict__ in2,
    const float* __restrict__ Wq, const float* __restrict__ bq,
    const float* __restrict__ Wk, const float* __restrict__ bk,
    const float* __restrict__ Wv, const float* __restrict__ bv)
{
    int z = blockIdx.z;
    int m = z % 3, b = z / 3;
    const float* W    = (m == 0) ? Wq : (m == 1) ? Wk : Wv;
    const float* bias = (m == 0) ? bq : (m == 1) ? bk : bv;
    float* out = ((m == 0) ? g_q : (m == 1) ? g_k : g_v) + (size_t)b * PER_BATCH;
    const float* x1 = in1 + (size_t)b * 256 * LQ;
    const float* x2 = in2 + (size_t)b * 256 * LQ;

    int s0 = blockIdx.x * 64, o0 = blockIdx.y * 64;
    __shared__ float As[16][64];   // [c][o]
    __shared__ float Bs[16][64];   // [c][s]
    int tid = threadIdx.x;
    int tx = tid & 15, ty = tid >> 4;
    float acc[4][4] = {};

    for (int k0 = 0; k0 < CC; k0 += 16) {
        {   // A: W[o0+r][k0+g*4 ..]
            int r = tid >> 2, g = tid & 3;
            float4 w = *(const float4*)(W + (size_t)(o0 + r) * CC + k0 + g * 4);
            As[g*4+0][r] = w.x; As[g*4+1][r] = w.y; As[g*4+2][r] = w.z; As[g*4+3][r] = w.w;
        }
        {   // B: X[k0+c][s0+g2*4 ..]   (c<256 -> input_1, else input_2)
            int c = tid >> 4, g2 = tid & 15;
            int cg = k0 + c;
            const float* xr = (cg < 256) ? (x1 + (size_t)cg * LQ) : (x2 + (size_t)(cg - 256) * LQ);
            float4 v = *(const float4*)(xr + s0 + g2 * 4);
            *(float4*)&Bs[c][g2 * 4] = v;
        }
        __syncthreads();
        #pragma unroll
        for (int kk = 0; kk < 16; kk++) {
            float a[4], bb[4];
            #pragma unroll
            for (int i = 0; i < 4; i++) a[i]  = As[kk][ty * 4 + i];
            #pragma unroll
            for (int j = 0; j < 4; j++) bb[j] = Bs[kk][tx * 4 + j];
            #pragma unroll
            for (int i = 0; i < 4; i++)
                #pragma unroll
                for (int j = 0; j < 4; j++) acc[i][j] += a[i] * bb[j];
        }
        __syncthreads();
    }
    #pragma unroll
    for (int i = 0; i < 4; i++) {
        int o = o0 + ty * 4 + i;
        float bv_ = bias[o];
        #pragma unroll
        for (int j = 0; j < 4; j++)
            out[(size_t)o * LQ + s0 + tx * 4 + j] = acc[i][j] + bv_;
    }
}

// ---------------- 2) gather K_sample (pad rows [450,512) with zeros) ----------------
__global__ void k_gather_ks(const int* __restrict__ idx)
{
    int b = blockIdx.y, s = blockIdx.x;
    float* dst = g_ksamp + ((size_t)b * UP + s) * DD;
    if (s < UU) {
        const float* src = g_k + (size_t)b * PER_BATCH + (size_t)idx[s] * DD;
        for (int d = threadIdx.x; d < DD; d += blockDim.x) dst[d] = src[d];
    } else {
        for (int d = threadIdx.x; d < DD; d += blockDim.x) dst[d] = 0.f;
    }
}

// ---------------- 3) QKs = Q @ Ks^T  -> g_S[b][l*512 + s] ----------------
__global__ __launch_bounds__(256) void k_qks()
{
    int b = blockIdx.z;
    const float* Q  = g_q     + (size_t)b * PER_BATCH;
    const float* Ks = g_ksamp + (size_t)b * UP * DD;
    float* Sout     = g_S     + (size_t)b * PER_BATCH;
    int l0 = blockIdx.y * 64, s0 = blockIdx.x * 64;
    __shared__ float As[16][64];   // [d][l]
    __shared__ float Bs[16][64];   // [d][s]
    int tid = threadIdx.x;
    int tx = tid & 15, ty = tid >> 4;
    float acc[4][4] = {};
    for (int k0 = 0; k0 < DD; k0 += 16) {
        int r = tid >> 2, g = tid & 3;
        float4 a = *(const float4*)(Q  + (size_t)(l0 + r) * DD + k0 + g * 4);
        As[g*4+0][r] = a.x; As[g*4+1][r] = a.y; As[g*4+2][r] = a.z; As[g*4+3][r] = a.w;
        float4 c = *(const float4*)(Ks + (size_t)(s0 + r) * DD + k0 + g * 4);
        Bs[g*4+0][r] = c.x; Bs[g*4+1][r] = c.y; Bs[g*4+2][r] = c.z; Bs[g*4+3][r] = c.w;
        __syncthreads();
        #pragma unroll
        for (int kk = 0; kk < 16; kk++) {
            float av[4], bb[4];
            #pragma unroll
            for (int i = 0; i < 4; i++) av[i] = As[kk][ty * 4 + i];
            #pragma unroll
            for (int j = 0; j < 4; j++) bb[j] = Bs[kk][tx * 4 + j];
            #pragma unroll
            for (int i = 0; i < 4; i++)
                #pragma unroll
                for (int j = 0; j < 4; j++) acc[i][j] += av[i] * bb[j];
        }
        __syncthreads();
    }
    #pragma unroll
    for (int i = 0; i < 4; i++)
        #pragma unroll
        for (int j = 0; j < 4; j++)
            Sout[(size_t)(l0 + ty * 4 + i) * UP + s0 + tx * 4 + j] = acc[i][j];
}

// ---------------- 4) M[l] = max_{s<450} QKs - sum_{s<450} QKs / 4096 ----------------
__global__ void k_mreduce()
{
    int b = blockIdx.y;
    int l = blockIdx.x * 8 + (threadIdx.x >> 5);
    int lane = threadIdx.x & 31;
    const float* row = g_S + (size_t)b * PER_BATCH + (size_t)l * UP;
    float mx = -CUDART_INF_F, sm = 0.f;
    for (int s = lane; s < UU; s += 32) { float v = row[s]; mx = fmaxf(mx, v); sm += v; }
    #pragma unroll
    for (int o = 16; o; o >>= 1) {
        mx = fmaxf(mx, __shfl_xor_sync(0xffffffffu, mx, o));
        sm += __shfl_xor_sync(0xffffffffu, sm, o);
    }
    if (lane == 0) g_M[b * LQ + l] = mx - sm * (1.0f / LQ);
}

// ---------------- 5) top-450 per batch via bitonic sort (descending) ----------------
__global__ __launch_bounds__(1024) void k_topk()
{
    __shared__ float sv[LQ];
    __shared__ int   si[LQ];
    int b = blockIdx.x;
    for (int i = threadIdx.x; i < LQ; i += 1024) { sv[i] = g_M[b * LQ + i]; si[i] = i; }
    __syncthreads();
    for (int k = 2; k <= LQ; k <<= 1) {
        for (int j = k >> 1; j > 0; j >>= 1) {
            for (int t = threadIdx.x; t < LQ / 2; t += 1024) {
                int i   = ((t & ~(j - 1)) << 1) | (t & (j - 1));
                int ixj = i | j;
                bool desc = ((i & k) == 0);
                float a = sv[i], c = sv[ixj];
                bool sw = desc ? (a < c) : (a > c);
                if (sw) {
                    sv[i] = c; sv[ixj] = a;
                    int ti = si[i]; si[i] = si[ixj]; si[ixj] = ti;
                }
            }
            __syncthreads();
        }
    }
    for (int u = threadIdx.x; u < UU; u += 1024) g_topk[b * UP + u] = si[u];
}

// ---------------- 6) gather Q_reduce (pad rows with zeros) ----------------
__global__ void k_gather_qr()
{
    int b = blockIdx.y, u = blockIdx.x;
    float* dst = g_qr + ((size_t)b * UP + u) * DD;
    if (u < UU) {
        int l = g_topk[b * UP + u];
        const float* src = g_q + (size_t)b * PER_BATCH + (size_t)l * DD;
        for (int d = threadIdx.x; d < DD; d += blockDim.x) dst[d] = src[d];
    } else {
        for (int d = threadIdx.x; d < DD; d += blockDim.x) dst[d] = 0.f;
    }
}

// ---------------- 7) scores = (Qr @ K^T) * 1/sqrt(512) -> g_S[b][u*4096 + l] ----------------
__global__ __launch_bounds__(256) void k_scores()
{
    const float alpha = 0.044194173824159216f;   // 1/sqrt(512)
    int b = blockIdx.z;
    const float* Qr = g_qr + (size_t)b * UP * DD;
    const float* K  = g_k  + (size_t)b * PER_BATCH;
    float* Sout     = g_S  + (size_t)b * PER_BATCH;
    int u0 = blockIdx.y * 64, l0 = blockIdx.x * 64;
    __shared__ float As[16][64];   // [d][u]
    __shared__ float Bs[16][64];   // [d][l]
    int tid = threadIdx.x;
    int tx = tid & 15, ty = tid >> 4;
    float acc[4][4] = {};
    for (int k0 = 0; k0 < DD; k0 += 16) {
        int r = tid >> 2, g = tid & 3;
        float4 a = *(const float4*)(Qr + (size_t)(u0 + r) * DD + k0 + g * 4);
        As[g*4+0][r] = a.x; As[g*4+1][r] = a.y; As[g*4+2][r] = a.z; As[g*4+3][r] = a.w;
        float4 c = *(const float4*)(K  + (size_t)(l0 + r) * DD + k0 + g * 4);
        Bs[g*4+0][r] = c.x; Bs[g*4+1][r] = c.y; Bs[g*4+2][r] = c.z; Bs[g*4+3][r] = c.w;
        __syncthreads();
        #pragma unroll
        for (int kk = 0; kk < 16; kk++) {
            float av[4], bb[4];
            #pragma unroll
            for (int i = 0; i < 4; i++) av[i] = As[kk][ty * 4 + i];
            #pragma unroll
            for (int j = 0; j < 4; j++) bb[j] = Bs[kk][tx * 4 + j];
            #pragma unroll
            for (int i = 0; i < 4; i++)
                #pragma unroll
                for (int j = 0; j < 4; j++) acc[i][j] += av[i] * bb[j];
        }
        __syncthreads();
    }
    #pragma unroll
    for (int i = 0; i < 4; i++)
        #pragma unroll
        for (int j = 0; j < 4; j++)
            Sout[(size_t)(u0 + ty * 4 + i) * LQ + l0 + tx * 4 + j] = acc[i][j] * alpha;
}

// ---------------- 8) softmax over l (in place, rows u<450) ----------------
__global__ __launch_bounds__(256) void k_softmax()
{
    int b = blockIdx.y, u = blockIdx.x;
    float* row = g_S + (size_t)b * PER_BATCH + (size_t)u * LQ;
    __shared__ float red[256];
    int t = threadIdx.x;
    float mx = -CUDART_INF_F;
    for (int l = t; l < LQ; l += 256) mx = fmaxf(mx, row[l]);
    red[t] = mx; __syncthreads();
    for (int o = 128; o; o >>= 1) { if (t < o) red[t] = fmaxf(red[t], red[t + o]); __syncthreads(); }
    mx = red[0]; __syncthreads();
    float sm = 0.f;
    for (int l = t; l < LQ; l += 256) { float e = expf(row[l] - mx); row[l] = e; sm += e; }
    red[t] = sm; __syncthreads();
    for (int o = 128; o; o >>= 1) { if (t < o) red[t] += red[t + o]; __syncthreads(); }
    float inv = 1.0f / red[0];
    for (int l = t; l < LQ; l += 256) row[l] *= inv;
}

// ---------------- 9) V column means (deterministic two-stage) ----------------
__global__ void k_vmean1()
{
    int b = blockIdx.y, c = blockIdx.x;
    const float* V = g_v + (size_t)b * PER_BATCH + (size_t)c * 256 * DD;
    int d = threadIdx.x;
    float acc = 0.f;
    #pragma unroll 4
    for (int l = 0; l < 256; l++) acc += V[l * DD + d];
    g_vpart[((size_t)b * 16 + c) * DD + d] = acc;
}
__global__ void k_vmean2()
{
    int b = blockIdx.x, d = threadIdx.x;
    float acc = 0.f;
    #pragma unroll
    for (int c = 0; c < 16; c++) acc += g_vpart[((size_t)b * 16 + c) * DD + d];
    g_vmean[b * DD + d] = acc * (1.0f / LQ);
}

// ---------------- 10) upd = attn @ V  (NN GEMM, K=4096) ----------------
__global__ __launch_bounds__(256) void k_upd()
{
    int b = blockIdx.z;
    const float* A = g_S + (size_t)b * PER_BATCH;   // attn [u][4096]
    const float* V = g_v + (size_t)b * PER_BATCH;   // [l][512]
    float* C       = g_upd + (size_t)b * UP * DD;
    int u0 = blockIdx.y * 64, d0 = blockIdx.x * 64;
    __shared__ float As[16][64];   // [l][u]
    __shared__ float Bs[16][64];   // [l][d]
    int tid = threadIdx.x;
    int tx = tid & 15, ty = tid >> 4;
    float acc[4][4] = {};
    for (int k0 = 0; k0 < LQ; k0 += 16) {
        {   int r = tid >> 2, g = tid & 3;
            float4 a = *(const float4*)(A + (size_t)(u0 + r) * LQ + k0 + g * 4);
            As[g*4+0][r] = a.x; As[g*4+1][r] = a.y; As[g*4+2][r] = a.z; As[g*4+3][r] = a.w;
        }
        {   int c = tid >> 4, g2 = tid & 15;
            float4 v = *(const float4*)(V + (size_t)(k0 + c) * DD + d0 + g2 * 4);
            *(float4*)&Bs[c][g2 * 4] = v;
        }
        __syncthreads();
        #pragma unroll
        for (int kk = 0; kk < 16; kk++) {
            float av[4], bb[4];
            #pragma unroll
            for (int i = 0; i < 4; i++) av[i] = As[kk][ty * 4 + i];
            #pragma unroll
            for (int j = 0; j < 4; j++) bb[j] = Bs[kk][tx * 4 + j];
            #pragma unroll
            for (int i = 0; i < 4; i++)
                #pragma unroll
                for (int j = 0; j < 4; j++) acc[i][j] += av[i] * bb[j];
        }
        __syncthreads();
    }
    #pragma unroll
    for (int i = 0; i < 4; i++)
        #pragma unroll
        for (int j = 0; j < 4; j++)
            C[(size_t)(u0 + ty * 4 + i) * DD + d0 + tx * 4 + j] = acc[i][j];
}

// ---------------- 11) fill out with broadcast vmean ----------------
__global__ void k_fill(float* __restrict__ out)
{
    const size_t n4 = (size_t)NB * PER_BATCH / 4;
    for (size_t i = (size_t)blockIdx.x * blockDim.x + threadIdx.x; i < n4;
         i += (size_t)gridDim.x * blockDim.x) {
        size_t e = i * 4;
        int b = (int)(e >> 21);            // / PER_BATCH
        int d = (int)(e & (DD - 1));
        ((float4*)out)[i] = *(const float4*)&g_vmean[b * DD + d];
    }
}

// ---------------- 12) scatter upd rows into out at top-k positions ----------------
__global__ void k_scatter(float* __restrict__ out)
{
    int b = blockIdx.y, u = blockIdx.x;
    int l = g_topk[b * UP + u];
    const float* src = g_upd + ((size_t)b * UP + u) * DD;
    float* dst = out + (size_t)b * PER_BATCH + (size_t)l * DD;
    for (int d = threadIdx.x; d < DD; d += blockDim.x) dst[d] = src[d];
}

// ---------------- launch ----------------
extern "C" void kernel_launch(void* const* d_in, const int* in_sizes, int n_in,
                              void* d_out, int out_size)
{
    const float* in1 = (const float*)d_in[0];
    const float* in2 = (const float*)d_in[1];
    const float* Wq  = (const float*)d_in[2];
    const float* bq  = (const float*)d_in[3];
    const float* Wk  = (const float*)d_in[4];
    const float* bk  = (const float*)d_in[5];
    const float* Wv  = (const float*)d_in[6];
    const float* bv  = (const float*)d_in[7];
    const int*   idx = (const int*)d_in[8];
    float* out = (float*)d_out;

    k_proj<<<dim3(LQ / 64, 8, NB * 3), 256>>>(in1, in2, Wq, bq, Wk, bk, Wv, bv);
    k_gather_ks<<<dim3(UP, NB), 128>>>(idx);
    k_qks<<<dim3(UP / 64, LQ / 64, NB), 256>>>();
    k_mreduce<<<dim3(LQ / 8, NB), 256>>>();
    k_topk<<<NB, 1024>>>();
    k_gather_qr<<<dim3(UP, NB), 128>>>();
    k_scores<<<dim3(LQ / 64, UP / 64, NB), 256>>>();
    k_softmax<<<dim3(UU, NB), 256>>>();
    k_vmean1<<<dim3(16, NB), 512>>>();
    k_vmean2<<<NB, 512>>>();
    k_upd<<<dim3(DD / 64, UP / 64, NB), 256>>>();
    k_fill<<<4096, 256>>>(out);
    k_scatter<<<dim3(UU, NB), 256>>>(out);
}

// round 2
// speedup vs baseline: 1.5568x; 1.5568x over previous
#include <cuda_runtime.h>
#include <cuda_bf16.h>
#include <math_constants.h>

// Problem constants
#define NB 16
#define LQ 4096          // L = 64*64
#define DD 512           // D
#define CC 512           // 2*Cin
#define UU 450           // u = top-k count = sample count
#define UP 512           // padded U
#define PER_BATCH (LQ*DD)

typedef unsigned long long ull;

// ---------------- device scratch (static, no allocation) ----------------
__device__ float g_q[(size_t)NB*PER_BATCH];
__device__ float g_k[(size_t)NB*PER_BATCH];
__device__ float g_v[(size_t)NB*PER_BATCH];
__device__ float g_S[(size_t)NB*PER_BATCH];        // QKs [l][512] then exp-scores [u][4096]
__device__ float g_ksamp[(size_t)NB*UP*DD];
__device__ float g_qr[(size_t)NB*UP*DD];
__device__ float g_upd[(size_t)NB*UP*DD];
__device__ float g_M[NB*LQ];
__device__ int   g_topk[NB*UP];
__device__ float g_vpart[NB*16*DD];
__device__ float g_vmean[NB*DD];
__device__ float g_denom[NB*UP];

// ---------------- packed f32x2 helpers (Blackwell FFMA2 path) ----------------
__device__ __forceinline__ void fma2(ull& d, ull a, ull b) {
    asm("fma.rn.f32x2 %0, %1, %2, %0;" : "+l"(d) : "l"(a), "l"(b));
}
__device__ __forceinline__ ull pack2(float x, float y) {
    ull r; asm("mov.b64 %0, {%1, %2};" : "=l"(r) : "f"(x), "f"(y)); return r;
}
__device__ __forceinline__ float2 unpack2(ull v) {
    float2 r; asm("mov.b64 {%0, %1}, %2;" : "=f"(r.x), "=f"(r.y) : "l"(v)); return r;
}

// ============================================================================
// Unified 128x128x16 fp32 GEMM body, f32x2 packed accumulation.
//  A is always row-major [M][K] (lda == K).
//  BMODE 0: B row-major [N][K] (TN GEMM, ldb == K)
//  BMODE 1: B row-major [K][N] (NN GEMM, ldb = row stride)
//  BMODE 2: like 1, but rows k<256 from B0 and k>=256 from B1 (proj inputs)
//  EPI   0: C += aux[m]  (bias)     1: plain     2: C *= alpha
//        3: C *= (m<UU ? 1/aux[m] : 0)   (softmax denom fusion)
// ============================================================================
template<int BMODE, int EPI>
__device__ __forceinline__ void gemm_body(
    const float* __restrict__ A,
    const float* __restrict__ B0, const float* __restrict__ B1, int ldb,
    float* __restrict__ C, int ldc,
    const float* __restrict__ aux, float alpha, int K)
{
    const int m0 = blockIdx.y * 128;
    const int n0 = blockIdx.x * 128;

    __shared__ float As[2][16][132];
    __shared__ float Bs[2][16][132];

    const int tid = threadIdx.x;
    const int tx4 = (tid & 15) * 4;
    const int ty4 = ((tid >> 4) & 15) * 4;

    const int arow = tid >> 2;        // 0..63
    const int akg  = (tid & 3) * 4;   // 0,4,8,12
    const int brow = tid >> 5;        // 0..7  (direct B)
    const int bng  = (tid & 31) * 4;  // 0..124

    ull acc2[8][4];
    #pragma unroll
    for (int i = 0; i < 8; i++)
        #pragma unroll
        for (int j = 0; j < 4; j++) acc2[i][j] = 0ull;

    float4 pa[2], pb[2];

    // ---- fetch k-step into registers ----
    #define GB_FETCH(k0)                                                          \
    {                                                                             \
        _Pragma("unroll")                                                         \
        for (int h = 0; h < 2; h++) {                                             \
            int r = arow + h * 64;                                                \
            pa[h] = *(const float4*)(A + (size_t)(m0 + r) * K + (k0) + akg);      \
        }                                                                         \
        if (BMODE == 0) {                                                         \
            _Pragma("unroll")                                                     \
            for (int h = 0; h < 2; h++) {                                         \
                int r = arow + h * 64;                                            \
                pb[h] = *(const float4*)(B0 + (size_t)(n0 + r) * K + (k0) + akg); \
            }                                                                     \
        } else {                                                                  \
            _Pragma("unroll")                                                     \
            for (int h = 0; h < 2; h++) {                                         \
                int kr = (k0) + brow + h * 8;                                     \
                const float* rp;                                                  \
                if (BMODE == 1) rp = B0 + (size_t)kr * ldb;                       \
                else rp = (kr < 256) ? (B0 + (size_t)kr * ldb)                    \
                                     : (B1 + (size_t)(kr - 256) * ldb);           \
                pb[h] = *(const float4*)(rp + n0 + bng);                          \
            }                                                                     \
        }                                                                         \
    }

    // ---- store registers into smem buffer ----
    #define GB_STORE(buf)                                                         \
    {                                                                             \
        _Pragma("unroll")                                                         \
        for (int h = 0; h < 2; h++) {                                             \
            int r = arow + h * 64;                                                \
            As[buf][akg+0][r] = pa[h].x; As[buf][akg+1][r] = pa[h].y;             \
            As[buf][akg+2][r] = pa[h].z; As[buf][akg+3][r] = pa[h].w;             \
        }                                                                         \
        if (BMODE == 0) {                                                         \
            _Pragma("unroll")                                                     \
            for (int h = 0; h < 2; h++) {                                         \
                int r = arow + h * 64;                                            \
                Bs[buf][akg+0][r] = pb[h].x; Bs[buf][akg+1][r] = pb[h].y;         \
                Bs[buf][akg+2][r] = pb[h].z; Bs[buf][akg+3][r] = pb[h].w;         \
            }                                                                     \
        } else {                                                                  \
            _Pragma("unroll")                                                     \
            for (int h = 0; h < 2; h++)                                           \
                *(float4*)&Bs[buf][brow + h * 8][bng] = pb[h];                    \
        }                                                                         \
    }

    GB_FETCH(0);
    GB_STORE(0);
    __syncthreads();

    const int KS = K / 16;
    for (int ks = 0; ks < KS; ks++) {
        const int cur = ks & 1;
        if (ks + 1 < KS) GB_FETCH((ks + 1) * 16);

        #pragma unroll
        for (int kk = 0; kk < 16; kk++) {
            float4 a0 = *(const float4*)&As[cur][kk][ty4];
            float4 a1 = *(const float4*)&As[cur][kk][64 + ty4];
            float4 b0 = *(const float4*)&Bs[cur][kk][tx4];
            float4 b1 = *(const float4*)&Bs[cur][kk][64 + tx4];
            ull B2[4];
            B2[0] = pack2(b0.x, b0.y); B2[1] = pack2(b0.z, b0.w);
            B2[2] = pack2(b1.x, b1.y); B2[3] = pack2(b1.z, b1.w);
            float av[8] = {a0.x, a0.y, a0.z, a0.w, a1.x, a1.y, a1.z, a1.w};
            #pragma unroll
            for (int i = 0; i < 8; i++) {
                ull A2 = pack2(av[i], av[i]);
                #pragma unroll
                for (int j = 0; j < 4; j++) fma2(acc2[i][j], A2, B2[j]);
            }
        }

        if (ks + 1 < KS) GB_STORE(cur ^ 1);
        __syncthreads();
    }

    // ---- epilogue ----
    #pragma unroll
    for (int i = 0; i < 8; i++) {
        int mloc = (i < 4) ? (ty4 + i) : (64 + ty4 + i - 4);
        int gm = m0 + mloc;
        float add = 0.f, mul = 1.f;
        if (EPI == 0) add = aux[gm];
        if (EPI == 2) mul = alpha;
        if (EPI == 3) mul = (gm < UU) ? (1.f / aux[gm]) : 0.f;
        float2 c01 = unpack2(acc2[i][0]), c23 = unpack2(acc2[i][1]);
        float2 c45 = unpack2(acc2[i][2]), c67 = unpack2(acc2[i][3]);
        float4 w0 = make_float4(c01.x * mul + add, c01.y * mul + add,
                                c23.x * mul + add, c23.y * mul + add);
        float4 w1 = make_float4(c45.x * mul + add, c45.y * mul + add,
                                c67.x * mul + add, c67.y * mul + add);
        *(float4*)(C + (size_t)gm * ldc + n0 + tx4)      = w0;
        *(float4*)(C + (size_t)gm * ldc + n0 + 64 + tx4) = w1;
    }
    #undef GB_FETCH
    #undef GB_STORE
}

// ---------------- GEMM wrappers ----------------
__global__ __launch_bounds__(256, 2) void k_proj(
    const float* __restrict__ in1, const float* __restrict__ in2,
    const float* __restrict__ Wq, const float* __restrict__ bq,
    const float* __restrict__ Wk, const float* __restrict__ bk,
    const float* __restrict__ Wv, const float* __restrict__ bv)
{
    int z = blockIdx.z;
    int m = z % 3, b = z / 3;
    const float* W    = (m == 0) ? Wq : (m == 1) ? Wk : Wv;
    const float* bias = (m == 0) ? bq : (m == 1) ? bk : bv;
    float* out = ((m == 0) ? g_q : (m == 1) ? g_k : g_v) + (size_t)b * PER_BATCH;
    gemm_body<2, 0>(W, in1 + (size_t)b * 256 * LQ, in2 + (size_t)b * 256 * LQ, LQ,
                    out, LQ, bias, 1.f, CC);
}

__global__ __launch_bounds__(256, 2) void k_qks()
{
    int b = blockIdx.z;
    gemm_body<0, 1>(g_q + (size_t)b * PER_BATCH, g_ksamp + (size_t)b * UP * DD, nullptr, DD,
                    g_S + (size_t)b * PER_BATCH, UP, nullptr, 1.f, DD);
}

__global__ __launch_bounds__(256, 2) void k_scores()
{
    int b = blockIdx.z;
    gemm_body<0, 2>(g_qr + (size_t)b * UP * DD, g_k + (size_t)b * PER_BATCH, nullptr, DD,
                    g_S + (size_t)b * PER_BATCH, LQ, nullptr,
                    0.044194173824159216f /* 1/sqrt(512) */, DD);
}

__global__ __launch_bounds__(256, 2) void k_upd()
{
    int b = blockIdx.z;
    gemm_body<1, 3>(g_S + (size_t)b * PER_BATCH, g_v + (size_t)b * PER_BATCH, nullptr, DD,
                    g_upd + (size_t)b * UP * DD, DD, g_denom + b * UP, 1.f, LQ);
}

// ---------------- gather K_sample (pad rows [450,512) with zeros) ----------------
__global__ void k_gather_ks(const int* __restrict__ idx)
{
    int b = blockIdx.y, s = blockIdx.x;
    float* dst = g_ksamp + ((size_t)b * UP + s) * DD;
    if (s < UU) {
        const float* src = g_k + (size_t)b * PER_BATCH + (size_t)idx[s] * DD;
        for (int d = threadIdx.x; d < DD; d += blockDim.x) dst[d] = src[d];
    } else {
        for (int d = threadIdx.x; d < DD; d += blockDim.x) dst[d] = 0.f;
    }
}

// ---------------- M[l] = max_{s<450} - sum_{s<450}/4096 ----------------
__global__ void k_mreduce()
{
    int b = blockIdx.y;
    int l = blockIdx.x * 8 + (threadIdx.x >> 5);
    int lane = threadIdx.x & 31;
    const float* row = g_S + (size_t)b * PER_BATCH + (size_t)l * UP;
    float mx = -CUDART_INF_F, sm = 0.f;
    for (int s = lane; s < UU; s += 32) { float v = row[s]; mx = fmaxf(mx, v); sm += v; }
    #pragma unroll
    for (int o = 16; o; o >>= 1) {
        mx = fmaxf(mx, __shfl_xor_sync(0xffffffffu, mx, o));
        sm += __shfl_xor_sync(0xffffffffu, sm, o);
    }
    if (lane == 0) g_M[b * LQ + l] = mx - sm * (1.0f / LQ);
}

// ---------------- top-450 per batch via bitonic sort (descending) ----------------
__global__ __launch_bounds__(1024) void k_topk()
{
    __shared__ float sv[LQ];
    __shared__ int   si[LQ];
    int b = blockIdx.x;
    for (int i = threadIdx.x; i < LQ; i += 1024) { sv[i] = g_M[b * LQ + i]; si[i] = i; }
    __syncthreads();
    for (int k = 2; k <= LQ; k <<= 1) {
        for (int j = k >> 1; j > 0; j >>= 1) {
            for (int t = threadIdx.x; t < LQ / 2; t += 1024) {
                int i   = ((t & ~(j - 1)) << 1) | (t & (j - 1));
                int ixj = i | j;
                bool desc = ((i & k) == 0);
                float a = sv[i], c = sv[ixj];
                bool sw = desc ? (a < c) : (a > c);
                if (sw) {
                    sv[i] = c; sv[ixj] = a;
                    int ti = si[i]; si[i] = si[ixj]; si[ixj] = ti;
                }
            }
            __syncthreads();
        }
    }
    for (int u = threadIdx.x; u < UU; u += 1024) g_topk[b * UP + u] = si[u];
}

// ---------------- gather Q_reduce (pad rows with zeros) ----------------
__global__ void k_gather_qr()
{
    int b = blockIdx.y, u = blockIdx.x;
    float* dst = g_qr + ((size_t)b * UP + u) * DD;
    if (u < UU) {
        int l = g_topk[b * UP + u];
        const float* src = g_q + (size_t)b * PER_BATCH + (size_t)l * DD;
        for (int d = threadIdx.x; d < DD; d += blockDim.x) dst[d] = src[d];
    } else {
        for (int d = threadIdx.x; d < DD; d += blockDim.x) dst[d] = 0.f;
    }
}

// ---------------- softmax: write unnormalized exp + per-row denom ----------------
__global__ __launch_bounds__(256) void k_softmax()
{
    int b = blockIdx.y, u = blockIdx.x;
    float* row = g_S + (size_t)b * PER_BATCH + (size_t)u * LQ;
    __shared__ float red[256];
    int t = threadIdx.x;
    float mx = -CUDART_INF_F;
    for (int l = t; l < LQ; l += 256) mx = fmaxf(mx, row[l]);
    red[t] = mx; __syncthreads();
    for (int o = 128; o; o >>= 1) { if (t < o) red[t] = fmaxf(red[t], red[t + o]); __syncthreads(); }
    mx = red[0]; __syncthreads();
    float sm = 0.f;
    for (int l = t; l < LQ; l += 256) { float e = expf(row[l] - mx); row[l] = e; sm += e; }
    red[t] = sm; __syncthreads();
    for (int o = 128; o; o >>= 1) { if (t < o) red[t] += red[t + o]; __syncthreads(); }
    if (t == 0) g_denom[b * UP + u] = red[0];
}

// ---------------- V column means (deterministic two-stage) ----------------
__global__ void k_vmean1()
{
    int b = blockIdx.y, c = blockIdx.x;
    const float* V = g_v + (size_t)b * PER_BATCH + (size_t)c * 256 * DD;
    int d = threadIdx.x;
    float acc = 0.f;
    #pragma unroll 4
    for (int l = 0; l < 256; l++) acc += V[l * DD + d];
    g_vpart[((size_t)b * 16 + c) * DD + d] = acc;
}
__global__ void k_vmean2()
{
    int b = blockIdx.x, d = threadIdx.x;
    float acc = 0.f;
    #pragma unroll
    for (int c = 0; c < 16; c++) acc += g_vpart[((size_t)b * 16 + c) * DD + d];
    g_vmean[b * DD + d] = acc * (1.0f / LQ);
}

// ---------------- fill out with broadcast vmean ----------------
__global__ void k_fill(float* __restrict__ out)
{
    const size_t n4 = (size_t)NB * PER_BATCH / 4;
    for (size_t i = (size_t)blockIdx.x * blockDim.x + threadIdx.x; i < n4;
         i += (size_t)gridDim.x * blockDim.x) {
        size_t e = i * 4;
        int b = (int)(e >> 21);
        int d = (int)(e & (DD - 1));
        ((float4*)out)[i] = *(const float4*)&g_vmean[b * DD + d];
    }
}

// ---------------- scatter upd rows into out at top-k positions ----------------
__global__ void k_scatter(float* __restrict__ out)
{
    int b = blockIdx.y, u = blockIdx.x;
    int l = g_topk[b * UP + u];
    const float* src = g_upd + ((size_t)b * UP + u) * DD;
    float* dst = out + (size_t)b * PER_BATCH + (size_t)l * DD;
    for (int d = threadIdx.x; d < DD; d += blockDim.x) dst[d] = src[d];
}

// ---------------- launch ----------------
extern "C" void kernel_launch(void* const* d_in, const int* in_sizes, int n_in,
                              void* d_out, int out_size)
{
    const float* in1 = (const float*)d_in[0];
    const float* in2 = (const float*)d_in[1];
    const float* Wq  = (const float*)d_in[2];
    const float* bq  = (const float*)d_in[3];
    const float* Wk  = (const float*)d_in[4];
    const float* bk  = (const float*)d_in[5];
    const float* Wv  = (const float*)d_in[6];
    const float* bv  = (const float*)d_in[7];
    const int*   idx = (const int*)d_in[8];
    float* out = (float*)d_out;

    k_proj<<<dim3(LQ / 128, DD / 128, NB * 3), 256>>>(in1, in2, Wq, bq, Wk, bk, Wv, bv);
    k_gather_ks<<<dim3(UP, NB), 128>>>(idx);
    k_qks<<<dim3(UP / 128, LQ / 128, NB), 256>>>();
    k_mreduce<<<dim3(LQ / 8, NB), 256>>>();
    k_topk<<<NB, 1024>>>();
    k_gather_qr<<<dim3(UP, NB), 128>>>();
    k_scores<<<dim3(LQ / 128, UP / 128, NB), 256>>>();
    k_softmax<<<dim3(UU, NB), 256>>>();
    k_vmean1<<<dim3(16, NB), 512>>>();
    k_vmean2<<<NB, 512>>>();
    k_upd<<<dim3(DD / 128, UP / 128, NB), 256>>>();
    k_fill<<<4096, 256>>>(out);
    k_scatter<<<dim3(UU, NB), 256>>>(out);
}

// round 6
// speedup vs baseline: 1.9380x; 1.2449x over previous
#include <cuda_runtime.h>
#include <cuda_bf16.h>
#include <math_constants.h>
#include <cstdint>
#include <mma.h>

using namespace nvcuda;

#define NB 16
#define LQ 4096          // L
#define DD 512           // D
#define CC 512           // 2*Cin
#define UU 450           // top-k count
#define UP 512           // padded U
#define PER_BATCH (LQ*DD)

typedef __nv_bfloat16 bf16;

// ---------------- device scratch ----------------
__device__ float g_v[(size_t)NB*PER_BATCH];     // proj-V flat [o][4096] == v[l][d]
__device__ float g_S[(size_t)NB*PER_BATCH];     // QKs [l][512] then scores [u][4096]
__device__ float g_upd[(size_t)NB*UP*DD];
__device__ float g_M[NB*LQ];
__device__ int   g_topk[NB*UP];
__device__ float g_vpart[NB*16*DD];
__device__ float g_vmean[NB*DD];
__device__ float g_denom[NB*UP];

__device__ __align__(16) bf16 g_Whi[3*DD*CC],            g_Wlo[3*DD*CC];
__device__ __align__(16) bf16 g_XThi[(size_t)NB*LQ*CC],  g_XTlo[(size_t)NB*LQ*CC];  // [s][c]
__device__ __align__(16) bf16 g_Qhi[(size_t)NB*LQ*DD],   g_Qlo[(size_t)NB*LQ*DD];   // flat: [o][4096] == q[l][d]
__device__ __align__(16) bf16 g_Khi[(size_t)NB*LQ*DD],   g_Klo[(size_t)NB*LQ*DD];   // flat
__device__ __align__(16) bf16 g_KShi[(size_t)NB*UP*DD],  g_KSlo[(size_t)NB*UP*DD];  // [s][d]
__device__ __align__(16) bf16 g_QRhi[(size_t)NB*UP*DD],  g_QRlo[(size_t)NB*UP*DD];  // [u][d]
__device__ __align__(16) bf16 g_SEhi[(size_t)NB*UP*LQ],  g_SElo[(size_t)NB*UP*LQ];  // [u][l]
__device__ __align__(16) bf16 g_VThi[(size_t)NB*DD*LQ],  g_VTlo[(size_t)NB*DD*LQ];  // [d][l] true transpose

// ---------------- helpers ----------------
__device__ __forceinline__ uint32_t smem_u32(const void* p) {
    uint32_t a;
    asm("{ .reg .u64 t; cvta.to.shared.u64 t, %1; cvt.u32.u64 %0, t; }" : "=r"(a) : "l"(p));
    return a;
}
__device__ __forceinline__ void cpa16(uint32_t dst, const void* src) {
    asm volatile("cp.async.cg.shared.global [%0], [%1], 16;" :: "r"(dst), "l"(src));
}
__device__ __forceinline__ void cp_commit() { asm volatile("cp.async.commit_group;" ::: "memory"); }
template<int N> __device__ __forceinline__ void cp_wait() {
    asm volatile("cp.async.wait_group %0;" :: "n"(N) : "memory");
}
__device__ __forceinline__ bf16 hi_of(float x) { return __float2bfloat16(x); }
__device__ __forceinline__ bf16 lo_of(float x, bf16 h) { return __float2bfloat16(x - __bfloat162float(h)); }

// ============================================================================
// wmma GEMM: CTA tile 128(M) x 128(N), BK=32, 8 warps (4M x 2N), double buffer.
// A [Mtot][K] K-major (hi/lo), B [Ntot][K] K-major (hi/lo).
// 3-product split: Ah*Bh + Ah*Bl + Al*Bh, fp32 accum.
// EPI: 0 row-bias -> bf16 split | 1 row-bias -> fp32
//      2 plain fp32 | 3 alpha fp32 | 4 row-denom fp32 (m<UU ? 1/aux[m] : 0)
// ============================================================================
#define SA 48                    // smem row stride in halfs (96B, 32B-aligned rows)
#define ARRB (128*SA*2)          // 12288 B per array
#define STAGE (4*ARRB)           // 49152 B per stage
#define SM_TOTAL (2*STAGE)       // 98304 B  (C-stage 128*132*4=67584 reuses this)

template<int EPI>
__device__ __forceinline__ void gemm_wmma(
    const bf16* __restrict__ Ahi, const bf16* __restrict__ Alo,
    const bf16* __restrict__ Bhi, const bf16* __restrict__ Blo, int K,
    float* __restrict__ C, bf16* __restrict__ Chi, bf16* __restrict__ Clo, int ldc,
    const float* __restrict__ aux, float alpha)
{
    extern __shared__ char sm[];
    const uint32_t smb = smem_u32(sm);
    const int tid = threadIdx.x, w = tid >> 5;
    const int mw = w >> 1, nw = w & 1;           // 4 x 2 warp grid
    const int m0 = blockIdx.y * 128, n0 = blockIdx.x * 128;
    const int NS = K >> 5;

    wmma::fragment<wmma::accumulator, 16, 16, 16, float> fc[2][4];
    #pragma unroll
    for (int i = 0; i < 2; i++)
        #pragma unroll
        for (int j = 0; j < 4; j++) wmma::fill_fragment(fc[i][j], 0.f);

    // loader: 512 16B-chunks per array; thread t does chunks 2t, 2t+1
    const int ch0 = tid * 2;
    const int lr0 = ch0 >> 2,       lco0 = (ch0 & 3) * 16;        // bytes in row
    const int lr1 = (ch0 + 1) >> 2, lco1 = ((ch0 + 1) & 3) * 16;
    const int lc0 = (ch0 & 3) * 8,  lc1 = ((ch0 + 1) & 3) * 8;    // halfs in gmem

    auto load_stage = [&](int s, int b) {
        const int k0 = s << 5;
        const uint32_t base = smb + b * STAGE;
        cpa16(base            + lr0*96 + lco0, Ahi + (size_t)(m0+lr0)*K + k0 + lc0);
        cpa16(base            + lr1*96 + lco1, Ahi + (size_t)(m0+lr1)*K + k0 + lc1);
        cpa16(base +   ARRB   + lr0*96 + lco0, Alo + (size_t)(m0+lr0)*K + k0 + lc0);
        cpa16(base +   ARRB   + lr1*96 + lco1, Alo + (size_t)(m0+lr1)*K + k0 + lc1);
        cpa16(base + 2*ARRB   + lr0*96 + lco0, Bhi + (size_t)(n0+lr0)*K + k0 + lc0);
        cpa16(base + 2*ARRB   + lr1*96 + lco1, Bhi + (size_t)(n0+lr1)*K + k0 + lc1);
        cpa16(base + 3*ARRB   + lr0*96 + lco0, Blo + (size_t)(n0+lr0)*K + k0 + lc0);
        cpa16(base + 3*ARRB   + lr1*96 + lco1, Blo + (size_t)(n0+lr1)*K + k0 + lc1);
        cp_commit();
    };

    load_stage(0, 0);

    for (int s = 0; s < NS; s++) {
        const int b = s & 1;
        if (s + 1 < NS) { load_stage(s + 1, b ^ 1); cp_wait<1>(); }
        else            { cp_wait<0>(); }
        __syncthreads();

        const bf16* sAh = (const bf16*)(sm + b * STAGE);
        const bf16* sAl = (const bf16*)(sm + b * STAGE + ARRB);
        const bf16* sBh = (const bf16*)(sm + b * STAGE + 2*ARRB);
        const bf16* sBl = (const bf16*)(sm + b * STAGE + 3*ARRB);

        #pragma unroll
        for (int ks = 0; ks < 2; ks++) {
            wmma::fragment<wmma::matrix_a, 16, 16, 16, bf16, wmma::row_major> fah[2], fal[2];
            wmma::fragment<wmma::matrix_b, 16, 16, 16, bf16, wmma::col_major> fbh[4], fbl[4];
            #pragma unroll
            for (int i = 0; i < 2; i++) {
                const int r = mw * 32 + i * 16;
                wmma::load_matrix_sync(fah[i], sAh + r * SA + ks * 16, SA);
                wmma::load_matrix_sync(fal[i], sAl + r * SA + ks * 16, SA);
            }
            #pragma unroll
            for (int j = 0; j < 4; j++) {
                const int n = nw * 64 + j * 16;
                wmma::load_matrix_sync(fbh[j], sBh + n * SA + ks * 16, SA);
                wmma::load_matrix_sync(fbl[j], sBl + n * SA + ks * 16, SA);
            }
            #pragma unroll
            for (int i = 0; i < 2; i++)
                #pragma unroll
                for (int j = 0; j < 4; j++) {
                    wmma::mma_sync(fc[i][j], fah[i], fbh[j], fc[i][j]);
                    wmma::mma_sync(fc[i][j], fah[i], fbl[j], fc[i][j]);
                    wmma::mma_sync(fc[i][j], fal[i], fbh[j], fc[i][j]);
                }
        }
        __syncthreads();
    }

    // ---- epilogue via smem C-stage (known layout) ----
    float* csm = (float*)sm;
    #pragma unroll
    for (int i = 0; i < 2; i++)
        #pragma unroll
        for (int j = 0; j < 4; j++)
            wmma::store_matrix_sync(csm + (mw*32 + i*16) * 132 + nw*64 + j*16,
                                    fc[i][j], 132, wmma::mem_row_major);
    __syncthreads();

    const int r = tid >> 1, chf = (tid & 1) * 64;
    const int gm = m0 + r;
    const float* src = csm + r * 132 + chf;

    if (EPI == 0) {                       // row bias -> bf16 hi/lo split
        const float add = aux[gm];
        ushort hs[64], ls[64];
        #pragma unroll
        for (int c = 0; c < 64; c++) {
            float v = src[c] + add;
            bf16 h = hi_of(v);
            hs[c] = __bfloat16_as_ushort(h);
            ls[c] = __bfloat16_as_ushort(lo_of(v, h));
        }
        bf16* ph = Chi + (size_t)gm * ldc + n0 + chf;
        bf16* pl = Clo + (size_t)gm * ldc + n0 + chf;
        #pragma unroll
        for (int j = 0; j < 8; j++) {
            *(uint4*)(ph + j * 8) = *(uint4*)&hs[j * 8];
            *(uint4*)(pl + j * 8) = *(uint4*)&ls[j * 8];
        }
    } else {
        float add = 0.f, mul = 1.f;
        if (EPI == 1) add = aux[gm];
        if (EPI == 3) mul = alpha;
        if (EPI == 4) mul = (gm < UU) ? (1.f / aux[gm]) : 0.f;
        float* pc = C + (size_t)gm * ldc + n0 + chf;
        #pragma unroll
        for (int j = 0; j < 16; j++) {
            float4 v = *(const float4*)(src + j * 4);
            v.x = v.x * mul + add; v.y = v.y * mul + add;
            v.z = v.z * mul + add; v.w = v.w * mul + add;
            *(float4*)(pc + j * 4) = v;
        }
    }
}

// ---------------- GEMM wrappers ----------------
// Q/K proj: Y[o][s] = W[o][c] . XT[s][c] + b[o], stored flat (== q[l][d] reinterpreted)
__global__ __launch_bounds__(256) void k_proj_qk(const float* __restrict__ bq,
                                                 const float* __restrict__ bk)
{
    int z = blockIdx.z, mi = z >> 4, b = z & 15;
    gemm_wmma<0>(g_Whi + (size_t)mi*DD*CC, g_Wlo + (size_t)mi*DD*CC,
                 g_XThi + (size_t)b*LQ*CC, g_XTlo + (size_t)b*LQ*CC, CC,
                 nullptr,
                 (mi ? g_Khi : g_Qhi) + (size_t)b*PER_BATCH,
                 (mi ? g_Klo : g_Qlo) + (size_t)b*PER_BATCH, LQ,
                 mi ? bk : bq, 1.f);
}
// V proj: Yv[o][s] = W[o][c] . XT[s][c] + bv[o] -> fp32 g_v flat
__global__ __launch_bounds__(256) void k_proj_v(const float* __restrict__ bv)
{
    int b = blockIdx.z;
    gemm_wmma<1>(g_Whi + (size_t)2*DD*CC, g_Wlo + (size_t)2*DD*CC,
                 g_XThi + (size_t)b*LQ*CC, g_XTlo + (size_t)b*LQ*CC, CC,
                 g_v + (size_t)b*PER_BATCH, nullptr, nullptr, LQ,
                 bv, 1.f);
}
// QKs: S[l][s] = Q[l][d] . KS[s][d]   (Q = flat buffer viewed [l][512])
__global__ __launch_bounds__(256) void k_qks()
{
    int b = blockIdx.z;
    gemm_wmma<2>(g_Qhi + (size_t)b*PER_BATCH, g_Qlo + (size_t)b*PER_BATCH,
                 g_KShi + (size_t)b*UP*DD, g_KSlo + (size_t)b*UP*DD, DD,
                 g_S + (size_t)b*PER_BATCH, nullptr, nullptr, UP, nullptr, 1.f);
}
// scores: S[u][l] = alpha * QR[u][d] . K[l][d]
__global__ __launch_bounds__(256) void k_scores()
{
    int b = blockIdx.z;
    gemm_wmma<3>(g_QRhi + (size_t)b*UP*DD, g_QRlo + (size_t)b*UP*DD,
                 g_Khi + (size_t)b*PER_BATCH, g_Klo + (size_t)b*PER_BATCH, DD,
                 g_S + (size_t)b*PER_BATCH, nullptr, nullptr, LQ, nullptr,
                 0.044194173824159216f);
}
// upd: U[u][d] = (SE[u][l] . VT[d][l]) / denom[u]
__global__ __launch_bounds__(256) void k_upd()
{
    int b = blockIdx.z;
    gemm_wmma<4>(g_SEhi + (size_t)b*UP*LQ, g_SElo + (size_t)b*UP*LQ,
                 g_VThi + (size_t)b*DD*LQ, g_VTlo + (size_t)b*DD*LQ, LQ,
                 g_upd + (size_t)b*UP*DD, nullptr, nullptr, DD,
                 g_denom + b*UP, 1.f);
}

// ---------------- conversions ----------------
__global__ void k_convW(const float* __restrict__ Wq, const float* __restrict__ Wk,
                        const float* __restrict__ Wv)
{
    int i = blockIdx.x * 256 + threadIdx.x;
    int mi = i >> 18, r = i & 262143;
    const float* W = (mi == 0) ? Wq : (mi == 1) ? Wk : Wv;
    float x = W[r];
    bf16 h = hi_of(x);
    g_Whi[i] = h; g_Wlo[i] = lo_of(x, h);
}

// X [b][c][s] (c<256 in1, else in2) -> XT [b][s][c] bf16 hi/lo
__global__ void k_convX(const float* __restrict__ in1, const float* __restrict__ in2)
{
    __shared__ float t[32][33];
    int b = blockIdx.z, s0 = blockIdx.x * 32, c0 = blockIdx.y * 32;
    const float* src = (c0 < 256) ? (in1 + ((size_t)b * 256 + c0) * LQ)
                                  : (in2 + ((size_t)b * 256 + (c0 - 256)) * LQ);
    for (int i = threadIdx.y; i < 32; i += 8)
        t[i][threadIdx.x] = src[(size_t)i * LQ + s0 + threadIdx.x];
    __syncthreads();
    for (int i = threadIdx.y; i < 32; i += 8) {
        float x = t[threadIdx.x][i];
        bf16 h = hi_of(x);
        size_t off = ((size_t)b * LQ + s0 + i) * CC + c0 + threadIdx.x;
        g_XThi[off] = h; g_XTlo[off] = lo_of(x, h);
    }
}

// g_v flat viewed v[l][d] -> VT[d][l] bf16 hi/lo (true transpose)
__global__ void k_transV()
{
    __shared__ float t[32][33];
    int b = blockIdx.z, d0 = blockIdx.x * 32, l0 = blockIdx.y * 32;
    const float* src = g_v + (size_t)b * PER_BATCH;
    for (int i = threadIdx.y; i < 32; i += 8)
        t[i][threadIdx.x] = src[(size_t)(l0 + i) * DD + d0 + threadIdx.x];
    __syncthreads();
    for (int i = threadIdx.y; i < 32; i += 8) {
        float x = t[threadIdx.x][i];
        bf16 h = hi_of(x);
        size_t off = ((size_t)b * DD + d0 + i) * LQ + l0 + threadIdx.x;
        g_VThi[off] = h; g_VTlo[off] = lo_of(x, h);
    }
}

// ---------------- gathers ----------------
__global__ void k_gather_ks(const int* __restrict__ idx)
{
    int b = blockIdx.y, s = blockIdx.x, t = threadIdx.x;   // 128 threads
    size_t drow = ((size_t)b * UP + s) * DD;
    uint2* dh = (uint2*)(g_KShi + drow);
    uint2* dl = (uint2*)(g_KSlo + drow);
    if (s < UU) {
        size_t srow = ((size_t)b * LQ + idx[s]) * DD;
        dh[t] = ((const uint2*)(g_Khi + srow))[t];
        dl[t] = ((const uint2*)(g_Klo + srow))[t];
    } else {
        dh[t] = make_uint2(0, 0); dl[t] = make_uint2(0, 0);
    }
}
__global__ void k_gather_qr()
{
    int b = blockIdx.y, u = blockIdx.x, t = threadIdx.x;
    size_t drow = ((size_t)b * UP + u) * DD;
    uint2* dh = (uint2*)(g_QRhi + drow);
    uint2* dl = (uint2*)(g_QRlo + drow);
    if (u < UU) {
        size_t srow = ((size_t)b * LQ + g_topk[b * UP + u]) * DD;
        dh[t] = ((const uint2*)(g_Qhi + srow))[t];
        dl[t] = ((const uint2*)(g_Qlo + srow))[t];
    } else {
        dh[t] = make_uint2(0, 0); dl[t] = make_uint2(0, 0);
    }
}

// ---------------- M reduce, top-k ----------------
__global__ void k_mreduce()
{
    int b = blockIdx.y;
    int l = blockIdx.x * 8 + (threadIdx.x >> 5);
    int lane = threadIdx.x & 31;
    const float* row = g_S + (size_t)b * PER_BATCH + (size_t)l * UP;
    float mx = -CUDART_INF_F, sm = 0.f;
    for (int s = lane; s < UU; s += 32) { float v = row[s]; mx = fmaxf(mx, v); sm += v; }
    #pragma unroll
    for (int o = 16; o; o >>= 1) {
        mx = fmaxf(mx, __shfl_xor_sync(0xffffffffu, mx, o));
        sm += __shfl_xor_sync(0xffffffffu, sm, o);
    }
    if (lane == 0) g_M[b * LQ + l] = mx - sm * (1.0f / LQ);
}

__global__ __launch_bounds__(1024) void k_topk()
{
    __shared__ float sv[LQ];
    __shared__ int   si[LQ];
    int b = blockIdx.x;
    for (int i = threadIdx.x; i < LQ; i += 1024) { sv[i] = g_M[b * LQ + i]; si[i] = i; }
    __syncthreads();
    for (int k = 2; k <= LQ; k <<= 1) {
        for (int j = k >> 1; j > 0; j >>= 1) {
            for (int t = threadIdx.x; t < LQ / 2; t += 1024) {
                int i = ((t & ~(j - 1)) << 1) | (t & (j - 1));
                int ixj = i | j;
                bool desc = ((i & k) == 0);
                float a = sv[i], c = sv[ixj];
                bool sw = desc ? (a < c) : (a > c);
                if (sw) { sv[i] = c; sv[ixj] = a; int ti = si[i]; si[i] = si[ixj]; si[ixj] = ti; }
            }
            __syncthreads();
        }
    }
    for (int u = threadIdx.x; u < UU; u += 1024) g_topk[b * UP + u] = si[u];
}

// ---------------- softmax -> unnormalized exp (bf16 hi/lo) + denom ----------------
__global__ __launch_bounds__(256) void k_softmax()
{
    int b = blockIdx.y, u = blockIdx.x, t = threadIdx.x;
    size_t off = (size_t)b * PER_BATCH + (size_t)u * LQ;
    bf16* eh = g_SEhi + off;
    bf16* el = g_SElo + off;
    if (u >= UU) {
        for (int l = t; l < LQ; l += 256) { eh[l] = __ushort_as_bfloat16(0); el[l] = __ushort_as_bfloat16(0); }
        if (t == 0) g_denom[b * UP + u] = 1.f;
        return;
    }
    const float* row = g_S + off;
    __shared__ float red[256];
    float mx = -CUDART_INF_F;
    for (int l = t; l < LQ; l += 256) mx = fmaxf(mx, row[l]);
    red[t] = mx; __syncthreads();
    for (int o = 128; o; o >>= 1) { if (t < o) red[t] = fmaxf(red[t], red[t + o]); __syncthreads(); }
    mx = red[0]; __syncthreads();
    float sm = 0.f;
    for (int l = t; l < LQ; l += 256) {
        float e = expf(row[l] - mx);
        bf16 h = hi_of(e);
        eh[l] = h; el[l] = lo_of(e, h);
        sm += e;
    }
    red[t] = sm; __syncthreads();
    for (int o = 128; o; o >>= 1) { if (t < o) red[t] += red[t + o]; __syncthreads(); }
    if (t == 0) g_denom[b * UP + u] = red[0];
}

// ---------------- V column means (deterministic two-stage, from fp32 g_v) ----------------
__global__ void k_vmean1()
{
    int b = blockIdx.y, c = blockIdx.x;
    const float* V = g_v + (size_t)b * PER_BATCH + (size_t)c * 256 * DD;
    int d = threadIdx.x;
    float acc = 0.f;
    #pragma unroll 4
    for (int l = 0; l < 256; l++) acc += V[l * DD + d];
    g_vpart[((size_t)b * 16 + c) * DD + d] = acc;
}
__global__ void k_vmean2()
{
    int b = blockIdx.x, d = threadIdx.x;
    float acc = 0.f;
    #pragma unroll
    for (int c = 0; c < 16; c++) acc += g_vpart[((size_t)b * 16 + c) * DD + d];
    g_vmean[b * DD + d] = acc * (1.0f / LQ);
}

// ---------------- fill / scatter ----------------
__global__ void k_fill(float* __restrict__ out)
{
    const size_t n4 = (size_t)NB * PER_BATCH / 4;
    for (size_t i = (size_t)blockIdx.x * blockDim.x + threadIdx.x; i < n4;
         i += (size_t)gridDim.x * blockDim.x) {
        size_t e = i * 4;
        int b = (int)(e >> 21);
        int d = (int)(e & (DD - 1));
        ((float4*)out)[i] = *(const float4*)&g_vmean[b * DD + d];
    }
}
__global__ void k_scatter(float* __restrict__ out)
{
    int b = blockIdx.y, u = blockIdx.x;
    int l = g_topk[b * UP + u];
    const float* src = g_upd + ((size_t)b * UP + u) * DD;
    float* dst = out + (size_t)b * PER_BATCH + (size_t)l * DD;
    for (int d = threadIdx.x; d < DD; d += blockDim.x) dst[d] = src[d];
}

// ---------------- launch ----------------
extern "C" void kernel_launch(void* const* d_in, const int* in_sizes, int n_in,
                              void* d_out, int out_size)
{
    const float* in1 = (const float*)d_in[0];
    const float* in2 = (const float*)d_in[1];
    const float* Wq  = (const float*)d_in[2];
    const float* bq  = (const float*)d_in[3];
    const float* Wk  = (const float*)d_in[4];
    const float* bk  = (const float*)d_in[5];
    const float* Wv  = (const float*)d_in[6];
    const float* bv  = (const float*)d_in[7];
    const int*   idx = (const int*)d_in[8];
    float* out = (float*)d_out;

    cudaFuncSetAttribute(k_proj_qk, cudaFuncAttributeMaxDynamicSharedMemorySize, SM_TOTAL);
    cudaFuncSetAttribute(k_proj_v,  cudaFuncAttributeMaxDynamicSharedMemorySize, SM_TOTAL);
    cudaFuncSetAttribute(k_qks,     cudaFuncAttributeMaxDynamicSharedMemorySize, SM_TOTAL);
    cudaFuncSetAttribute(k_scores,  cudaFuncAttributeMaxDynamicSharedMemorySize, SM_TOTAL);
    cudaFuncSetAttribute(k_upd,     cudaFuncAttributeMaxDynamicSharedMemorySize, SM_TOTAL);

    k_convW<<<3072, 256>>>(Wq, Wk, Wv);
    k_convX<<<dim3(LQ / 32, CC / 32, NB), dim3(32, 8)>>>(in1, in2);

    // proj: M = DD (o rows), N = LQ (s cols)
    k_proj_qk<<<dim3(LQ / 128, DD / 128, NB * 2), 256, SM_TOTAL>>>(bq, bk);
    k_proj_v <<<dim3(LQ / 128, DD / 128, NB),     256, SM_TOTAL>>>(bv);

    k_transV<<<dim3(DD / 32, LQ / 32, NB), dim3(32, 8)>>>();
    k_vmean1<<<dim3(16, NB), 512>>>();
    k_vmean2<<<NB, 512>>>();

    k_gather_ks<<<dim3(UP, NB), 128>>>(idx);
    k_qks<<<dim3(UP / 128, LQ / 128, NB), 256, SM_TOTAL>>>();
    k_mreduce<<<dim3(LQ / 8, NB), 256>>>();
    k_topk<<<NB, 1024>>>();
    k_gather_qr<<<dim3(UP, NB), 128>>>();

    k_scores<<<dim3(LQ / 128, UP / 128, NB), 256, SM_TOTAL>>>();
    k_softmax<<<dim3(UP, NB), 256>>>();
    k_upd<<<dim3(DD / 128, UP / 128, NB), 256, SM_TOTAL>>>();

    k_fill<<<4096, 256>>>(out);
    k_scatter<<<dim3(UU, NB), 256>>>(out);
}

// round 7
// speedup vs baseline: 2.0872x; 1.0770x over previous
#include <cuda_runtime.h>
#include <cuda_bf16.h>
#include <math_constants.h>
#include <cstdint>
#include <mma.h>

using namespace nvcuda;

#define NB 16
#define LQ 4096          // L
#define DD 512           // D
#define CC 512           // 2*Cin
#define UU 450           // top-k count
#define UP 512           // padded U
#define PER_BATCH (LQ*DD)

typedef __nv_bfloat16 bf16;

// ---------------- device scratch ----------------
__device__ float g_v[(size_t)NB*PER_BATCH];     // proj-V flat [o][4096] == v[l][d]
__device__ float g_S[(size_t)NB*PER_BATCH];     // QKs [l][512] then scores [u][4096]
__device__ float g_upd[(size_t)NB*UP*DD];
__device__ float g_M[NB*LQ];
__device__ int   g_topk[NB*UP];
__device__ float g_vpart[NB*16*DD];
__device__ float g_vmean[NB*DD];
__device__ float g_denom[NB*UP];

__device__ __align__(16) bf16 g_Whi[3*DD*CC],            g_Wlo[3*DD*CC];
__device__ __align__(16) bf16 g_XThi[(size_t)NB*LQ*CC],  g_XTlo[(size_t)NB*LQ*CC];  // [s][c]
__device__ __align__(16) bf16 g_Qhi[(size_t)NB*LQ*DD],   g_Qlo[(size_t)NB*LQ*DD];   // flat: [o][4096] == q[l][d]
__device__ __align__(16) bf16 g_Khi[(size_t)NB*LQ*DD],   g_Klo[(size_t)NB*LQ*DD];   // flat
__device__ __align__(16) bf16 g_KShi[(size_t)NB*UP*DD],  g_KSlo[(size_t)NB*UP*DD];  // [s][d]
__device__ __align__(16) bf16 g_QRhi[(size_t)NB*UP*DD],  g_QRlo[(size_t)NB*UP*DD];  // [u][d]
__device__ __align__(16) bf16 g_SEhi[(size_t)NB*UP*LQ],  g_SElo[(size_t)NB*UP*LQ];  // [u][l]
__device__ __align__(16) bf16 g_VThi[(size_t)NB*DD*LQ],  g_VTlo[(size_t)NB*DD*LQ];  // [d][l] true transpose

// ---------------- helpers ----------------
__device__ __forceinline__ uint32_t smem_u32(const void* p) {
    uint32_t a;
    asm("{ .reg .u64 t; cvta.to.shared.u64 t, %1; cvt.u32.u64 %0, t; }" : "=r"(a) : "l"(p));
    return a;
}
__device__ __forceinline__ void cpa16(uint32_t dst, const void* src) {
    asm volatile("cp.async.cg.shared.global [%0], [%1], 16;" :: "r"(dst), "l"(src));
}
__device__ __forceinline__ void cp_commit() { asm volatile("cp.async.commit_group;" ::: "memory"); }
template<int N> __device__ __forceinline__ void cp_wait() {
    asm volatile("cp.async.wait_group %0;" :: "n"(N) : "memory");
}
__device__ __forceinline__ bf16 hi_of(float x) { return __float2bfloat16(x); }
__device__ __forceinline__ bf16 lo_of(float x, bf16 h) { return __float2bfloat16(x - __bfloat162float(h)); }

// ============================================================================
// wmma GEMM: CTA tile 128(M) x 128(N), BK=32, 8 warps (4M x 2N), double buffer.
// A [Mtot][K] K-major (hi/lo), B [Ntot][K] K-major (hi/lo).
// 3-product split: Ah*Bh + Ah*Bl + Al*Bh, fp32 accum.
// EPI: 0 row-bias -> bf16 split | 1 row-bias -> fp32
//      2 plain fp32 | 3 alpha fp32 | 4 row-denom fp32 (m<UU ? 1/aux[m] : 0)
// ============================================================================
#define SA 48                    // smem row stride in halfs (96B, 32B-aligned rows)
#define ARRB (128*SA*2)          // 12288 B per array
#define STAGE (4*ARRB)           // 49152 B per stage
#define SM_TOTAL (2*STAGE)       // 98304 B  (C-stage 128*132*4=67584 reuses this)

template<int EPI>
__device__ __forceinline__ void gemm_wmma(
    const bf16* __restrict__ Ahi, const bf16* __restrict__ Alo,
    const bf16* __restrict__ Bhi, const bf16* __restrict__ Blo, int K,
    float* __restrict__ C, bf16* __restrict__ Chi, bf16* __restrict__ Clo, int ldc,
    const float* __restrict__ aux, float alpha)
{
    extern __shared__ char sm[];
    const uint32_t smb = smem_u32(sm);
    const int tid = threadIdx.x, w = tid >> 5;
    const int mw = w >> 1, nw = w & 1;           // 4 x 2 warp grid
    const int m0 = blockIdx.y * 128, n0 = blockIdx.x * 128;
    const int NS = K >> 5;

    wmma::fragment<wmma::accumulator, 16, 16, 16, float> fc[2][4];
    #pragma unroll
    for (int i = 0; i < 2; i++)
        #pragma unroll
        for (int j = 0; j < 4; j++) wmma::fill_fragment(fc[i][j], 0.f);

    // loader: 512 16B-chunks per array; thread t does chunks 2t, 2t+1
    const int ch0 = tid * 2;
    const int lr0 = ch0 >> 2,       lco0 = (ch0 & 3) * 16;        // bytes in row
    const int lr1 = (ch0 + 1) >> 2, lco1 = ((ch0 + 1) & 3) * 16;
    const int lc0 = (ch0 & 3) * 8,  lc1 = ((ch0 + 1) & 3) * 8;    // halfs in gmem

    auto load_stage = [&](int s, int b) {
        const int k0 = s << 5;
        const uint32_t base = smb + b * STAGE;
        cpa16(base            + lr0*96 + lco0, Ahi + (size_t)(m0+lr0)*K + k0 + lc0);
        cpa16(base            + lr1*96 + lco1, Ahi + (size_t)(m0+lr1)*K + k0 + lc1);
        cpa16(base +   ARRB   + lr0*96 + lco0, Alo + (size_t)(m0+lr0)*K + k0 + lc0);
        cpa16(base +   ARRB   + lr1*96 + lco1, Alo + (size_t)(m0+lr1)*K + k0 + lc1);
        cpa16(base + 2*ARRB   + lr0*96 + lco0, Bhi + (size_t)(n0+lr0)*K + k0 + lc0);
        cpa16(base + 2*ARRB   + lr1*96 + lco1, Bhi + (size_t)(n0+lr1)*K + k0 + lc1);
        cpa16(base + 3*ARRB   + lr0*96 + lco0, Blo + (size_t)(n0+lr0)*K + k0 + lc0);
        cpa16(base + 3*ARRB   + lr1*96 + lco1, Blo + (size_t)(n0+lr1)*K + k0 + lc1);
        cp_commit();
    };

    load_stage(0, 0);

    for (int s = 0; s < NS; s++) {
        const int b = s & 1;
        if (s + 1 < NS) { load_stage(s + 1, b ^ 1); cp_wait<1>(); }
        else            { cp_wait<0>(); }
        __syncthreads();

        const bf16* sAh = (const bf16*)(sm + b * STAGE);
        const bf16* sAl = (const bf16*)(sm + b * STAGE + ARRB);
        const bf16* sBh = (const bf16*)(sm + b * STAGE + 2*ARRB);
        const bf16* sBl = (const bf16*)(sm + b * STAGE + 3*ARRB);

        #pragma unroll
        for (int ks = 0; ks < 2; ks++) {
            wmma::fragment<wmma::matrix_a, 16, 16, 16, bf16, wmma::row_major> fah[2], fal[2];
            wmma::fragment<wmma::matrix_b, 16, 16, 16, bf16, wmma::col_major> fbh[4], fbl[4];
            #pragma unroll
            for (int i = 0; i < 2; i++) {
                const int r = mw * 32 + i * 16;
                wmma::load_matrix_sync(fah[i], sAh + r * SA + ks * 16, SA);
                wmma::load_matrix_sync(fal[i], sAl + r * SA + ks * 16, SA);
            }
            #pragma unroll
            for (int j = 0; j < 4; j++) {
                const int n = nw * 64 + j * 16;
                wmma::load_matrix_sync(fbh[j], sBh + n * SA + ks * 16, SA);
                wmma::load_matrix_sync(fbl[j], sBl + n * SA + ks * 16, SA);
            }
            #pragma unroll
            for (int i = 0; i < 2; i++)
                #pragma unroll
                for (int j = 0; j < 4; j++) {
                    wmma::mma_sync(fc[i][j], fah[i], fbh[j], fc[i][j]);
                    wmma::mma_sync(fc[i][j], fah[i], fbl[j], fc[i][j]);
                    wmma::mma_sync(fc[i][j], fal[i], fbh[j], fc[i][j]);
                }
        }
        __syncthreads();
    }

    // ---- epilogue via smem C-stage (known layout) ----
    float* csm = (float*)sm;
    #pragma unroll
    for (int i = 0; i < 2; i++)
        #pragma unroll
        for (int j = 0; j < 4; j++)
            wmma::store_matrix_sync(csm + (mw*32 + i*16) * 132 + nw*64 + j*16,
                                    fc[i][j], 132, wmma::mem_row_major);
    __syncthreads();

    const int r = tid >> 1, chf = (tid & 1) * 64;
    const int gm = m0 + r;
    const float* src = csm + r * 132 + chf;

    if (EPI == 0) {                       // row bias -> bf16 hi/lo split
        const float add = aux[gm];
        ushort hs[64], ls[64];
        #pragma unroll
        for (int c = 0; c < 64; c++) {
            float v = src[c] + add;
            bf16 h = hi_of(v);
            hs[c] = __bfloat16_as_ushort(h);
            ls[c] = __bfloat16_as_ushort(lo_of(v, h));
        }
        bf16* ph = Chi + (size_t)gm * ldc + n0 + chf;
        bf16* pl = Clo + (size_t)gm * ldc + n0 + chf;
        #pragma unroll
        for (int j = 0; j < 8; j++) {
            *(uint4*)(ph + j * 8) = *(uint4*)&hs[j * 8];
            *(uint4*)(pl + j * 8) = *(uint4*)&ls[j * 8];
        }
    } else {
        float add = 0.f, mul = 1.f;
        if (EPI == 1) add = aux[gm];
        if (EPI == 3) mul = alpha;
        if (EPI == 4) mul = (gm < UU) ? (1.f / aux[gm]) : 0.f;
        float* pc = C + (size_t)gm * ldc + n0 + chf;
        #pragma unroll
        for (int j = 0; j < 16; j++) {
            float4 v = *(const float4*)(src + j * 4);
            v.x = v.x * mul + add; v.y = v.y * mul + add;
            v.z = v.z * mul + add; v.w = v.w * mul + add;
            *(float4*)(pc + j * 4) = v;
        }
    }
}

// ---------------- GEMM wrappers (2 CTAs/SM forced) ----------------
// Q/K proj: Y[o][s] = W[o][c] . XT[s][c] + b[o], stored flat (== q[l][d] reinterpreted)
__global__ __launch_bounds__(256, 2) void k_proj_qk(const float* __restrict__ bq,
                                                    const float* __restrict__ bk)
{
    int z = blockIdx.z, mi = z >> 4, b = z & 15;
    gemm_wmma<0>(g_Whi + (size_t)mi*DD*CC, g_Wlo + (size_t)mi*DD*CC,
                 g_XThi + (size_t)b*LQ*CC, g_XTlo + (size_t)b*LQ*CC, CC,
                 nullptr,
                 (mi ? g_Khi : g_Qhi) + (size_t)b*PER_BATCH,
                 (mi ? g_Klo : g_Qlo) + (size_t)b*PER_BATCH, LQ,
                 mi ? bk : bq, 1.f);
}
// V proj: Yv[o][s] = W[o][c] . XT[s][c] + bv[o] -> fp32 g_v flat
__global__ __launch_bounds__(256, 2) void k_proj_v(const float* __restrict__ bv)
{
    int b = blockIdx.z;
    gemm_wmma<1>(g_Whi + (size_t)2*DD*CC, g_Wlo + (size_t)2*DD*CC,
                 g_XThi + (size_t)b*LQ*CC, g_XTlo + (size_t)b*LQ*CC, CC,
                 g_v + (size_t)b*PER_BATCH, nullptr, nullptr, LQ,
                 bv, 1.f);
}
// QKs: S[l][s] = Q[l][d] . KS[s][d]   (Q = flat buffer viewed [l][512])
__global__ __launch_bounds__(256, 2) void k_qks()
{
    int b = blockIdx.z;
    gemm_wmma<2>(g_Qhi + (size_t)b*PER_BATCH, g_Qlo + (size_t)b*PER_BATCH,
                 g_KShi + (size_t)b*UP*DD, g_KSlo + (size_t)b*UP*DD, DD,
                 g_S + (size_t)b*PER_BATCH, nullptr, nullptr, UP, nullptr, 1.f);
}
// scores: S[u][l] = alpha * QR[u][d] . K[l][d]
__global__ __launch_bounds__(256, 2) void k_scores()
{
    int b = blockIdx.z;
    gemm_wmma<3>(g_QRhi + (size_t)b*UP*DD, g_QRlo + (size_t)b*UP*DD,
                 g_Khi + (size_t)b*PER_BATCH, g_Klo + (size_t)b*PER_BATCH, DD,
                 g_S + (size_t)b*PER_BATCH, nullptr, nullptr, LQ, nullptr,
                 0.044194173824159216f);
}
// upd: U[u][d] = (SE[u][l] . VT[d][l]) / denom[u]
__global__ __launch_bounds__(256, 2) void k_upd()
{
    int b = blockIdx.z;
    gemm_wmma<4>(g_SEhi + (size_t)b*UP*LQ, g_SElo + (size_t)b*UP*LQ,
                 g_VThi + (size_t)b*DD*LQ, g_VTlo + (size_t)b*DD*LQ, LQ,
                 g_upd + (size_t)b*UP*DD, nullptr, nullptr, DD,
                 g_denom + b*UP, 1.f);
}

// ---------------- conversions ----------------
__global__ void k_convW(const float* __restrict__ Wq, const float* __restrict__ Wk,
                        const float* __restrict__ Wv)
{
    int i = blockIdx.x * 256 + threadIdx.x;
    int mi = i >> 18, r = i & 262143;
    const float* W = (mi == 0) ? Wq : (mi == 1) ? Wk : Wv;
    float x = W[r];
    bf16 h = hi_of(x);
    g_Whi[i] = h; g_Wlo[i] = lo_of(x, h);
}

// X [b][c][s] (c<256 in1, else in2) -> XT [b][s][c] bf16 hi/lo
__global__ void k_convX(const float* __restrict__ in1, const float* __restrict__ in2)
{
    __shared__ float t[32][33];
    int b = blockIdx.z, s0 = blockIdx.x * 32, c0 = blockIdx.y * 32;
    const float* src = (c0 < 256) ? (in1 + ((size_t)b * 256 + c0) * LQ)
                                  : (in2 + ((size_t)b * 256 + (c0 - 256)) * LQ);
    for (int i = threadIdx.y; i < 32; i += 8)
        t[i][threadIdx.x] = src[(size_t)i * LQ + s0 + threadIdx.x];
    __syncthreads();
    for (int i = threadIdx.y; i < 32; i += 8) {
        float x = t[threadIdx.x][i];
        bf16 h = hi_of(x);
        size_t off = ((size_t)b * LQ + s0 + i) * CC + c0 + threadIdx.x;
        g_XThi[off] = h; g_XTlo[off] = lo_of(x, h);
    }
}

// g_v flat viewed v[l][d] -> VT[d][l] bf16 hi/lo (true transpose)
__global__ void k_transV()
{
    __shared__ float t[32][33];
    int b = blockIdx.z, d0 = blockIdx.x * 32, l0 = blockIdx.y * 32;
    const float* src = g_v + (size_t)b * PER_BATCH;
    for (int i = threadIdx.y; i < 32; i += 8)
        t[i][threadIdx.x] = src[(size_t)(l0 + i) * DD + d0 + threadIdx.x];
    __syncthreads();
    for (int i = threadIdx.y; i < 32; i += 8) {
        float x = t[threadIdx.x][i];
        bf16 h = hi_of(x);
        size_t off = ((size_t)b * DD + d0 + i) * LQ + l0 + threadIdx.x;
        g_VThi[off] = h; g_VTlo[off] = lo_of(x, h);
    }
}

// ---------------- gathers ----------------
__global__ void k_gather_ks(const int* __restrict__ idx)
{
    int b = blockIdx.y, s = blockIdx.x, t = threadIdx.x;   // 128 threads
    size_t drow = ((size_t)b * UP + s) * DD;
    uint2* dh = (uint2*)(g_KShi + drow);
    uint2* dl = (uint2*)(g_KSlo + drow);
    if (s < UU) {
        size_t srow = ((size_t)b * LQ + idx[s]) * DD;
        dh[t] = ((const uint2*)(g_Khi + srow))[t];
        dl[t] = ((const uint2*)(g_Klo + srow))[t];
    } else {
        dh[t] = make_uint2(0, 0); dl[t] = make_uint2(0, 0);
    }
}
__global__ void k_gather_qr()
{
    int b = blockIdx.y, u = blockIdx.x, t = threadIdx.x;
    size_t drow = ((size_t)b * UP + u) * DD;
    uint2* dh = (uint2*)(g_QRhi + drow);
    uint2* dl = (uint2*)(g_QRlo + drow);
    if (u < UU) {
        size_t srow = ((size_t)b * LQ + g_topk[b * UP + u]) * DD;
        dh[t] = ((const uint2*)(g_Qhi + srow))[t];
        dl[t] = ((const uint2*)(g_Qlo + srow))[t];
    } else {
        dh[t] = make_uint2(0, 0); dl[t] = make_uint2(0, 0);
    }
}

// ---------------- M reduce, top-k ----------------
__global__ void k_mreduce()
{
    int b = blockIdx.y;
    int l = blockIdx.x * 8 + (threadIdx.x >> 5);
    int lane = threadIdx.x & 31;
    const float* row = g_S + (size_t)b * PER_BATCH + (size_t)l * UP;
    float mx = -CUDART_INF_F, sm = 0.f;
    for (int s = lane; s < UU; s += 32) { float v = row[s]; mx = fmaxf(mx, v); sm += v; }
    #pragma unroll
    for (int o = 16; o; o >>= 1) {
        mx = fmaxf(mx, __shfl_xor_sync(0xffffffffu, mx, o));
        sm += __shfl_xor_sync(0xffffffffu, sm, o);
    }
    if (lane == 0) g_M[b * LQ + l] = mx - sm * (1.0f / LQ);
}

__global__ __launch_bounds__(1024) void k_topk()
{
    __shared__ float sv[LQ];
    __shared__ int   si[LQ];
    int b = blockIdx.x;
    for (int i = threadIdx.x; i < LQ; i += 1024) { sv[i] = g_M[b * LQ + i]; si[i] = i; }
    __syncthreads();
    for (int k = 2; k <= LQ; k <<= 1) {
        for (int j = k >> 1; j > 0; j >>= 1) {
            for (int t = threadIdx.x; t < LQ / 2; t += 1024) {
                int i = ((t & ~(j - 1)) << 1) | (t & (j - 1));
                int ixj = i | j;
                bool desc = ((i & k) == 0);
                float a = sv[i], c = sv[ixj];
                bool sw = desc ? (a < c) : (a > c);
                if (sw) { sv[i] = c; sv[ixj] = a; int ti = si[i]; si[i] = si[ixj]; si[ixj] = ti; }
            }
            __syncthreads();
        }
    }
    for (int u = threadIdx.x; u < UU; u += 1024) g_topk[b * UP + u] = si[u];
}

// ---------------- softmax -> unnormalized exp (bf16 hi/lo) + denom ----------------
__global__ __launch_bounds__(256) void k_softmax()
{
    int b = blockIdx.y, u = blockIdx.x, t = threadIdx.x;
    size_t off = (size_t)b * PER_BATCH + (size_t)u * LQ;
    bf16* eh = g_SEhi + off;
    bf16* el = g_SElo + off;
    if (u >= UU) {
        for (int l = t; l < LQ; l += 256) { eh[l] = __ushort_as_bfloat16(0); el[l] = __ushort_as_bfloat16(0); }
        if (t == 0) g_denom[b * UP + u] = 1.f;
        return;
    }
    const float* row = g_S + off;
    __shared__ float red[256];
    float mx = -CUDART_INF_F;
    for (int l = t; l < LQ; l += 256) mx = fmaxf(mx, row[l]);
    red[t] = mx; __syncthreads();
    for (int o = 128; o; o >>= 1) { if (t < o) red[t] = fmaxf(red[t], red[t + o]); __syncthreads(); }
    mx = red[0]; __syncthreads();
    float sm = 0.f;
    for (int l = t; l < LQ; l += 256) {
        float e = expf(row[l] - mx);
        bf16 h = hi_of(e);
        eh[l] = h; el[l] = lo_of(e, h);
        sm += e;
    }
    red[t] = sm; __syncthreads();
    for (int o = 128; o; o >>= 1) { if (t < o) red[t] += red[t + o]; __syncthreads(); }
    if (t == 0) g_denom[b * UP + u] = red[0];
}

// ---------------- V column means (deterministic two-stage, from fp32 g_v) ----------------
__global__ void k_vmean1()
{
    int b = blockIdx.y, c = blockIdx.x;
    const float* V = g_v + (size_t)b * PER_BATCH + (size_t)c * 256 * DD;
    int d = threadIdx.x;
    float acc = 0.f;
    #pragma unroll 4
    for (int l = 0; l < 256; l++) acc += V[l * DD + d];
    g_vpart[((size_t)b * 16 + c) * DD + d] = acc;
}
__global__ void k_vmean2()
{
    int b = blockIdx.x, d = threadIdx.x;
    float acc = 0.f;
    #pragma unroll
    for (int c = 0; c < 16; c++) acc += g_vpart[((size_t)b * 16 + c) * DD + d];
    g_vmean[b * DD + d] = acc * (1.0f / LQ);
}

// ---------------- fill / scatter ----------------
__global__ void k_fill(float* __restrict__ out)
{
    const size_t n4 = (size_t)NB * PER_BATCH / 4;
    for (size_t i = (size_t)blockIdx.x * blockDim.x + threadIdx.x; i < n4;
         i += (size_t)gridDim.x * blockDim.x) {
        size_t e = i * 4;
        int b = (int)(e >> 21);
        int d = (int)(e & (DD - 1));
        ((float4*)out)[i] = *(const float4*)&g_vmean[b * DD + d];
    }
}
__global__ void k_scatter(float* __restrict__ out)
{
    int b = blockIdx.y, u = blockIdx.x;
    int l = g_topk[b * UP + u];
    const float* src = g_upd + ((size_t)b * UP + u) * DD;
    float* dst = out + (size_t)b * PER_BATCH + (size_t)l * DD;
    for (int d = threadIdx.x; d < DD; d += blockDim.x) dst[d] = src[d];
}

// ---------------- launch ----------------
extern "C" void kernel_launch(void* const* d_in, const int* in_sizes, int n_in,
                              void* d_out, int out_size)
{
    const float* in1 = (const float*)d_in[0];
    const float* in2 = (const float*)d_in[1];
    const float* Wq  = (const float*)d_in[2];
    const float* bq  = (const float*)d_in[3];
    const float* Wk  = (const float*)d_in[4];
    const float* bk  = (const float*)d_in[5];
    const float* Wv  = (const float*)d_in[6];
    const float* bv  = (const float*)d_in[7];
    const int*   idx = (const int*)d_in[8];
    float* out = (float*)d_out;

    cudaFuncSetAttribute(k_proj_qk, cudaFuncAttributeMaxDynamicSharedMemorySize, SM_TOTAL);
    cudaFuncSetAttribute(k_proj_v,  cudaFuncAttributeMaxDynamicSharedMemorySize, SM_TOTAL);
    cudaFuncSetAttribute(k_qks,     cudaFuncAttributeMaxDynamicSharedMemorySize, SM_TOTAL);
    cudaFuncSetAttribute(k_scores,  cudaFuncAttributeMaxDynamicSharedMemorySize, SM_TOTAL);
    cudaFuncSetAttribute(k_upd,     cudaFuncAttributeMaxDynamicSharedMemorySize, SM_TOTAL);

    k_convW<<<3072, 256>>>(Wq, Wk, Wv);
    k_convX<<<dim3(LQ / 32, CC / 32, NB), dim3(32, 8)>>>(in1, in2);

    // proj: M = DD (o rows), N = LQ (s cols)
    k_proj_qk<<<dim3(LQ / 128, DD / 128, NB * 2), 256, SM_TOTAL>>>(bq, bk);
    k_proj_v <<<dim3(LQ / 128, DD / 128, NB),     256, SM_TOTAL>>>(bv);

    k_transV<<<dim3(DD / 32, LQ / 32, NB), dim3(32, 8)>>>();
    k_vmean1<<<dim3(16, NB), 512>>>();
    k_vmean2<<<NB, 512>>>();

    k_gather_ks<<<dim3(UP, NB), 128>>>(idx);
    k_qks<<<dim3(UP / 128, LQ / 128, NB), 256, SM_TOTAL>>>();
    k_mreduce<<<dim3(LQ / 8, NB), 256>>>();
    k_topk<<<NB, 1024>>>();
    k_gather_qr<<<dim3(UP, NB), 128>>>();

    k_scores<<<dim3(LQ / 128, UP / 128, NB), 256, SM_TOTAL>>>();
    k_softmax<<<dim3(UP, NB), 256>>>();
    k_upd<<<dim3(DD / 128, UP / 128, NB), 256, SM_TOTAL>>>();

    k_fill<<<4096, 256>>>(out);
    k_scatter<<<dim3(UU, NB), 256>>>(out);
}

// round 8
// speedup vs baseline: 2.1888x; 1.0487x over previous
#include <cuda_runtime.h>
#include <cuda_bf16.h>
#include <math_constants.h>
#include <cstdint>
#include <mma.h>

using namespace nvcuda;

#define NB 16
#define LQ 4096          // L
#define DD 512           // D
#define CC 512           // 2*Cin
#define UU 450           // top-k count
#define UP 512           // padded U
#define PER_BATCH (LQ*DD)

typedef __nv_bfloat16 bf16;

// ---------------- device scratch ----------------
__device__ float g_v[(size_t)NB*PER_BATCH];     // proj-V flat [o][4096] == v[l][d]
__device__ float g_S[(size_t)NB*PER_BATCH];     // QKs [l][512] then scores [u][4096]
__device__ float g_upd[(size_t)NB*UP*DD];
__device__ float g_M[NB*LQ];
__device__ int   g_topk[NB*UP];
__device__ float g_vpart[NB*16*DD];
__device__ float g_vmean[NB*DD];
__device__ float g_denom[NB*UP];

__device__ __align__(16) bf16 g_Whi[3*DD*CC],            g_Wlo[3*DD*CC];
__device__ __align__(16) bf16 g_XThi[(size_t)NB*LQ*CC],  g_XTlo[(size_t)NB*LQ*CC];  // [s][c]
__device__ __align__(16) bf16 g_Qhi[(size_t)NB*LQ*DD],   g_Qlo[(size_t)NB*LQ*DD];   // flat: [o][4096] == q[l][d]
__device__ __align__(16) bf16 g_Khi[(size_t)NB*LQ*DD],   g_Klo[(size_t)NB*LQ*DD];   // flat
__device__ __align__(16) bf16 g_KShi[(size_t)NB*UP*DD],  g_KSlo[(size_t)NB*UP*DD];  // [s][d]
__device__ __align__(16) bf16 g_QRhi[(size_t)NB*UP*DD],  g_QRlo[(size_t)NB*UP*DD];  // [u][d]
__device__ __align__(16) bf16 g_SEhi[(size_t)NB*UP*LQ],  g_SElo[(size_t)NB*UP*LQ];  // [u][l]
__device__ __align__(16) bf16 g_VThi[(size_t)NB*DD*LQ],  g_VTlo[(size_t)NB*DD*LQ];  // [d][l] true transpose

// ---------------- helpers ----------------
__device__ __forceinline__ uint32_t smem_u32(const void* p) {
    uint32_t a;
    asm("{ .reg .u64 t; cvta.to.shared.u64 t, %1; cvt.u32.u64 %0, t; }" : "=r"(a) : "l"(p));
    return a;
}
__device__ __forceinline__ void cpa16(uint32_t dst, const void* src) {
    asm volatile("cp.async.cg.shared.global [%0], [%1], 16;" :: "r"(dst), "l"(src));
}
__device__ __forceinline__ void cp_commit() { asm volatile("cp.async.commit_group;" ::: "memory"); }
template<int N> __device__ __forceinline__ void cp_wait() {
    asm volatile("cp.async.wait_group %0;" :: "n"(N) : "memory");
}
__device__ __forceinline__ bf16 hi_of(float x) { return __float2bfloat16(x); }
__device__ __forceinline__ bf16 lo_of(float x, bf16 h) { return __float2bfloat16(x - __bfloat162float(h)); }

// ============================================================================
// wmma GEMM: CTA tile 128(M) x 128(N), BK=32, 8 warps (4M x 2N), double buffer.
// A [Mtot][K] K-major (hi/lo), B [Ntot][K] K-major (hi/lo).
// 3-product split: Ah*Bh + Ah*Bl + Al*Bh, fp32 accum.
// JIT B-fragment loading keeps live regs ~112 -> no spills at (256,2).
// EPI: 0 row-bias -> bf16 split | 1 row-bias -> fp32
//      2 plain fp32 | 3 alpha fp32 | 4 row-denom fp32 (m<UU ? 1/aux[m] : 0)
// ============================================================================
#define SA 48                    // smem row stride in halfs (96B, 32B-aligned rows)
#define ARRB (128*SA*2)          // 12288 B per array
#define STAGE (4*ARRB)           // 49152 B per stage
#define SM_TOTAL (2*STAGE)       // 98304 B  (C-stage 128*132*4=67584 reuses this)

template<int EPI>
__device__ __forceinline__ void gemm_wmma(
    const bf16* __restrict__ Ahi, const bf16* __restrict__ Alo,
    const bf16* __restrict__ Bhi, const bf16* __restrict__ Blo, int K,
    float* __restrict__ C, bf16* __restrict__ Chi, bf16* __restrict__ Clo, int ldc,
    const float* __restrict__ aux, float alpha)
{
    extern __shared__ char sm[];
    const uint32_t smb = smem_u32(sm);
    const int tid = threadIdx.x, w = tid >> 5;
    const int mw = w >> 1, nw = w & 1;           // 4 x 2 warp grid
    const int m0 = blockIdx.y * 128, n0 = blockIdx.x * 128;
    const int NS = K >> 5;

    wmma::fragment<wmma::accumulator, 16, 16, 16, float> fc[2][4];
    #pragma unroll
    for (int i = 0; i < 2; i++)
        #pragma unroll
        for (int j = 0; j < 4; j++) wmma::fill_fragment(fc[i][j], 0.f);

    // loader: 512 16B-chunks per array; thread t does chunks 2t, 2t+1
    const int ch0 = tid * 2;
    const int lr0 = ch0 >> 2,       lco0 = (ch0 & 3) * 16;        // bytes in row
    const int lr1 = (ch0 + 1) >> 2, lco1 = ((ch0 + 1) & 3) * 16;
    const int lc0 = (ch0 & 3) * 8,  lc1 = ((ch0 + 1) & 3) * 8;    // halfs in gmem

    auto load_stage = [&](int s, int b) {
        const int k0 = s << 5;
        const uint32_t base = smb + b * STAGE;
        cpa16(base            + lr0*96 + lco0, Ahi + (size_t)(m0+lr0)*K + k0 + lc0);
        cpa16(base            + lr1*96 + lco1, Ahi + (size_t)(m0+lr1)*K + k0 + lc1);
        cpa16(base +   ARRB   + lr0*96 + lco0, Alo + (size_t)(m0+lr0)*K + k0 + lc0);
        cpa16(base +   ARRB   + lr1*96 + lco1, Alo + (size_t)(m0+lr1)*K + k0 + lc1);
        cpa16(base + 2*ARRB   + lr0*96 + lco0, Bhi + (size_t)(n0+lr0)*K + k0 + lc0);
        cpa16(base + 2*ARRB   + lr1*96 + lco1, Bhi + (size_t)(n0+lr1)*K + k0 + lc1);
        cpa16(base + 3*ARRB   + lr0*96 + lco0, Blo + (size_t)(n0+lr0)*K + k0 + lc0);
        cpa16(base + 3*ARRB   + lr1*96 + lco1, Blo + (size_t)(n0+lr1)*K + k0 + lc1);
        cp_commit();
    };

    load_stage(0, 0);

    for (int s = 0; s < NS; s++) {
        const int b = s & 1;
        if (s + 1 < NS) { load_stage(s + 1, b ^ 1); cp_wait<1>(); }
        else            { cp_wait<0>(); }
        __syncthreads();

        const bf16* sAh = (const bf16*)(sm + b * STAGE);
        const bf16* sAl = (const bf16*)(sm + b * STAGE + ARRB);
        const bf16* sBh = (const bf16*)(sm + b * STAGE + 2*ARRB);
        const bf16* sBl = (const bf16*)(sm + b * STAGE + 3*ARRB);

        #pragma unroll
        for (int ks = 0; ks < 2; ks++) {
            wmma::fragment<wmma::matrix_a, 16, 16, 16, bf16, wmma::row_major> fah[2], fal[2];
            #pragma unroll
            for (int i = 0; i < 2; i++) {
                const int r = mw * 32 + i * 16;
                wmma::load_matrix_sync(fah[i], sAh + r * SA + ks * 16, SA);
                wmma::load_matrix_sync(fal[i], sAl + r * SA + ks * 16, SA);
            }
            // JIT B fragments: only one (hi,lo) pair live at a time
            #pragma unroll
            for (int j = 0; j < 4; j++) {
                wmma::fragment<wmma::matrix_b, 16, 16, 16, bf16, wmma::col_major> fbh, fbl;
                const int n = nw * 64 + j * 16;
                wmma::load_matrix_sync(fbh, sBh + n * SA + ks * 16, SA);
                wmma::load_matrix_sync(fbl, sBl + n * SA + ks * 16, SA);
                #pragma unroll
                for (int i = 0; i < 2; i++) {
                    wmma::mma_sync(fc[i][j], fah[i], fbh, fc[i][j]);
                    wmma::mma_sync(fc[i][j], fah[i], fbl, fc[i][j]);
                    wmma::mma_sync(fc[i][j], fal[i], fbh, fc[i][j]);
                }
            }
        }
        __syncthreads();
    }

    // ---- epilogue via smem C-stage (known layout) ----
    float* csm = (float*)sm;
    #pragma unroll
    for (int i = 0; i < 2; i++)
        #pragma unroll
        for (int j = 0; j < 4; j++)
            wmma::store_matrix_sync(csm + (mw*32 + i*16) * 132 + nw*64 + j*16,
                                    fc[i][j], 132, wmma::mem_row_major);
    __syncthreads();

    const int r = tid >> 1, chf = (tid & 1) * 64;
    const int gm = m0 + r;
    const float* src = csm + r * 132 + chf;

    if (EPI == 0) {                       // row bias -> bf16 hi/lo split
        const float add = aux[gm];
        ushort hs[64], ls[64];
        #pragma unroll
        for (int c = 0; c < 64; c++) {
            float v = src[c] + add;
            bf16 h = hi_of(v);
            hs[c] = __bfloat16_as_ushort(h);
            ls[c] = __bfloat16_as_ushort(lo_of(v, h));
        }
        bf16* ph = Chi + (size_t)gm * ldc + n0 + chf;
        bf16* pl = Clo + (size_t)gm * ldc + n0 + chf;
        #pragma unroll
        for (int j = 0; j < 8; j++) {
            *(uint4*)(ph + j * 8) = *(uint4*)&hs[j * 8];
            *(uint4*)(pl + j * 8) = *(uint4*)&ls[j * 8];
        }
    } else {
        float add = 0.f, mul = 1.f;
        if (EPI == 1) add = aux[gm];
        if (EPI == 3) mul = alpha;
        if (EPI == 4) mul = (gm < UU) ? (1.f / aux[gm]) : 0.f;
        float* pc = C + (size_t)gm * ldc + n0 + chf;
        #pragma unroll
        for (int j = 0; j < 16; j++) {
            float4 v = *(const float4*)(src + j * 4);
            v.x = v.x * mul + add; v.y = v.y * mul + add;
            v.z = v.z * mul + add; v.w = v.w * mul + add;
            *(float4*)(pc + j * 4) = v;
        }
    }
}

// ---------------- GEMM wrappers (2 CTAs/SM) ----------------
// Q/K proj: Y[o][s] = W[o][c] . XT[s][c] + b[o], stored flat (== q[l][d] reinterpreted)
__global__ __launch_bounds__(256, 2) void k_proj_qk(const float* __restrict__ bq,
                                                    const float* __restrict__ bk)
{
    int z = blockIdx.z, mi = z >> 4, b = z & 15;
    gemm_wmma<0>(g_Whi + (size_t)mi*DD*CC, g_Wlo + (size_t)mi*DD*CC,
                 g_XThi + (size_t)b*LQ*CC, g_XTlo + (size_t)b*LQ*CC, CC,
                 nullptr,
                 (mi ? g_Khi : g_Qhi) + (size_t)b*PER_BATCH,
                 (mi ? g_Klo : g_Qlo) + (size_t)b*PER_BATCH, LQ,
                 mi ? bk : bq, 1.f);
}
// V proj: Yv[o][s] = W[o][c] . XT[s][c] + bv[o] -> fp32 g_v flat
__global__ __launch_bounds__(256, 2) void k_proj_v(const float* __restrict__ bv)
{
    int b = blockIdx.z;
    gemm_wmma<1>(g_Whi + (size_t)2*DD*CC, g_Wlo + (size_t)2*DD*CC,
                 g_XThi + (size_t)b*LQ*CC, g_XTlo + (size_t)b*LQ*CC, CC,
                 g_v + (size_t)b*PER_BATCH, nullptr, nullptr, LQ,
                 bv, 1.f);
}
// QKs: S[l][s] = Q[l][d] . KS[s][d]   (Q = flat buffer viewed [l][512])
__global__ __launch_bounds__(256, 2) void k_qks()
{
    int b = blockIdx.z;
    gemm_wmma<2>(g_Qhi + (size_t)b*PER_BATCH, g_Qlo + (size_t)b*PER_BATCH,
                 g_KShi + (size_t)b*UP*DD, g_KSlo + (size_t)b*UP*DD, DD,
                 g_S + (size_t)b*PER_BATCH, nullptr, nullptr, UP, nullptr, 1.f);
}
// scores: S[u][l] = alpha * QR[u][d] . K[l][d]
__global__ __launch_bounds__(256, 2) void k_scores()
{
    int b = blockIdx.z;
    gemm_wmma<3>(g_QRhi + (size_t)b*UP*DD, g_QRlo + (size_t)b*UP*DD,
                 g_Khi + (size_t)b*PER_BATCH, g_Klo + (size_t)b*PER_BATCH, DD,
                 g_S + (size_t)b*PER_BATCH, nullptr, nullptr, LQ, nullptr,
                 0.044194173824159216f);
}
// upd: U[u][d] = (SE[u][l] . VT[d][l]) / denom[u]
__global__ __launch_bounds__(256, 2) void k_upd()
{
    int b = blockIdx.z;
    gemm_wmma<4>(g_SEhi + (size_t)b*UP*LQ, g_SElo + (size_t)b*UP*LQ,
                 g_VThi + (size_t)b*DD*LQ, g_VTlo + (size_t)b*DD*LQ, LQ,
                 g_upd + (size_t)b*UP*DD, nullptr, nullptr, DD,
                 g_denom + b*UP, 1.f);
}

// ---------------- conversions ----------------
__global__ void k_convW(const float* __restrict__ Wq, const float* __restrict__ Wk,
                        const float* __restrict__ Wv)
{
    int i = blockIdx.x * 256 + threadIdx.x;
    int mi = i >> 18, r = i & 262143;
    const float* W = (mi == 0) ? Wq : (mi == 1) ? Wk : Wv;
    float x = W[r];
    bf16 h = hi_of(x);
    g_Whi[i] = h; g_Wlo[i] = lo_of(x, h);
}

// X [b][c][s] (c<256 in1, else in2) -> XT [b][s][c] bf16 hi/lo
__global__ void k_convX(const float* __restrict__ in1, const float* __restrict__ in2)
{
    __shared__ float t[32][33];
    int b = blockIdx.z, s0 = blockIdx.x * 32, c0 = blockIdx.y * 32;
    const float* src = (c0 < 256) ? (in1 + ((size_t)b * 256 + c0) * LQ)
                                  : (in2 + ((size_t)b * 256 + (c0 - 256)) * LQ);
    for (int i = threadIdx.y; i < 32; i += 8)
        t[i][threadIdx.x] = src[(size_t)i * LQ + s0 + threadIdx.x];
    __syncthreads();
    for (int i = threadIdx.y; i < 32; i += 8) {
        float x = t[threadIdx.x][i];
        bf16 h = hi_of(x);
        size_t off = ((size_t)b * LQ + s0 + i) * CC + c0 + threadIdx.x;
        g_XThi[off] = h; g_XTlo[off] = lo_of(x, h);
    }
}

// g_v flat viewed v[l][d] -> VT[d][l] bf16 hi/lo (true transpose)
__global__ void k_transV()
{
    __shared__ float t[32][33];
    int b = blockIdx.z, d0 = blockIdx.x * 32, l0 = blockIdx.y * 32;
    const float* src = g_v + (size_t)b * PER_BATCH;
    for (int i = threadIdx.y; i < 32; i += 8)
        t[i][threadIdx.x] = src[(size_t)(l0 + i) * DD + d0 + threadIdx.x];
    __syncthreads();
    for (int i = threadIdx.y; i < 32; i += 8) {
        float x = t[threadIdx.x][i];
        bf16 h = hi_of(x);
        size_t off = ((size_t)b * DD + d0 + i) * LQ + l0 + threadIdx.x;
        g_VThi[off] = h; g_VTlo[off] = lo_of(x, h);
    }
}

// ---------------- gathers ----------------
__global__ void k_gather_ks(const int* __restrict__ idx)
{
    int b = blockIdx.y, s = blockIdx.x, t = threadIdx.x;   // 128 threads
    size_t drow = ((size_t)b * UP + s) * DD;
    uint2* dh = (uint2*)(g_KShi + drow);
    uint2* dl = (uint2*)(g_KSlo + drow);
    if (s < UU) {
        size_t srow = ((size_t)b * LQ + idx[s]) * DD;
        dh[t] = ((const uint2*)(g_Khi + srow))[t];
        dl[t] = ((const uint2*)(g_Klo + srow))[t];
    } else {
        dh[t] = make_uint2(0, 0); dl[t] = make_uint2(0, 0);
    }
}
__global__ void k_gather_qr()
{
    int b = blockIdx.y, u = blockIdx.x, t = threadIdx.x;
    size_t drow = ((size_t)b * UP + u) * DD;
    uint2* dh = (uint2*)(g_QRhi + drow);
    uint2* dl = (uint2*)(g_QRlo + drow);
    if (u < UU) {
        size_t srow = ((size_t)b * LQ + g_topk[b * UP + u]) * DD;
        dh[t] = ((const uint2*)(g_Qhi + srow))[t];
        dl[t] = ((const uint2*)(g_Qlo + srow))[t];
    } else {
        dh[t] = make_uint2(0, 0); dl[t] = make_uint2(0, 0);
    }
}

// ---------------- M reduce, top-k ----------------
__global__ void k_mreduce()
{
    int b = blockIdx.y;
    int l = blockIdx.x * 8 + (threadIdx.x >> 5);
    int lane = threadIdx.x & 31;
    const float* row = g_S + (size_t)b * PER_BATCH + (size_t)l * UP;
    float mx = -CUDART_INF_F, sm = 0.f;
    for (int s = lane; s < UU; s += 32) { float v = row[s]; mx = fmaxf(mx, v); sm += v; }
    #pragma unroll
    for (int o = 16; o; o >>= 1) {
        mx = fmaxf(mx, __shfl_xor_sync(0xffffffffu, mx, o));
        sm += __shfl_xor_sync(0xffffffffu, sm, o);
    }
    if (lane == 0) g_M[b * LQ + l] = mx - sm * (1.0f / LQ);
}

__global__ __launch_bounds__(1024) void k_topk()
{
    __shared__ float sv[LQ];
    __shared__ int   si[LQ];
    int b = blockIdx.x;
    for (int i = threadIdx.x; i < LQ; i += 1024) { sv[i] = g_M[b * LQ + i]; si[i] = i; }
    __syncthreads();
    for (int k = 2; k <= LQ; k <<= 1) {
        for (int j = k >> 1; j > 0; j >>= 1) {
            for (int t = threadIdx.x; t < LQ / 2; t += 1024) {
                int i = ((t & ~(j - 1)) << 1) | (t & (j - 1));
                int ixj = i | j;
                bool desc = ((i & k) == 0);
                float a = sv[i], c = sv[ixj];
                bool sw = desc ? (a < c) : (a > c);
                if (sw) { sv[i] = c; sv[ixj] = a; int ti = si[i]; si[i] = si[ixj]; si[ixj] = ti; }
            }
            __syncthreads();
        }
    }
    for (int u = threadIdx.x; u < UU; u += 1024) g_topk[b * UP + u] = si[u];
}

// ---------------- softmax -> unnormalized exp (bf16 hi/lo) + denom ----------------
__global__ __launch_bounds__(256) void k_softmax()
{
    int b = blockIdx.y, u = blockIdx.x, t = threadIdx.x;
    size_t off = (size_t)b * PER_BATCH + (size_t)u * LQ;
    bf16* eh = g_SEhi + off;
    bf16* el = g_SElo + off;
    if (u >= UU) {
        for (int l = t; l < LQ; l += 256) { eh[l] = __ushort_as_bfloat16(0); el[l] = __ushort_as_bfloat16(0); }
        if (t == 0) g_denom[b * UP + u] = 1.f;
        return;
    }
    const float* row = g_S + off;
    __shared__ float red[256];
    float mx = -CUDART_INF_F;
    for (int l = t; l < LQ; l += 256) mx = fmaxf(mx, row[l]);
    red[t] = mx; __syncthreads();
    for (int o = 128; o; o >>= 1) { if (t < o) red[t] = fmaxf(red[t], red[t + o]); __syncthreads(); }
    mx = red[0]; __syncthreads();
    float sm = 0.f;
    for (int l = t; l < LQ; l += 256) {
        float e = expf(row[l] - mx);
        bf16 h = hi_of(e);
        eh[l] = h; el[l] = lo_of(e, h);
        sm += e;
    }
    red[t] = sm; __syncthreads();
    for (int o = 128; o; o >>= 1) { if (t < o) red[t] += red[t + o]; __syncthreads(); }
    if (t == 0) g_denom[b * UP + u] = red[0];
}

// ---------------- V column means (deterministic two-stage, from fp32 g_v) ----------------
__global__ void k_vmean1()
{
    int b = blockIdx.y, c = blockIdx.x;
    const float* V = g_v + (size_t)b * PER_BATCH + (size_t)c * 256 * DD;
    int d = threadIdx.x;
    float acc = 0.f;
    #pragma unroll 4
    for (int l = 0; l < 256; l++) acc += V[l * DD + d];
    g_vpart[((size_t)b * 16 + c) * DD + d] = acc;
}
__global__ void k_vmean2()
{
    int b = blockIdx.x, d = threadIdx.x;
    float acc = 0.f;
    #pragma unroll
    for (int c = 0; c < 16; c++) acc += g_vpart[((size_t)b * 16 + c) * DD + d];
    g_vmean[b * DD + d] = acc * (1.0f / LQ);
}

// ---------------- fill / scatter ----------------
__global__ void k_fill(float* __restrict__ out)
{
    const size_t n4 = (size_t)NB * PER_BATCH / 4;
    for (size_t i = (size_t)blockIdx.x * blockDim.x + threadIdx.x; i < n4;
         i += (size_t)gridDim.x * blockDim.x) {
        size_t e = i * 4;
        int b = (int)(e >> 21);
        int d = (int)(e & (DD - 1));
        ((float4*)out)[i] = *(const float4*)&g_vmean[b * DD + d];
    }
}
__global__ void k_scatter(float* __restrict__ out)
{
    int b = blockIdx.y, u = blockIdx.x;
    int l = g_topk[b * UP + u];
    const float* src = g_upd + ((size_t)b * UP + u) * DD;
    float* dst = out + (size_t)b * PER_BATCH + (size_t)l * DD;
    for (int d = threadIdx.x; d < DD; d += blockDim.x) dst[d] = src[d];
}

// ---------------- launch ----------------
extern "C" void kernel_launch(void* const* d_in, const int* in_sizes, int n_in,
                              void* d_out, int out_size)
{
    const float* in1 = (const float*)d_in[0];
    const float* in2 = (const float*)d_in[1];
    const float* Wq  = (const float*)d_in[2];
    const float* bq  = (const float*)d_in[3];
    const float* Wk  = (const float*)d_in[4];
    const float* bk  = (const float*)d_in[5];
    const float* Wv  = (const float*)d_in[6];
    const float* bv  = (const float*)d_in[7];
    const int*   idx = (const int*)d_in[8];
    float* out = (float*)d_out;

    cudaFuncSetAttribute(k_proj_qk, cudaFuncAttributeMaxDynamicSharedMemorySize, SM_TOTAL);
    cudaFuncSetAttribute(k_proj_v,  cudaFuncAttributeMaxDynamicSharedMemorySize, SM_TOTAL);
    cudaFuncSetAttribute(k_qks,     cudaFuncAttributeMaxDynamicSharedMemorySize, SM_TOTAL);
    cudaFuncSetAttribute(k_scores,  cudaFuncAttributeMaxDynamicSharedMemorySize, SM_TOTAL);
    cudaFuncSetAttribute(k_upd,     cudaFuncAttributeMaxDynamicSharedMemorySize, SM_TOTAL);

    k_convW<<<3072, 256>>>(Wq, Wk, Wv);
    k_convX<<<dim3(LQ / 32, CC / 32, NB), dim3(32, 8)>>>(in1, in2);

    // proj: M = DD (o rows), N = LQ (s cols)
    k_proj_qk<<<dim3(LQ / 128, DD / 128, NB * 2), 256, SM_TOTAL>>>(bq, bk);
    k_proj_v <<<dim3(LQ / 128, DD / 128, NB),     256, SM_TOTAL>>>(bv);

    k_transV<<<dim3(DD / 32, LQ / 32, NB), dim3(32, 8)>>>();
    k_vmean1<<<dim3(16, NB), 512>>>();
    k_vmean2<<<NB, 512>>>();

    k_gather_ks<<<dim3(UP, NB), 128>>>(idx);
    k_qks<<<dim3(UP / 128, LQ / 128, NB), 256, SM_TOTAL>>>();
    k_mreduce<<<dim3(LQ / 8, NB), 256>>>();
    k_topk<<<NB, 1024>>>();
    k_gather_qr<<<dim3(UP, NB), 128>>>();

    k_scores<<<dim3(LQ / 128, UP / 128, NB), 256, SM_TOTAL>>>();
    k_softmax<<<dim3(UP, NB), 256>>>();
    k_upd<<<dim3(DD / 128, UP / 128, NB), 256, SM_TOTAL>>>();

    k_fill<<<4096, 256>>>(out);
    k_scatter<<<dim3(UU, NB), 256>>>(out);
}

// round 9
// speedup vs baseline: 2.3715x; 1.0834x over previous
#include <cuda_runtime.h>
#include <cuda_bf16.h>
#include <math_constants.h>
#include <cstdint>
#include <mma.h>

using namespace nvcuda;

#define NB 16
#define LQ 4096          // L
#define DD 512           // D
#define CC 512           // 2*Cin
#define UU 450           // top-k count
#define UP 512           // padded U
#define PER_BATCH (LQ*DD)

typedef __nv_bfloat16 bf16;

// ---------------- device scratch ----------------
__device__ float g_v[(size_t)NB*PER_BATCH];     // proj-V flat [o][4096] == v[l][d]
__device__ float g_S[(size_t)NB*PER_BATCH];     // QKs [l][512] then scores [u][4096]
__device__ float g_upd[(size_t)NB*UP*DD];
__device__ float g_M[NB*LQ];
__device__ int   g_topk[NB*UP];
__device__ float g_vpart[NB*16*DD];
__device__ float g_vmean[NB*DD];
__device__ float g_denom[NB*UP];

__device__ __align__(16) bf16 g_Whi[3*DD*CC],            g_Wlo[3*DD*CC];
__device__ __align__(16) bf16 g_XThi[(size_t)NB*LQ*CC],  g_XTlo[(size_t)NB*LQ*CC];  // [s][c]
__device__ __align__(16) bf16 g_Qhi[(size_t)NB*LQ*DD],   g_Qlo[(size_t)NB*LQ*DD];   // flat: [o][4096] == q[l][d]
__device__ __align__(16) bf16 g_Khi[(size_t)NB*LQ*DD],   g_Klo[(size_t)NB*LQ*DD];   // flat
__device__ __align__(16) bf16 g_KShi[(size_t)NB*UP*DD],  g_KSlo[(size_t)NB*UP*DD];  // [s][d]
__device__ __align__(16) bf16 g_QRhi[(size_t)NB*UP*DD],  g_QRlo[(size_t)NB*UP*DD];  // [u][d]
__device__ __align__(16) bf16 g_SEhi[(size_t)NB*UP*LQ],  g_SElo[(size_t)NB*UP*LQ];  // [u][l]
__device__ __align__(16) bf16 g_VThi[(size_t)NB*DD*LQ],  g_VTlo[(size_t)NB*DD*LQ];  // [d][l] true transpose

// ---------------- helpers ----------------
__device__ __forceinline__ uint32_t smem_u32(const void* p) {
    uint32_t a;
    asm("{ .reg .u64 t; cvta.to.shared.u64 t, %1; cvt.u32.u64 %0, t; }" : "=r"(a) : "l"(p));
    return a;
}
__device__ __forceinline__ void cpa16(uint32_t dst, const void* src) {
    asm volatile("cp.async.cg.shared.global [%0], [%1], 16;" :: "r"(dst), "l"(src));
}
__device__ __forceinline__ void cp_commit() { asm volatile("cp.async.commit_group;" ::: "memory"); }
template<int N> __device__ __forceinline__ void cp_wait() {
    asm volatile("cp.async.wait_group %0;" :: "n"(N) : "memory");
}
__device__ __forceinline__ bf16 hi_of(float x) { return __float2bfloat16(x); }
__device__ __forceinline__ bf16 lo_of(float x, bf16 h) { return __float2bfloat16(x - __bfloat162float(h)); }

// ============================================================================
// wmma GEMM: CTA tile 128(M) x 256(N), BK=32, 8 warps (2M x 4N), warp 64x64,
// double-buffered cp.async. A [Mtot][K], B [Ntot][K], both K-major hi/lo.
// 3-product split: Ah*Bh + Ah*Bl + Al*Bh, fp32 accum.
// FLOP/LDSM ratio 3.0 (was 2.0). 1 CTA/SM (smem 144KB), ~190 regs, no spill.
// EPI: 0 row-bias -> bf16 split | 1 row-bias -> fp32
//      2 plain fp32 | 3 alpha fp32 | 4 row-denom fp32 (m<UU ? 1/aux[m] : 0)
// ============================================================================
#define SA 48                     // smem row stride in halfs (96B)
#define ARR_A (128*SA*2)          // 12288 B
#define ARR_B (256*SA*2)          // 24576 B
#define STAGE (2*ARR_A + 2*ARR_B) // 73728 B
#define SM_TOTAL (2*STAGE)        // 147456 B (C-stage 128*260*4=133120 reuses)

template<int EPI>
__device__ __forceinline__ void gemm_wmma(
    const bf16* __restrict__ Ahi, const bf16* __restrict__ Alo,
    const bf16* __restrict__ Bhi, const bf16* __restrict__ Blo, int K,
    float* __restrict__ C, bf16* __restrict__ Chi, bf16* __restrict__ Clo, int ldc,
    const float* __restrict__ aux, float alpha)
{
    extern __shared__ char sm[];
    const uint32_t smb = smem_u32(sm);
    const int tid = threadIdx.x, w = tid >> 5;
    const int mw = w >> 2, nw = w & 3;           // 2M x 4N warp grid
    const int m0 = blockIdx.y * 128, n0 = blockIdx.x * 256;
    const int NS = K >> 5;

    wmma::fragment<wmma::accumulator, 16, 16, 16, float> fc[4][4];
    #pragma unroll
    for (int i = 0; i < 4; i++)
        #pragma unroll
        for (int j = 0; j < 4; j++) wmma::fill_fragment(fc[i][j], 0.f);

    auto load_stage = [&](int s, int bufb) {
        const int k0 = s << 5;
        const uint32_t base = smb + bufb * STAGE;
        // A hi/lo: 128 rows x 4 chunks = 512 chunks each
        #pragma unroll
        for (int q = 0; q < 2; q++) {
            const bf16* src = q ? Alo : Ahi;
            const uint32_t dst = base + q * ARR_A;
            #pragma unroll
            for (int c0 = 0; c0 < 512; c0 += 256) {
                int c = c0 + tid;
                int row = c >> 2, col = c & 3;
                cpa16(dst + row * 96 + col * 16,
                      src + (size_t)(m0 + row) * K + k0 + col * 8);
            }
        }
        // B hi/lo: 256 rows x 4 chunks = 1024 chunks each
        #pragma unroll
        for (int q = 0; q < 2; q++) {
            const bf16* src = q ? Blo : Bhi;
            const uint32_t dst = base + 2 * ARR_A + q * ARR_B;
            #pragma unroll
            for (int c0 = 0; c0 < 1024; c0 += 256) {
                int c = c0 + tid;
                int row = c >> 2, col = c & 3;
                cpa16(dst + row * 96 + col * 16,
                      src + (size_t)(n0 + row) * K + k0 + col * 8);
            }
        }
        cp_commit();
    };

    load_stage(0, 0);

    for (int s = 0; s < NS; s++) {
        const int b = s & 1;
        if (s + 1 < NS) { load_stage(s + 1, b ^ 1); cp_wait<1>(); }
        else            { cp_wait<0>(); }
        __syncthreads();

        const bf16* sAh = (const bf16*)(sm + b * STAGE);
        const bf16* sAl = (const bf16*)(sm + b * STAGE + ARR_A);
        const bf16* sBh = (const bf16*)(sm + b * STAGE + 2 * ARR_A);
        const bf16* sBl = (const bf16*)(sm + b * STAGE + 2 * ARR_A + ARR_B);

        #pragma unroll
        for (int ks = 0; ks < 2; ks++) {
            wmma::fragment<wmma::matrix_a, 16, 16, 16, bf16, wmma::row_major> fah[4], fal[4];
            #pragma unroll
            for (int i = 0; i < 4; i++) {
                const int r = mw * 64 + i * 16;
                wmma::load_matrix_sync(fah[i], sAh + r * SA + ks * 16, SA);
                wmma::load_matrix_sync(fal[i], sAl + r * SA + ks * 16, SA);
            }
            // JIT B fragments: one (hi,lo) pair live at a time
            #pragma unroll
            for (int j = 0; j < 4; j++) {
                wmma::fragment<wmma::matrix_b, 16, 16, 16, bf16, wmma::col_major> fbh, fbl;
                const int n = nw * 64 + j * 16;
                wmma::load_matrix_sync(fbh, sBh + n * SA + ks * 16, SA);
                wmma::load_matrix_sync(fbl, sBl + n * SA + ks * 16, SA);
                #pragma unroll
                for (int i = 0; i < 4; i++) {
                    wmma::mma_sync(fc[i][j], fah[i], fbh, fc[i][j]);
                    wmma::mma_sync(fc[i][j], fah[i], fbl, fc[i][j]);
                    wmma::mma_sync(fc[i][j], fal[i], fbh, fc[i][j]);
                }
            }
        }
        __syncthreads();
    }

    // ---- epilogue via smem C-stage (known layout), 128 x 260 fp32 ----
    float* csm = (float*)sm;
    #pragma unroll
    for (int i = 0; i < 4; i++)
        #pragma unroll
        for (int j = 0; j < 4; j++)
            wmma::store_matrix_sync(csm + (mw*64 + i*16) * 260 + nw*64 + j*16,
                                    fc[i][j], 260, wmma::mem_row_major);
    __syncthreads();

    const int r = tid >> 1, gm = m0 + r;
    const int cb0 = (tid & 1) * 128;
    const float* src = csm + r * 260 + cb0;

    if (EPI == 0) {                       // row bias -> bf16 hi/lo split
        const float add = aux[gm];
        #pragma unroll
        for (int g = 0; g < 4; g++) {     // 32 cols per group
            ushort hs[32], ls[32];
            #pragma unroll
            for (int c = 0; c < 32; c++) {
                float v = src[g * 32 + c] + add;
                bf16 h = hi_of(v);
                hs[c] = __bfloat16_as_ushort(h);
                ls[c] = __bfloat16_as_ushort(lo_of(v, h));
            }
            bf16* ph = Chi + (size_t)gm * ldc + n0 + cb0 + g * 32;
            bf16* pl = Clo + (size_t)gm * ldc + n0 + cb0 + g * 32;
            #pragma unroll
            for (int j = 0; j < 4; j++) {
                *(uint4*)(ph + j * 8) = *(uint4*)&hs[j * 8];
                *(uint4*)(pl + j * 8) = *(uint4*)&ls[j * 8];
            }
        }
    } else {
        float add = 0.f, mul = 1.f;
        if (EPI == 1) add = aux[gm];
        if (EPI == 3) mul = alpha;
        if (EPI == 4) mul = (gm < UU) ? (1.f / aux[gm]) : 0.f;
        float* pc = C + (size_t)gm * ldc + n0 + cb0;
        #pragma unroll
        for (int j = 0; j < 32; j++) {
            float4 v = *(const float4*)(src + j * 4);
            v.x = v.x * mul + add; v.y = v.y * mul + add;
            v.z = v.z * mul + add; v.w = v.w * mul + add;
            *(float4*)(pc + j * 4) = v;
        }
    }
}

// ---------------- GEMM wrappers (1 CTA/SM, full register file) ----------------
// Q/K proj: Y[o][s] = W[o][c] . XT[s][c] + b[o], stored flat (== q[l][d] reinterpreted)
__global__ __launch_bounds__(256, 1) void k_proj_qk(const float* __restrict__ bq,
                                                    const float* __restrict__ bk)
{
    int z = blockIdx.z, mi = z >> 4, b = z & 15;
    gemm_wmma<0>(g_Whi + (size_t)mi*DD*CC, g_Wlo + (size_t)mi*DD*CC,
                 g_XThi + (size_t)b*LQ*CC, g_XTlo + (size_t)b*LQ*CC, CC,
                 nullptr,
                 (mi ? g_Khi : g_Qhi) + (size_t)b*PER_BATCH,
                 (mi ? g_Klo : g_Qlo) + (size_t)b*PER_BATCH, LQ,
                 mi ? bk : bq, 1.f);
}
// V proj: Yv[o][s] = W[o][c] . XT[s][c] + bv[o] -> fp32 g_v flat
__global__ __launch_bounds__(256, 1) void k_proj_v(const float* __restrict__ bv)
{
    int b = blockIdx.z;
    gemm_wmma<1>(g_Whi + (size_t)2*DD*CC, g_Wlo + (size_t)2*DD*CC,
                 g_XThi + (size_t)b*LQ*CC, g_XTlo + (size_t)b*LQ*CC, CC,
                 g_v + (size_t)b*PER_BATCH, nullptr, nullptr, LQ,
                 bv, 1.f);
}
// QKs: S[l][s] = Q[l][d] . KS[s][d]
__global__ __launch_bounds__(256, 1) void k_qks()
{
    int b = blockIdx.z;
    gemm_wmma<2>(g_Qhi + (size_t)b*PER_BATCH, g_Qlo + (size_t)b*PER_BATCH,
                 g_KShi + (size_t)b*UP*DD, g_KSlo + (size_t)b*UP*DD, DD,
                 g_S + (size_t)b*PER_BATCH, nullptr, nullptr, UP, nullptr, 1.f);
}
// scores: S[u][l] = alpha * QR[u][d] . K[l][d]
__global__ __launch_bounds__(256, 1) void k_scores()
{
    int b = blockIdx.z;
    gemm_wmma<3>(g_QRhi + (size_t)b*UP*DD, g_QRlo + (size_t)b*UP*DD,
                 g_Khi + (size_t)b*PER_BATCH, g_Klo + (size_t)b*PER_BATCH, DD,
                 g_S + (size_t)b*PER_BATCH, nullptr, nullptr, LQ, nullptr,
                 0.044194173824159216f);
}
// upd: U[u][d] = (SE[u][l] . VT[d][l]) / denom[u]
__global__ __launch_bounds__(256, 1) void k_upd()
{
    int b = blockIdx.z;
    gemm_wmma<4>(g_SEhi + (size_t)b*UP*LQ, g_SElo + (size_t)b*UP*LQ,
                 g_VThi + (size_t)b*DD*LQ, g_VTlo + (size_t)b*DD*LQ, LQ,
                 g_upd + (size_t)b*UP*DD, nullptr, nullptr, DD,
                 g_denom + b*UP, 1.f);
}

// ---------------- conversions ----------------
__global__ void k_convW(const float* __restrict__ Wq, const float* __restrict__ Wk,
                        const float* __restrict__ Wv)
{
    int i = blockIdx.x * 256 + threadIdx.x;
    int mi = i >> 18, r = i & 262143;
    const float* W = (mi == 0) ? Wq : (mi == 1) ? Wk : Wv;
    float x = W[r];
    bf16 h = hi_of(x);
    g_Whi[i] = h; g_Wlo[i] = lo_of(x, h);
}

// X [b][c][s] (c<256 in1, else in2) -> XT [b][s][c] bf16 hi/lo
__global__ void k_convX(const float* __restrict__ in1, const float* __restrict__ in2)
{
    __shared__ float t[32][33];
    int b = blockIdx.z, s0 = blockIdx.x * 32, c0 = blockIdx.y * 32;
    const float* src = (c0 < 256) ? (in1 + ((size_t)b * 256 + c0) * LQ)
                                  : (in2 + ((size_t)b * 256 + (c0 - 256)) * LQ);
    for (int i = threadIdx.y; i < 32; i += 8)
        t[i][threadIdx.x] = src[(size_t)i * LQ + s0 + threadIdx.x];
    __syncthreads();
    for (int i = threadIdx.y; i < 32; i += 8) {
        float x = t[threadIdx.x][i];
        bf16 h = hi_of(x);
        size_t off = ((size_t)b * LQ + s0 + i) * CC + c0 + threadIdx.x;
        g_XThi[off] = h; g_XTlo[off] = lo_of(x, h);
    }
}

// g_v flat viewed v[l][d] -> VT[d][l] bf16 hi/lo (true transpose)
__global__ void k_transV()
{
    __shared__ float t[32][33];
    int b = blockIdx.z, d0 = blockIdx.x * 32, l0 = blockIdx.y * 32;
    const float* src = g_v + (size_t)b * PER_BATCH;
    for (int i = threadIdx.y; i < 32; i += 8)
        t[i][threadIdx.x] = src[(size_t)(l0 + i) * DD + d0 + threadIdx.x];
    __syncthreads();
    for (int i = threadIdx.y; i < 32; i += 8) {
        float x = t[threadIdx.x][i];
        bf16 h = hi_of(x);
        size_t off = ((size_t)b * DD + d0 + i) * LQ + l0 + threadIdx.x;
        g_VThi[off] = h; g_VTlo[off] = lo_of(x, h);
    }
}

// ---------------- gathers ----------------
__global__ void k_gather_ks(const int* __restrict__ idx)
{
    int b = blockIdx.y, s = blockIdx.x, t = threadIdx.x;   // 128 threads
    size_t drow = ((size_t)b * UP + s) * DD;
    uint2* dh = (uint2*)(g_KShi + drow);
    uint2* dl = (uint2*)(g_KSlo + drow);
    if (s < UU) {
        size_t srow = ((size_t)b * LQ + idx[s]) * DD;
        dh[t] = ((const uint2*)(g_Khi + srow))[t];
        dl[t] = ((const uint2*)(g_Klo + srow))[t];
    } else {
        dh[t] = make_uint2(0, 0); dl[t] = make_uint2(0, 0);
    }
}
__global__ void k_gather_qr()
{
    int b = blockIdx.y, u = blockIdx.x, t = threadIdx.x;
    size_t drow = ((size_t)b * UP + u) * DD;
    uint2* dh = (uint2*)(g_QRhi + drow);
    uint2* dl = (uint2*)(g_QRlo + drow);
    if (u < UU) {
        size_t srow = ((size_t)b * LQ + g_topk[b * UP + u]) * DD;
        dh[t] = ((const uint2*)(g_Qhi + srow))[t];
        dl[t] = ((const uint2*)(g_Qlo + srow))[t];
    } else {
        dh[t] = make_uint2(0, 0); dl[t] = make_uint2(0, 0);
    }
}

// ---------------- M reduce, top-k ----------------
__global__ void k_mreduce()
{
    int b = blockIdx.y;
    int l = blockIdx.x * 8 + (threadIdx.x >> 5);
    int lane = threadIdx.x & 31;
    const float* row = g_S + (size_t)b * PER_BATCH + (size_t)l * UP;
    float mx = -CUDART_INF_F, sm = 0.f;
    for (int s = lane; s < UU; s += 32) { float v = row[s]; mx = fmaxf(mx, v); sm += v; }
    #pragma unroll
    for (int o = 16; o; o >>= 1) {
        mx = fmaxf(mx, __shfl_xor_sync(0xffffffffu, mx, o));
        sm += __shfl_xor_sync(0xffffffffu, sm, o);
    }
    if (lane == 0) g_M[b * LQ + l] = mx - sm * (1.0f / LQ);
}

__global__ __launch_bounds__(1024) void k_topk()
{
    __shared__ float sv[LQ];
    __shared__ int   si[LQ];
    int b = blockIdx.x;
    for (int i = threadIdx.x; i < LQ; i += 1024) { sv[i] = g_M[b * LQ + i]; si[i] = i; }
    __syncthreads();
    for (int k = 2; k <= LQ; k <<= 1) {
        for (int j = k >> 1; j > 0; j >>= 1) {
            for (int t = threadIdx.x; t < LQ / 2; t += 1024) {
                int i = ((t & ~(j - 1)) << 1) | (t & (j - 1));
                int ixj = i | j;
                bool desc = ((i & k) == 0);
                float a = sv[i], c = sv[ixj];
                bool sw = desc ? (a < c) : (a > c);
                if (sw) { sv[i] = c; sv[ixj] = a; int ti = si[i]; si[i] = si[ixj]; si[ixj] = ti; }
            }
            __syncthreads();
        }
    }
    for (int u = threadIdx.x; u < UU; u += 1024) g_topk[b * UP + u] = si[u];
}

// ---------------- softmax -> unnormalized exp (bf16 hi/lo) + denom ----------------
__global__ __launch_bounds__(256) void k_softmax()
{
    int b = blockIdx.y, u = blockIdx.x, t = threadIdx.x;
    size_t off = (size_t)b * PER_BATCH + (size_t)u * LQ;
    bf16* eh = g_SEhi + off;
    bf16* el = g_SElo + off;
    if (u >= UU) {
        for (int l = t; l < LQ; l += 256) { eh[l] = __ushort_as_bfloat16(0); el[l] = __ushort_as_bfloat16(0); }
        if (t == 0) g_denom[b * UP + u] = 1.f;
        return;
    }
    const float* row = g_S + off;
    __shared__ float red[256];
    float mx = -CUDART_INF_F;
    for (int l = t; l < LQ; l += 256) mx = fmaxf(mx, row[l]);
    red[t] = mx; __syncthreads();
    for (int o = 128; o; o >>= 1) { if (t < o) red[t] = fmaxf(red[t], red[t + o]); __syncthreads(); }
    mx = red[0]; __syncthreads();
    float sm = 0.f;
    for (int l = t; l < LQ; l += 256) {
        float e = expf(row[l] - mx);
        bf16 h = hi_of(e);
        eh[l] = h; el[l] = lo_of(e, h);
        sm += e;
    }
    red[t] = sm; __syncthreads();
    for (int o = 128; o; o >>= 1) { if (t < o) red[t] += red[t + o]; __syncthreads(); }
    if (t == 0) g_denom[b * UP + u] = red[0];
}

// ---------------- V column means (deterministic two-stage, from fp32 g_v) ----------------
__global__ void k_vmean1()
{
    int b = blockIdx.y, c = blockIdx.x;
    const float* V = g_v + (size_t)b * PER_BATCH + (size_t)c * 256 * DD;
    int d = threadIdx.x;
    float acc = 0.f;
    #pragma unroll 4
    for (int l = 0; l < 256; l++) acc += V[l * DD + d];
    g_vpart[((size_t)b * 16 + c) * DD + d] = acc;
}
__global__ void k_vmean2()
{
    int b = blockIdx.x, d = threadIdx.x;
    float acc = 0.f;
    #pragma unroll
    for (int c = 0; c < 16; c++) acc += g_vpart[((size_t)b * 16 + c) * DD + d];
    g_vmean[b * DD + d] = acc * (1.0f / LQ);
}

// ---------------- fill / scatter ----------------
__global__ void k_fill(float* __restrict__ out)
{
    const size_t n4 = (size_t)NB * PER_BATCH / 4;
    for (size_t i = (size_t)blockIdx.x * blockDim.x + threadIdx.x; i < n4;
         i += (size_t)gridDim.x * blockDim.x) {
        size_t e = i * 4;
        int b = (int)(e >> 21);
        int d = (int)(e & (DD - 1));
        ((float4*)out)[i] = *(const float4*)&g_vmean[b * DD + d];
    }
}
__global__ void k_scatter(float* __restrict__ out)
{
    int b = blockIdx.y, u = blockIdx.x;
    int l = g_topk[b * UP + u];
    const float* src = g_upd + ((size_t)b * UP + u) * DD;
    float* dst = out + (size_t)b * PER_BATCH + (size_t)l * DD;
    for (int d = threadIdx.x; d < DD; d += blockDim.x) dst[d] = src[d];
}

// ---------------- launch ----------------
extern "C" void kernel_launch(void* const* d_in, const int* in_sizes, int n_in,
                              void* d_out, int out_size)
{
    const float* in1 = (const float*)d_in[0];
    const float* in2 = (const float*)d_in[1];
    const float* Wq  = (const float*)d_in[2];
    const float* bq  = (const float*)d_in[3];
    const float* Wk  = (const float*)d_in[4];
    const float* bk  = (const float*)d_in[5];
    const float* Wv  = (const float*)d_in[6];
    const float* bv  = (const float*)d_in[7];
    const int*   idx = (const int*)d_in[8];
    float* out = (float*)d_out;

    cudaFuncSetAttribute(k_proj_qk, cudaFuncAttributeMaxDynamicSharedMemorySize, SM_TOTAL);
    cudaFuncSetAttribute(k_proj_v,  cudaFuncAttributeMaxDynamicSharedMemorySize, SM_TOTAL);
    cudaFuncSetAttribute(k_qks,     cudaFuncAttributeMaxDynamicSharedMemorySize, SM_TOTAL);
    cudaFuncSetAttribute(k_scores,  cudaFuncAttributeMaxDynamicSharedMemorySize, SM_TOTAL);
    cudaFuncSetAttribute(k_upd,     cudaFuncAttributeMaxDynamicSharedMemorySize, SM_TOTAL);

    k_convW<<<3072, 256>>>(Wq, Wk, Wv);
    k_convX<<<dim3(LQ / 32, CC / 32, NB), dim3(32, 8)>>>(in1, in2);

    // proj: M = DD (o rows), N = LQ (s cols); CTA tile 128M x 256N
    k_proj_qk<<<dim3(LQ / 256, DD / 128, NB * 2), 256, SM_TOTAL>>>(bq, bk);
    k_proj_v <<<dim3(LQ / 256, DD / 128, NB),     256, SM_TOTAL>>>(bv);

    k_transV<<<dim3(DD / 32, LQ / 32, NB), dim3(32, 8)>>>();
    k_vmean1<<<dim3(16, NB), 512>>>();
    k_vmean2<<<NB, 512>>>();

    k_gather_ks<<<dim3(UP, NB), 128>>>(idx);
    k_qks<<<dim3(UP / 256, LQ / 128, NB), 256, SM_TOTAL>>>();
    k_mreduce<<<dim3(LQ / 8, NB), 256>>>();
    k_topk<<<NB, 1024>>>();
    k_gather_qr<<<dim3(UP, NB), 128>>>();

    k_scores<<<dim3(LQ / 256, UP / 128, NB), 256, SM_TOTAL>>>();
    k_softmax<<<dim3(UP, NB), 256>>>();
    k_upd<<<dim3(DD / 256, UP / 128, NB), 256, SM_TOTAL>>>();

    k_fill<<<4096, 256>>>(out);
    k_scatter<<<dim3(UU, NB), 256>>>(out);
}

// round 10
// speedup vs baseline: 2.4604x; 1.0375x over previous
#include <cuda_runtime.h>
#include <cuda_bf16.h>
#include <math_constants.h>
#include <cstdint>
#include <mma.h>

using namespace nvcuda;

#define NB 16
#define LQ 4096          // L
#define DD 512           // D
#define CC 512           // 2*Cin
#define UU 450           // top-k count
#define UP 512           // padded U
#define PER_BATCH (LQ*DD)

typedef __nv_bfloat16 bf16;

// ---------------- device scratch ----------------
__device__ float g_v[(size_t)NB*PER_BATCH];     // proj-V flat [o][4096] == v[l][d]
__device__ float g_S[(size_t)NB*PER_BATCH];     // scores [u][4096] (fp32)
__device__ float g_upd[(size_t)NB*UP*DD];
__device__ float g_M[NB*LQ];
__device__ int   g_topk[NB*UP];
__device__ int   g_ulookup[NB*LQ];              // l -> u or -1
__device__ float2 g_Mpart[NB*LQ*2];             // qks fused max/sum partials (2 N-tiles)
__device__ float g_smaxp[NB*UP*16];             // scores fused row-max partials (16 N-tiles)
__device__ float g_vpart[NB*16*DD];
__device__ float g_vmean[NB*DD];
__device__ float g_denom[NB*UP];

__device__ __align__(16) bf16 g_Whi[3*DD*CC],            g_Wlo[3*DD*CC];
__device__ __align__(16) bf16 g_XThi[(size_t)NB*LQ*CC],  g_XTlo[(size_t)NB*LQ*CC];  // [s][c]
__device__ __align__(16) bf16 g_Qhi[(size_t)NB*LQ*DD],   g_Qlo[(size_t)NB*LQ*DD];   // flat: [o][4096] == q[l][d]
__device__ __align__(16) bf16 g_Khi[(size_t)NB*LQ*DD],   g_Klo[(size_t)NB*LQ*DD];   // flat
__device__ __align__(16) bf16 g_KShi[(size_t)NB*UP*DD],  g_KSlo[(size_t)NB*UP*DD];  // [s][d]
__device__ __align__(16) bf16 g_QRhi[(size_t)NB*UP*DD],  g_QRlo[(size_t)NB*UP*DD];  // [u][d]
__device__ __align__(16) bf16 g_SEhi[(size_t)NB*UP*LQ],  g_SElo[(size_t)NB*UP*LQ];  // [u][l]
__device__ __align__(16) bf16 g_VThi[(size_t)NB*DD*LQ],  g_VTlo[(size_t)NB*DD*LQ];  // [d][l]

// ---------------- helpers ----------------
__device__ __forceinline__ uint32_t smem_u32(const void* p) {
    uint32_t a;
    asm("{ .reg .u64 t; cvta.to.shared.u64 t, %1; cvt.u32.u64 %0, t; }" : "=r"(a) : "l"(p));
    return a;
}
__device__ __forceinline__ void cpa16(uint32_t dst, const void* src) {
    asm volatile("cp.async.cg.shared.global [%0], [%1], 16;" :: "r"(dst), "l"(src));
}
__device__ __forceinline__ void cp_commit() { asm volatile("cp.async.commit_group;" ::: "memory"); }
template<int N> __device__ __forceinline__ void cp_wait() {
    asm volatile("cp.async.wait_group %0;" :: "n"(N) : "memory");
}
__device__ __forceinline__ bf16 hi_of(float x) { return __float2bfloat16(x); }
__device__ __forceinline__ bf16 lo_of(float x, bf16 h) { return __float2bfloat16(x - __bfloat162float(h)); }

// ============================================================================
// wmma GEMM: CTA tile 128(M) x 256(N), BK=32, 8 warps (2M x 4N), warp 64x64,
// double-buffered cp.async. A [Mtot][K], B [Ntot][K], both K-major hi/lo.
// 3-product split: Ah*Bh + Ah*Bl + Al*Bh, fp32 accum.
// EPI: 0 row-bias -> bf16 split | 1 row-bias -> fp32
//      2 qks: NO C write; masked (col<UU) row max/sum partials -> part(float2)
//      3 scores: alpha fp32 + row-max partials -> part(float)
//      4 row-denom fp32 (m<UU ? 1/aux[m] : 0)
// ============================================================================
#define SA 48                     // smem row stride in halfs (96B)
#define ARR_A (128*SA*2)          // 12288 B
#define ARR_B (256*SA*2)          // 24576 B
#define STAGE (2*ARR_A + 2*ARR_B) // 73728 B
#define SM_TOTAL (2*STAGE)        // 147456 B (C-stage 128*260*4=133120 reuses)

template<int EPI>
__device__ __forceinline__ void gemm_wmma(
    const bf16* __restrict__ Ahi, const bf16* __restrict__ Alo,
    const bf16* __restrict__ Bhi, const bf16* __restrict__ Blo, int K,
    float* __restrict__ C, bf16* __restrict__ Chi, bf16* __restrict__ Clo, int ldc,
    const float* __restrict__ aux, float alpha, float* __restrict__ part)
{
    extern __shared__ char sm[];
    const uint32_t smb = smem_u32(sm);
    const int tid = threadIdx.x, w = tid >> 5;
    const int mw = w >> 2, nw = w & 3;           // 2M x 4N warp grid
    const int m0 = blockIdx.y * 128, n0 = blockIdx.x * 256;
    const int NS = K >> 5;

    wmma::fragment<wmma::accumulator, 16, 16, 16, float> fc[4][4];
    #pragma unroll
    for (int i = 0; i < 4; i++)
        #pragma unroll
        for (int j = 0; j < 4; j++) wmma::fill_fragment(fc[i][j], 0.f);

    auto load_stage = [&](int s, int bufb) {
        const int k0 = s << 5;
        const uint32_t base = smb + bufb * STAGE;
        #pragma unroll
        for (int q = 0; q < 2; q++) {
            const bf16* src = q ? Alo : Ahi;
            const uint32_t dst = base + q * ARR_A;
            #pragma unroll
            for (int c0 = 0; c0 < 512; c0 += 256) {
                int c = c0 + tid;
                int row = c >> 2, col = c & 3;
                cpa16(dst + row * 96 + col * 16,
                      src + (size_t)(m0 + row) * K + k0 + col * 8);
            }
        }
        #pragma unroll
        for (int q = 0; q < 2; q++) {
            const bf16* src = q ? Blo : Bhi;
            const uint32_t dst = base + 2 * ARR_A + q * ARR_B;
            #pragma unroll
            for (int c0 = 0; c0 < 1024; c0 += 256) {
                int c = c0 + tid;
                int row = c >> 2, col = c & 3;
                cpa16(dst + row * 96 + col * 16,
                      src + (size_t)(n0 + row) * K + k0 + col * 8);
            }
        }
        cp_commit();
    };

    load_stage(0, 0);

    for (int s = 0; s < NS; s++) {
        const int b = s & 1;
        if (s + 1 < NS) { load_stage(s + 1, b ^ 1); cp_wait<1>(); }
        else            { cp_wait<0>(); }
        __syncthreads();

        const bf16* sAh = (const bf16*)(sm + b * STAGE);
        const bf16* sAl = (const bf16*)(sm + b * STAGE + ARR_A);
        const bf16* sBh = (const bf16*)(sm + b * STAGE + 2 * ARR_A);
        const bf16* sBl = (const bf16*)(sm + b * STAGE + 2 * ARR_A + ARR_B);

        #pragma unroll
        for (int ks = 0; ks < 2; ks++) {
            wmma::fragment<wmma::matrix_a, 16, 16, 16, bf16, wmma::row_major> fah[4], fal[4];
            #pragma unroll
            for (int i = 0; i < 4; i++) {
                const int r = mw * 64 + i * 16;
                wmma::load_matrix_sync(fah[i], sAh + r * SA + ks * 16, SA);
                wmma::load_matrix_sync(fal[i], sAl + r * SA + ks * 16, SA);
            }
            #pragma unroll
            for (int j = 0; j < 4; j++) {
                wmma::fragment<wmma::matrix_b, 16, 16, 16, bf16, wmma::col_major> fbh, fbl;
                const int n = nw * 64 + j * 16;
                wmma::load_matrix_sync(fbh, sBh + n * SA + ks * 16, SA);
                wmma::load_matrix_sync(fbl, sBl + n * SA + ks * 16, SA);
                #pragma unroll
                for (int i = 0; i < 4; i++) {
                    wmma::mma_sync(fc[i][j], fah[i], fbh, fc[i][j]);
                    wmma::mma_sync(fc[i][j], fah[i], fbl, fc[i][j]);
                    wmma::mma_sync(fc[i][j], fal[i], fbh, fc[i][j]);
                }
            }
        }
        __syncthreads();
    }

    // ---- epilogue via smem C-stage (known layout), 128 x 260 fp32 ----
    float* csm = (float*)sm;
    #pragma unroll
    for (int i = 0; i < 4; i++)
        #pragma unroll
        for (int j = 0; j < 4; j++)
            wmma::store_matrix_sync(csm + (mw*64 + i*16) * 260 + nw*64 + j*16,
                                    fc[i][j], 260, wmma::mem_row_major);
    __syncthreads();

    const int r = tid >> 1, gm = m0 + r;
    const int cb0 = (tid & 1) * 128;
    const float* src = csm + r * 260 + cb0;

    if (EPI == 0) {                       // row bias -> bf16 hi/lo split
        const float add = aux[gm];
        #pragma unroll
        for (int g = 0; g < 4; g++) {
            ushort hs[32], ls[32];
            #pragma unroll
            for (int c = 0; c < 32; c++) {
                float v = src[g * 32 + c] + add;
                bf16 h = hi_of(v);
                hs[c] = __bfloat16_as_ushort(h);
                ls[c] = __bfloat16_as_ushort(lo_of(v, h));
            }
            bf16* ph = Chi + (size_t)gm * ldc + n0 + cb0 + g * 32;
            bf16* pl = Clo + (size_t)gm * ldc + n0 + cb0 + g * 32;
            #pragma unroll
            for (int j = 0; j < 4; j++) {
                *(uint4*)(ph + j * 8) = *(uint4*)&hs[j * 8];
                *(uint4*)(pl + j * 8) = *(uint4*)&ls[j * 8];
            }
        }
    } else if (EPI == 2) {                // qks: masked row max/sum, no C write
        float mx = -CUDART_INF_F, smv = 0.f;
        #pragma unroll 8
        for (int c = 0; c < 128; c++) {
            int scol = n0 + cb0 + c;
            if (scol < UU) { float v = src[c]; mx = fmaxf(mx, v); smv += v; }
        }
        float mx2 = fmaxf(mx, __shfl_xor_sync(0xffffffffu, mx, 1));
        float sm2 = smv + __shfl_xor_sync(0xffffffffu, smv, 1);
        if ((tid & 1) == 0)
            ((float2*)part)[gm * 2 + blockIdx.x] = make_float2(mx2, sm2);
    } else {
        float add = 0.f, mul = 1.f;
        if (EPI == 1) add = aux[gm];
        if (EPI == 3) mul = alpha;
        if (EPI == 4) mul = (gm < UU) ? (1.f / aux[gm]) : 0.f;
        float* pc = C + (size_t)gm * ldc + n0 + cb0;
        float mx = -CUDART_INF_F;
        #pragma unroll
        for (int j = 0; j < 32; j++) {
            float4 v = *(const float4*)(src + j * 4);
            v.x = v.x * mul + add; v.y = v.y * mul + add;
            v.z = v.z * mul + add; v.w = v.w * mul + add;
            if (EPI == 3) mx = fmaxf(mx, fmaxf(fmaxf(v.x, v.y), fmaxf(v.z, v.w)));
            *(float4*)(pc + j * 4) = v;
        }
        if (EPI == 3) {
            float mx2 = fmaxf(mx, __shfl_xor_sync(0xffffffffu, mx, 1));
            if ((tid & 1) == 0) part[gm * 16 + blockIdx.x] = mx2;
        }
    }
}

// ---------------- GEMM wrappers (1 CTA/SM) ----------------
__global__ __launch_bounds__(256, 1) void k_proj_qk(const float* __restrict__ bq,
                                                    const float* __restrict__ bk)
{
    int z = blockIdx.z, mi = z >> 4, b = z & 15;
    gemm_wmma<0>(g_Whi + (size_t)mi*DD*CC, g_Wlo + (size_t)mi*DD*CC,
                 g_XThi + (size_t)b*LQ*CC, g_XTlo + (size_t)b*LQ*CC, CC,
                 nullptr,
                 (mi ? g_Khi : g_Qhi) + (size_t)b*PER_BATCH,
                 (mi ? g_Klo : g_Qlo) + (size_t)b*PER_BATCH, LQ,
                 mi ? bk : bq, 1.f, nullptr);
}
__global__ __launch_bounds__(256, 1) void k_proj_v(const float* __restrict__ bv)
{
    int b = blockIdx.z;
    gemm_wmma<1>(g_Whi + (size_t)2*DD*CC, g_Wlo + (size_t)2*DD*CC,
                 g_XThi + (size_t)b*LQ*CC, g_XTlo + (size_t)b*LQ*CC, CC,
                 g_v + (size_t)b*PER_BATCH, nullptr, nullptr, LQ,
                 bv, 1.f, nullptr);
}
// QKs fused: only max/sum partials, no matrix output
__global__ __launch_bounds__(256, 1) void k_qks()
{
    int b = blockIdx.z;
    gemm_wmma<2>(g_Qhi + (size_t)b*PER_BATCH, g_Qlo + (size_t)b*PER_BATCH,
                 g_KShi + (size_t)b*UP*DD, g_KSlo + (size_t)b*UP*DD, DD,
                 nullptr, nullptr, nullptr, UP, nullptr, 1.f,
                 (float*)(g_Mpart + (size_t)b*LQ*2));
}
__global__ __launch_bounds__(256, 1) void k_scores()
{
    int b = blockIdx.z;
    gemm_wmma<3>(g_QRhi + (size_t)b*UP*DD, g_QRlo + (size_t)b*UP*DD,
                 g_Khi + (size_t)b*PER_BATCH, g_Klo + (size_t)b*PER_BATCH, DD,
                 g_S + (size_t)b*PER_BATCH, nullptr, nullptr, LQ, nullptr,
                 0.044194173824159216f, g_smaxp + (size_t)b*UP*16);
}
__global__ __launch_bounds__(256, 1) void k_upd()
{
    int b = blockIdx.z;
    gemm_wmma<4>(g_SEhi + (size_t)b*UP*LQ, g_SElo + (size_t)b*UP*LQ,
                 g_VThi + (size_t)b*DD*LQ, g_VTlo + (size_t)b*DD*LQ, LQ,
                 g_upd + (size_t)b*UP*DD, nullptr, nullptr, DD,
                 g_denom + b*UP, 1.f, nullptr);
}

// ---------------- conversions ----------------
__global__ void k_convW(const float* __restrict__ Wq, const float* __restrict__ Wk,
                        const float* __restrict__ Wv)
{
    int i = blockIdx.x * 256 + threadIdx.x;
    int mi = i >> 18, r = i & 262143;
    const float* W = (mi == 0) ? Wq : (mi == 1) ? Wk : Wv;
    float x = W[r];
    bf16 h = hi_of(x);
    g_Whi[i] = h; g_Wlo[i] = lo_of(x, h);
}

__global__ void k_convX(const float* __restrict__ in1, const float* __restrict__ in2)
{
    __shared__ float t[32][33];
    int b = blockIdx.z, s0 = blockIdx.x * 32, c0 = blockIdx.y * 32;
    const float* src = (c0 < 256) ? (in1 + ((size_t)b * 256 + c0) * LQ)
                                  : (in2 + ((size_t)b * 256 + (c0 - 256)) * LQ);
    for (int i = threadIdx.y; i < 32; i += 8)
        t[i][threadIdx.x] = src[(size_t)i * LQ + s0 + threadIdx.x];
    __syncthreads();
    for (int i = threadIdx.y; i < 32; i += 8) {
        float x = t[threadIdx.x][i];
        bf16 h = hi_of(x);
        size_t off = ((size_t)b * LQ + s0 + i) * CC + c0 + threadIdx.x;
        g_XThi[off] = h; g_XTlo[off] = lo_of(x, h);
    }
}

__global__ void k_transV()
{
    __shared__ float t[32][33];
    int b = blockIdx.z, d0 = blockIdx.x * 32, l0 = blockIdx.y * 32;
    const float* src = g_v + (size_t)b * PER_BATCH;
    for (int i = threadIdx.y; i < 32; i += 8)
        t[i][threadIdx.x] = src[(size_t)(l0 + i) * DD + d0 + threadIdx.x];
    __syncthreads();
    for (int i = threadIdx.y; i < 32; i += 8) {
        float x = t[threadIdx.x][i];
        bf16 h = hi_of(x);
        size_t off = ((size_t)b * DD + d0 + i) * LQ + l0 + threadIdx.x;
        g_VThi[off] = h; g_VTlo[off] = lo_of(x, h);
    }
}

// ---------------- gathers ----------------
__global__ void k_gather_ks(const int* __restrict__ idx)
{
    int b = blockIdx.y, s = blockIdx.x, t = threadIdx.x;
    size_t drow = ((size_t)b * UP + s) * DD;
    uint2* dh = (uint2*)(g_KShi + drow);
    uint2* dl = (uint2*)(g_KSlo + drow);
    if (s < UU) {
        size_t srow = ((size_t)b * LQ + idx[s]) * DD;
        dh[t] = ((const uint2*)(g_Khi + srow))[t];
        dl[t] = ((const uint2*)(g_Klo + srow))[t];
    } else {
        dh[t] = make_uint2(0, 0); dl[t] = make_uint2(0, 0);
    }
}
__global__ void k_gather_qr()
{
    int b = blockIdx.y, u = blockIdx.x, t = threadIdx.x;
    size_t drow = ((size_t)b * UP + u) * DD;
    uint2* dh = (uint2*)(g_QRhi + drow);
    uint2* dl = (uint2*)(g_QRlo + drow);
    if (u < UU) {
        size_t srow = ((size_t)b * LQ + g_topk[b * UP + u]) * DD;
        dh[t] = ((const uint2*)(g_Qhi + srow))[t];
        dl[t] = ((const uint2*)(g_Qlo + srow))[t];
    } else {
        dh[t] = make_uint2(0, 0); dl[t] = make_uint2(0, 0);
    }
}

// ---------------- M combine (from qks fused partials) ----------------
__global__ void k_mcombine()
{
    int i = blockIdx.x * 256 + threadIdx.x;      // i = b*LQ + l
    float2 p0 = g_Mpart[i * 2 + 0];
    float2 p1 = g_Mpart[i * 2 + 1];
    g_M[i] = fmaxf(p0.x, p1.x) - (p0.y + p1.y) * (1.0f / LQ);
}

// ---------------- top-k + inverse lookup ----------------
__global__ __launch_bounds__(1024) void k_topk()
{
    __shared__ float sv[LQ];
    __shared__ int   si[LQ];
    int b = blockIdx.x;
    for (int i = threadIdx.x; i < LQ; i += 1024) {
        sv[i] = g_M[b * LQ + i]; si[i] = i;
        g_ulookup[b * LQ + i] = -1;
    }
    __syncthreads();
    for (int k = 2; k <= LQ; k <<= 1) {
        for (int j = k >> 1; j > 0; j >>= 1) {
            for (int t = threadIdx.x; t < LQ / 2; t += 1024) {
                int i = ((t & ~(j - 1)) << 1) | (t & (j - 1));
                int ixj = i | j;
                bool desc = ((i & k) == 0);
                float a = sv[i], c = sv[ixj];
                bool sw = desc ? (a < c) : (a > c);
                if (sw) { sv[i] = c; sv[ixj] = a; int ti = si[i]; si[i] = si[ixj]; si[ixj] = ti; }
            }
            __syncthreads();
        }
    }
    for (int u = threadIdx.x; u < UU; u += 1024) {
        g_topk[b * UP + u] = si[u];
        g_ulookup[b * LQ + si[u]] = u;
    }
}

// ---------------- softmax (single pass; max from scores partials) ----------------
__global__ __launch_bounds__(256) void k_softmax()
{
    int b = blockIdx.y, u = blockIdx.x, t = threadIdx.x;
    size_t off = (size_t)b * PER_BATCH + (size_t)u * LQ;
    bf16* eh = g_SEhi + off;
    bf16* el = g_SElo + off;
    if (u >= UU) {
        for (int l = t; l < LQ; l += 256) { eh[l] = __ushort_as_bfloat16(0); el[l] = __ushort_as_bfloat16(0); }
        if (t == 0) g_denom[b * UP + u] = 1.f;
        return;
    }
    const float* mp = g_smaxp + ((size_t)b * UP + u) * 16;
    float mx = -CUDART_INF_F;
    #pragma unroll
    for (int i = 0; i < 16; i++) mx = fmaxf(mx, mp[i]);

    const float* row = g_S + off;
    __shared__ float red[256];
    float sm = 0.f;
    for (int l = t; l < LQ; l += 256) {
        float e = expf(row[l] - mx);
        bf16 h = hi_of(e);
        eh[l] = h; el[l] = lo_of(e, h);
        sm += e;
    }
    red[t] = sm; __syncthreads();
    for (int o = 128; o; o >>= 1) { if (t < o) red[t] += red[t + o]; __syncthreads(); }
    if (t == 0) g_denom[b * UP + u] = red[0];
}

// ---------------- V column means ----------------
__global__ void k_vmean1()
{
    int b = blockIdx.y, c = blockIdx.x;
    const float* V = g_v + (size_t)b * PER_BATCH + (size_t)c * 256 * DD;
    int d = threadIdx.x;
    float acc = 0.f;
    #pragma unroll 4
    for (int l = 0; l < 256; l++) acc += V[l * DD + d];
    g_vpart[((size_t)b * 16 + c) * DD + d] = acc;
}
__global__ void k_vmean2()
{
    int b = blockIdx.x, d = threadIdx.x;
    float acc = 0.f;
    #pragma unroll
    for (int c = 0; c < 16; c++) acc += g_vpart[((size_t)b * 16 + c) * DD + d];
    g_vmean[b * DD + d] = acc * (1.0f / LQ);
}

// ---------------- fused output: vmean broadcast or upd row ----------------
__global__ void k_output(float* __restrict__ out)
{
    int b = blockIdx.y, l = blockIdx.x, t = threadIdx.x;
    int u = g_ulookup[b * LQ + l];
    const float4* src = (u >= 0)
        ? (const float4*)(g_upd + ((size_t)b * UP + u) * DD)
        : (const float4*)(g_vmean + (size_t)b * DD);
    ((float4*)(out + (size_t)b * PER_BATCH + (size_t)l * DD))[t] = src[t];
}

// ---------------- launch ----------------
extern "C" void kernel_launch(void* const* d_in, const int* in_sizes, int n_in,
                              void* d_out, int out_size)
{
    const float* in1 = (const float*)d_in[0];
    const float* in2 = (const float*)d_in[1];
    const float* Wq  = (const float*)d_in[2];
    const float* bq  = (const float*)d_in[3];
    const float* Wk  = (const float*)d_in[4];
    const float* bk  = (const float*)d_in[5];
    const float* Wv  = (const float*)d_in[6];
    const float* bv  = (const float*)d_in[7];
    const int*   idx = (const int*)d_in[8];
    float* out = (float*)d_out;

    cudaFuncSetAttribute(k_proj_qk, cudaFuncAttributeMaxDynamicSharedMemorySize, SM_TOTAL);
    cudaFuncSetAttribute(k_proj_v,  cudaFuncAttributeMaxDynamicSharedMemorySize, SM_TOTAL);
    cudaFuncSetAttribute(k_qks,     cudaFuncAttributeMaxDynamicSharedMemorySize, SM_TOTAL);
    cudaFuncSetAttribute(k_scores,  cudaFuncAttributeMaxDynamicSharedMemorySize, SM_TOTAL);
    cudaFuncSetAttribute(k_upd,     cudaFuncAttributeMaxDynamicSharedMemorySize, SM_TOTAL);

    k_convW<<<3072, 256>>>(Wq, Wk, Wv);
    k_convX<<<dim3(LQ / 32, CC / 32, NB), dim3(32, 8)>>>(in1, in2);

    k_proj_qk<<<dim3(LQ / 256, DD / 128, NB * 2), 256, SM_TOTAL>>>(bq, bk);
    k_proj_v <<<dim3(LQ / 256, DD / 128, NB),     256, SM_TOTAL>>>(bv);

    k_transV<<<dim3(DD / 32, LQ / 32, NB), dim3(32, 8)>>>();
    k_vmean1<<<dim3(16, NB), 512>>>();
    k_vmean2<<<NB, 512>>>();

    k_gather_ks<<<dim3(UP, NB), 128>>>(idx);
    k_qks<<<dim3(UP / 256, LQ / 128, NB), 256, SM_TOTAL>>>();
    k_mcombine<<<NB * LQ / 256, 256>>>();
    k_topk<<<NB, 1024>>>();
    k_gather_qr<<<dim3(UP, NB), 128>>>();

    k_scores<<<dim3(LQ / 256, UP / 128, NB), 256, SM_TOTAL>>>();
    k_softmax<<<dim3(UP, NB), 256>>>();
    k_upd<<<dim3(DD / 256, UP / 128, NB), 256, SM_TOTAL>>>();

    k_output<<<dim3(LQ, NB), 128>>>(out);
}

// round 11
// speedup vs baseline: 2.5346x; 1.0301x over previous
#include <cuda_runtime.h>
#include <cuda_bf16.h>
#include <math_constants.h>
#include <cstdint>
#include <mma.h>

using namespace nvcuda;

#define NB 16
#define LQ 4096          // L
#define DD 512           // D
#define CC 512           // 2*Cin
#define UU 450           // top-k count
#define UP 512           // padded U
#define PER_BATCH (LQ*DD)

typedef __nv_bfloat16 bf16;

// ---------------- device scratch ----------------
__device__ float g_v[(size_t)NB*PER_BATCH];     // proj-V flat [o][4096] == v[l][d]
__device__ float g_S[(size_t)NB*PER_BATCH];     // scores [u][4096] (fp32)
__device__ float g_updA[(size_t)NB*UP*DD];      // upd partial K half 0
__device__ float g_updB[(size_t)NB*UP*DD];      // upd partial K half 1
__device__ int   g_topk[NB*UP];
__device__ int   g_ulookup[NB*LQ];              // l -> u or -1
__device__ float2 g_Mpart[NB*LQ*2];             // qks fused max/sum partials (2 N-tiles)
__device__ float g_smaxp[NB*UP*16];             // scores fused row-max partials (16 N-tiles)
__device__ float g_vpart[NB*16*DD];
__device__ float g_vmean[NB*DD];
__device__ float g_denom[NB*UP];

__device__ __align__(16) bf16 g_Whi[3*DD*CC],            g_Wlo[3*DD*CC];
__device__ __align__(16) bf16 g_XThi[(size_t)NB*LQ*CC],  g_XTlo[(size_t)NB*LQ*CC];  // [s][c]
__device__ __align__(16) bf16 g_Qhi[(size_t)NB*LQ*DD],   g_Qlo[(size_t)NB*LQ*DD];   // flat: [o][4096] == q[l][d]
__device__ __align__(16) bf16 g_Khi[(size_t)NB*LQ*DD],   g_Klo[(size_t)NB*LQ*DD];   // flat
__device__ __align__(16) bf16 g_KShi[(size_t)NB*UP*DD],  g_KSlo[(size_t)NB*UP*DD];  // [s][d]
__device__ __align__(16) bf16 g_QRhi[(size_t)NB*UP*DD],  g_QRlo[(size_t)NB*UP*DD];  // [u][d]
__device__ __align__(16) bf16 g_SEhi[(size_t)NB*UP*LQ],  g_SElo[(size_t)NB*UP*LQ];  // [u][l]
__device__ __align__(16) bf16 g_VThi[(size_t)NB*DD*LQ],  g_VTlo[(size_t)NB*DD*LQ];  // [d][l]

// ---------------- helpers ----------------
__device__ __forceinline__ uint32_t smem_u32(const void* p) {
    uint32_t a;
    asm("{ .reg .u64 t; cvta.to.shared.u64 t, %1; cvt.u32.u64 %0, t; }" : "=r"(a) : "l"(p));
    return a;
}
__device__ __forceinline__ void cpa16(uint32_t dst, const void* src) {
    asm volatile("cp.async.cg.shared.global [%0], [%1], 16;" :: "r"(dst), "l"(src));
}
__device__ __forceinline__ void cp_commit() { asm volatile("cp.async.commit_group;" ::: "memory"); }
template<int N> __device__ __forceinline__ void cp_wait() {
    asm volatile("cp.async.wait_group %0;" :: "n"(N) : "memory");
}
__device__ __forceinline__ bf16 hi_of(float x) { return __float2bfloat16(x); }
__device__ __forceinline__ bf16 lo_of(float x, bf16 h) { return __float2bfloat16(x - __bfloat162float(h)); }

// ============================================================================
// wmma GEMM: CTA tile 128(M) x 256(N), BK=32, 8 warps (2M x 4N), warp 64x64,
// double-buffered cp.async. A [Mtot][lda] K-major hi/lo, B [Ntot][lda] hi/lo.
// NPROD=3: Ah*Bh + Ah*Bl + Al*Bh.  NPROD=2: Ah*Bh + Al*Bh (B hi only, Blo unloaded).
// KEXT = K extent of this pass; lda = row stride (supports K-split).
// EPI: 0 row-bias -> bf16 split | 1 row-bias -> fp32
//      2 qks: NO C write; masked (col<UU) row max/sum partials -> part(float2)
//      3 scores: alpha fp32 + row-max partials -> part(float)
//      4 plain fp32 (upd partial)
// ============================================================================
#define SA 48                     // smem row stride in halfs (96B)
#define ARR_A (128*SA*2)          // 12288 B
#define ARR_B (256*SA*2)          // 24576 B
#define STAGE (2*ARR_A + 2*ARR_B) // 73728 B
#define SM_TOTAL (2*STAGE)        // 147456 B (C-stage 128*260*4=133120 reuses)

template<int EPI, int NPROD>
__device__ __forceinline__ void gemm_wmma(
    const bf16* __restrict__ Ahi, const bf16* __restrict__ Alo,
    const bf16* __restrict__ Bhi, const bf16* __restrict__ Blo,
    int KEXT, int lda,
    float* __restrict__ C, bf16* __restrict__ Chi, bf16* __restrict__ Clo, int ldc,
    const float* __restrict__ aux, float alpha, float* __restrict__ part)
{
    extern __shared__ char sm[];
    const uint32_t smb = smem_u32(sm);
    const int tid = threadIdx.x, w = tid >> 5;
    const int mw = w >> 2, nw = w & 3;           // 2M x 4N warp grid
    const int m0 = blockIdx.y * 128, n0 = blockIdx.x * 256;
    const int NS = KEXT >> 5;

    wmma::fragment<wmma::accumulator, 16, 16, 16, float> fc[4][4];
    #pragma unroll
    for (int i = 0; i < 4; i++)
        #pragma unroll
        for (int j = 0; j < 4; j++) wmma::fill_fragment(fc[i][j], 0.f);

    auto load_stage = [&](int s, int bufb) {
        const int k0 = s << 5;
        const uint32_t base = smb + bufb * STAGE;
        #pragma unroll
        for (int q = 0; q < 2; q++) {
            const bf16* src = q ? Alo : Ahi;
            const uint32_t dst = base + q * ARR_A;
            #pragma unroll
            for (int c0 = 0; c0 < 512; c0 += 256) {
                int c = c0 + tid;
                int row = c >> 2, col = c & 3;
                cpa16(dst + row * 96 + col * 16,
                      src + (size_t)(m0 + row) * lda + k0 + col * 8);
            }
        }
        #pragma unroll
        for (int q = 0; q < 2; q++) {
            if (NPROD == 2 && q == 1) break;     // skip Blo entirely
            const bf16* src = q ? Blo : Bhi;
            const uint32_t dst = base + 2 * ARR_A + q * ARR_B;
            #pragma unroll
            for (int c0 = 0; c0 < 1024; c0 += 256) {
                int c = c0 + tid;
                int row = c >> 2, col = c & 3;
                cpa16(dst + row * 96 + col * 16,
                      src + (size_t)(n0 + row) * lda + k0 + col * 8);
            }
        }
        cp_commit();
    };

    load_stage(0, 0);

    for (int s = 0; s < NS; s++) {
        const int b = s & 1;
        if (s + 1 < NS) { load_stage(s + 1, b ^ 1); cp_wait<1>(); }
        else            { cp_wait<0>(); }
        __syncthreads();

        const bf16* sAh = (const bf16*)(sm + b * STAGE);
        const bf16* sAl = (const bf16*)(sm + b * STAGE + ARR_A);
        const bf16* sBh = (const bf16*)(sm + b * STAGE + 2 * ARR_A);
        const bf16* sBl = (const bf16*)(sm + b * STAGE + 2 * ARR_A + ARR_B);

        #pragma unroll
        for (int ks = 0; ks < 2; ks++) {
            wmma::fragment<wmma::matrix_a, 16, 16, 16, bf16, wmma::row_major> fah[4], fal[4];
            #pragma unroll
            for (int i = 0; i < 4; i++) {
                const int r = mw * 64 + i * 16;
                wmma::load_matrix_sync(fah[i], sAh + r * SA + ks * 16, SA);
                wmma::load_matrix_sync(fal[i], sAl + r * SA + ks * 16, SA);
            }
            #pragma unroll
            for (int j = 0; j < 4; j++) {
                wmma::fragment<wmma::matrix_b, 16, 16, 16, bf16, wmma::col_major> fbh, fbl;
                const int n = nw * 64 + j * 16;
                wmma::load_matrix_sync(fbh, sBh + n * SA + ks * 16, SA);
                if (NPROD == 3)
                    wmma::load_matrix_sync(fbl, sBl + n * SA + ks * 16, SA);
                #pragma unroll
                for (int i = 0; i < 4; i++) {
                    wmma::mma_sync(fc[i][j], fah[i], fbh, fc[i][j]);
                    if (NPROD == 3)
                        wmma::mma_sync(fc[i][j], fah[i], fbl, fc[i][j]);
                    wmma::mma_sync(fc[i][j], fal[i], fbh, fc[i][j]);
                }
            }
        }
        __syncthreads();
    }

    // ---- epilogue via smem C-stage (known layout), 128 x 260 fp32 ----
    float* csm = (float*)sm;
    #pragma unroll
    for (int i = 0; i < 4; i++)
        #pragma unroll
        for (int j = 0; j < 4; j++)
            wmma::store_matrix_sync(csm + (mw*64 + i*16) * 260 + nw*64 + j*16,
                                    fc[i][j], 260, wmma::mem_row_major);
    __syncthreads();

    const int r = tid >> 1, gm = m0 + r;
    const int cb0 = (tid & 1) * 128;
    const float* src = csm + r * 260 + cb0;

    if (EPI == 0) {                       // row bias -> bf16 hi/lo split
        const float add = aux[gm];
        #pragma unroll
        for (int g = 0; g < 4; g++) {
            ushort hs[32], ls[32];
            #pragma unroll
            for (int c = 0; c < 32; c++) {
                float v = src[g * 32 + c] + add;
                bf16 h = hi_of(v);
                hs[c] = __bfloat16_as_ushort(h);
                ls[c] = __bfloat16_as_ushort(lo_of(v, h));
            }
            bf16* ph = Chi + (size_t)gm * ldc + n0 + cb0 + g * 32;
            bf16* pl = Clo + (size_t)gm * ldc + n0 + cb0 + g * 32;
            #pragma unroll
            for (int j = 0; j < 4; j++) {
                *(uint4*)(ph + j * 8) = *(uint4*)&hs[j * 8];
                *(uint4*)(pl + j * 8) = *(uint4*)&ls[j * 8];
            }
        }
    } else if (EPI == 2) {                // qks: masked row max/sum, no C write
        float mx = -CUDART_INF_F, smv = 0.f;
        #pragma unroll 8
        for (int c = 0; c < 128; c++) {
            int scol = n0 + cb0 + c;
            if (scol < UU) { float v = src[c]; mx = fmaxf(mx, v); smv += v; }
        }
        float mx2 = fmaxf(mx, __shfl_xor_sync(0xffffffffu, mx, 1));
        float sm2 = smv + __shfl_xor_sync(0xffffffffu, smv, 1);
        if ((tid & 1) == 0)
            ((float2*)part)[gm * 2 + blockIdx.x] = make_float2(mx2, sm2);
    } else {
        float add = 0.f, mul = 1.f;
        if (EPI == 1) add = aux[gm];
        if (EPI == 3) mul = alpha;
        float* pc = C + (size_t)gm * ldc + n0 + cb0;
        float mx = -CUDART_INF_F;
        #pragma unroll
        for (int j = 0; j < 32; j++) {
            float4 v = *(const float4*)(src + j * 4);
            v.x = v.x * mul + add; v.y = v.y * mul + add;
            v.z = v.z * mul + add; v.w = v.w * mul + add;
            if (EPI == 3) mx = fmaxf(mx, fmaxf(fmaxf(v.x, v.y), fmaxf(v.z, v.w)));
            *(float4*)(pc + j * 4) = v;
        }
        if (EPI == 3) {
            float mx2 = fmaxf(mx, __shfl_xor_sync(0xffffffffu, mx, 1));
            if ((tid & 1) == 0) part[gm * 16 + blockIdx.x] = mx2;
        }
    }
}

// ---------------- GEMM wrappers (1 CTA/SM) ----------------
__global__ __launch_bounds__(256, 1) void k_proj_qk(const float* __restrict__ bq,
                                                    const float* __restrict__ bk)
{
    int z = blockIdx.z, mi = z >> 4, b = z & 15;
    gemm_wmma<0, 3>(g_Whi + (size_t)mi*DD*CC, g_Wlo + (size_t)mi*DD*CC,
                    g_XThi + (size_t)b*LQ*CC, g_XTlo + (size_t)b*LQ*CC, CC, CC,
                    nullptr,
                    (mi ? g_Khi : g_Qhi) + (size_t)b*PER_BATCH,
                    (mi ? g_Klo : g_Qlo) + (size_t)b*PER_BATCH, LQ,
                    mi ? bk : bq, 1.f, nullptr);
}
__global__ __launch_bounds__(256, 1) void k_proj_v(const float* __restrict__ bv)
{
    int b = blockIdx.z;
    gemm_wmma<1, 3>(g_Whi + (size_t)2*DD*CC, g_Wlo + (size_t)2*DD*CC,
                    g_XThi + (size_t)b*LQ*CC, g_XTlo + (size_t)b*LQ*CC, CC, CC,
                    g_v + (size_t)b*PER_BATCH, nullptr, nullptr, LQ,
                    bv, 1.f, nullptr);
}
// QKs fused: only max/sum partials, no matrix output (3-product: feeds top-k)
__global__ __launch_bounds__(256, 1) void k_qks()
{
    int b = blockIdx.z;
    gemm_wmma<2, 3>(g_Qhi + (size_t)b*PER_BATCH, g_Qlo + (size_t)b*PER_BATCH,
                    g_KShi + (size_t)b*UP*DD, g_KSlo + (size_t)b*UP*DD, DD, DD,
                    nullptr, nullptr, nullptr, UP, nullptr, 1.f,
                    (float*)(g_Mpart + (size_t)b*LQ*2));
}
// scores: 2-product (QR split x K_hi) — logit error ~4e-4, inside budget
__global__ __launch_bounds__(256, 1) void k_scores()
{
    int b = blockIdx.z;
    gemm_wmma<3, 2>(g_QRhi + (size_t)b*UP*DD, g_QRlo + (size_t)b*UP*DD,
                    g_Khi + (size_t)b*PER_BATCH, nullptr, DD, DD,
                    g_S + (size_t)b*PER_BATCH, nullptr, nullptr, LQ, nullptr,
                    0.044194173824159216f, g_smaxp + (size_t)b*UP*16);
}
// upd partial: K split in halves; z = half*16 + b
__global__ __launch_bounds__(256, 1) void k_upd()
{
    int z = blockIdx.z, h = z >> 4, b = z & 15;
    const size_t koff = (size_t)h * 2048;
    float* dst = (h ? g_updB : g_updA) + (size_t)b*UP*DD;
    gemm_wmma<4, 3>(g_SEhi + (size_t)b*UP*LQ + koff, g_SElo + (size_t)b*UP*LQ + koff,
                    g_VThi + (size_t)b*DD*LQ + koff, g_VTlo + (size_t)b*DD*LQ + koff,
                    2048, LQ,
                    dst, nullptr, nullptr, DD, nullptr, 1.f, nullptr);
}

// ---------------- conversions ----------------
__global__ void k_convW(const float* __restrict__ Wq, const float* __restrict__ Wk,
                        const float* __restrict__ Wv)
{
    int i = blockIdx.x * 256 + threadIdx.x;
    int mi = i >> 18, r = i & 262143;
    const float* W = (mi == 0) ? Wq : (mi == 1) ? Wk : Wv;
    float x = W[r];
    bf16 h = hi_of(x);
    g_Whi[i] = h; g_Wlo[i] = lo_of(x, h);
}

__global__ void k_convX(const float* __restrict__ in1, const float* __restrict__ in2)
{
    __shared__ float t[32][33];
    int b = blockIdx.z, s0 = blockIdx.x * 32, c0 = blockIdx.y * 32;
    const float* src = (c0 < 256) ? (in1 + ((size_t)b * 256 + c0) * LQ)
                                  : (in2 + ((size_t)b * 256 + (c0 - 256)) * LQ);
    for (int i = threadIdx.y; i < 32; i += 8)
        t[i][threadIdx.x] = src[(size_t)i * LQ + s0 + threadIdx.x];
    __syncthreads();
    for (int i = threadIdx.y; i < 32; i += 8) {
        float x = t[threadIdx.x][i];
        bf16 h = hi_of(x);
        size_t off = ((size_t)b * LQ + s0 + i) * CC + c0 + threadIdx.x;
        g_XThi[off] = h; g_XTlo[off] = lo_of(x, h);
    }
}

__global__ void k_transV()
{
    __shared__ float t[32][33];
    int b = blockIdx.z, d0 = blockIdx.x * 32, l0 = blockIdx.y * 32;
    const float* src = g_v + (size_t)b * PER_BATCH;
    for (int i = threadIdx.y; i < 32; i += 8)
        t[i][threadIdx.x] = src[(size_t)(l0 + i) * DD + d0 + threadIdx.x];
    __syncthreads();
    for (int i = threadIdx.y; i < 32; i += 8) {
        float x = t[threadIdx.x][i];
        bf16 h = hi_of(x);
        size_t off = ((size_t)b * DD + d0 + i) * LQ + l0 + threadIdx.x;
        g_VThi[off] = h; g_VTlo[off] = lo_of(x, h);
    }
}

// ---------------- gathers ----------------
__global__ void k_gather_ks(const int* __restrict__ idx)
{
    int b = blockIdx.y, s = blockIdx.x, t = threadIdx.x;
    size_t drow = ((size_t)b * UP + s) * DD;
    uint2* dh = (uint2*)(g_KShi + drow);
    uint2* dl = (uint2*)(g_KSlo + drow);
    if (s < UU) {
        size_t srow = ((size_t)b * LQ + idx[s]) * DD;
        dh[t] = ((const uint2*)(g_Khi + srow))[t];
        dl[t] = ((const uint2*)(g_Klo + srow))[t];
    } else {
        dh[t] = make_uint2(0, 0); dl[t] = make_uint2(0, 0);
    }
}
__global__ void k_gather_qr()
{
    int b = blockIdx.y, u = blockIdx.x, t = threadIdx.x;
    size_t drow = ((size_t)b * UP + u) * DD;
    uint2* dh = (uint2*)(g_QRhi + drow);
    uint2* dl = (uint2*)(g_QRlo + drow);
    if (u < UU) {
        size_t srow = ((size_t)b * LQ + g_topk[b * UP + u]) * DD;
        dh[t] = ((const uint2*)(g_Qhi + srow))[t];
        dl[t] = ((const uint2*)(g_Qlo + srow))[t];
    } else {
        dh[t] = make_uint2(0, 0); dl[t] = make_uint2(0, 0);
    }
}

// ---------------- top-k (M from qks partials) + inverse lookup ----------------
__global__ __launch_bounds__(1024) void k_topk()
{
    __shared__ float sv[LQ];
    __shared__ int   si[LQ];
    int b = blockIdx.x;
    for (int i = threadIdx.x; i < LQ; i += 1024) {
        float2 p0 = g_Mpart[(size_t)(b * LQ + i) * 2 + 0];
        float2 p1 = g_Mpart[(size_t)(b * LQ + i) * 2 + 1];
        sv[i] = fmaxf(p0.x, p1.x) - (p0.y + p1.y) * (1.0f / LQ);
        si[i] = i;
        g_ulookup[b * LQ + i] = -1;
    }
    __syncthreads();
    for (int k = 2; k <= LQ; k <<= 1) {
        for (int j = k >> 1; j > 0; j >>= 1) {
            for (int t = threadIdx.x; t < LQ / 2; t += 1024) {
                int i = ((t & ~(j - 1)) << 1) | (t & (j - 1));
                int ixj = i | j;
                bool desc = ((i & k) == 0);
                float a = sv[i], c = sv[ixj];
                bool sw = desc ? (a < c) : (a > c);
                if (sw) { sv[i] = c; sv[ixj] = a; int ti = si[i]; si[i] = si[ixj]; si[ixj] = ti; }
            }
            __syncthreads();
        }
    }
    for (int u = threadIdx.x; u < UU; u += 1024) {
        g_topk[b * UP + u] = si[u];
        g_ulookup[b * LQ + si[u]] = u;
    }
}

// ---------------- softmax (single pass; max from scores partials) ----------------
__global__ __launch_bounds__(256) void k_softmax()
{
    int b = blockIdx.y, u = blockIdx.x, t = threadIdx.x;
    size_t off = (size_t)b * PER_BATCH + (size_t)u * LQ;
    bf16* eh = g_SEhi + off;
    bf16* el = g_SElo + off;
    if (u >= UU) {
        for (int l = t; l < LQ; l += 256) { eh[l] = __ushort_as_bfloat16(0); el[l] = __ushort_as_bfloat16(0); }
        if (t == 0) g_denom[b * UP + u] = 1.f;
        return;
    }
    const float* mp = g_smaxp + ((size_t)b * UP + u) * 16;
    float mx = -CUDART_INF_F;
    #pragma unroll
    for (int i = 0; i < 16; i++) mx = fmaxf(mx, mp[i]);

    const float* row = g_S + off;
    __shared__ float red[256];
    float sm = 0.f;
    for (int l = t; l < LQ; l += 256) {
        float e = expf(row[l] - mx);
        bf16 h = hi_of(e);
        eh[l] = h; el[l] = lo_of(e, h);
        sm += e;
    }
    red[t] = sm; __syncthreads();
    for (int o = 128; o; o >>= 1) { if (t < o) red[t] += red[t + o]; __syncthreads(); }
    if (t == 0) g_denom[b * UP + u] = red[0];
}

// ---------------- V column means ----------------
__global__ void k_vmean1()
{
    int b = blockIdx.y, c = blockIdx.x;
    const float* V = g_v + (size_t)b * PER_BATCH + (size_t)c * 256 * DD;
    int d = threadIdx.x;
    float acc = 0.f;
    #pragma unroll 4
    for (int l = 0; l < 256; l++) acc += V[l * DD + d];
    g_vpart[((size_t)b * 16 + c) * DD + d] = acc;
}
__global__ void k_vmean2()
{
    int b = blockIdx.x, d = threadIdx.x;
    float acc = 0.f;
    #pragma unroll
    for (int c = 0; c < 16; c++) acc += g_vpart[((size_t)b * 16 + c) * DD + d];
    g_vmean[b * DD + d] = acc * (1.0f / LQ);
}

// ---------------- fused output: vmean broadcast or (updA+updB)/denom ----------------
__global__ void k_output(float* __restrict__ out)
{
    int b = blockIdx.y, l = blockIdx.x, t = threadIdx.x;
    int u = g_ulookup[b * LQ + l];
    float4 r;
    if (u >= 0) {
        float inv = 1.f / g_denom[b * UP + u];
        float4 a = ((const float4*)(g_updA + ((size_t)b * UP + u) * DD))[t];
        float4 c = ((const float4*)(g_updB + ((size_t)b * UP + u) * DD))[t];
        r = make_float4((a.x + c.x) * inv, (a.y + c.y) * inv,
                        (a.z + c.z) * inv, (a.w + c.w) * inv);
    } else {
        r = ((const float4*)(g_vmean + (size_t)b * DD))[t];
    }
    ((float4*)(out + (size_t)b * PER_BATCH + (size_t)l * DD))[t] = r;
}

// ---------------- launch ----------------
extern "C" void kernel_launch(void* const* d_in, const int* in_sizes, int n_in,
                              void* d_out, int out_size)
{
    const float* in1 = (const float*)d_in[0];
    const float* in2 = (const float*)d_in[1];
    const float* Wq  = (const float*)d_in[2];
    const float* bq  = (const float*)d_in[3];
    const float* Wk  = (const float*)d_in[4];
    const float* bk  = (const float*)d_in[5];
    const float* Wv  = (const float*)d_in[6];
    const float* bv  = (const float*)d_in[7];
    const int*   idx = (const int*)d_in[8];
    float* out = (float*)d_out;

    cudaFuncSetAttribute(k_proj_qk, cudaFuncAttributeMaxDynamicSharedMemorySize, SM_TOTAL);
    cudaFuncSetAttribute(k_proj_v,  cudaFuncAttributeMaxDynamicSharedMemorySize, SM_TOTAL);
    cudaFuncSetAttribute(k_qks,     cudaFuncAttributeMaxDynamicSharedMemorySize, SM_TOTAL);
    cudaFuncSetAttribute(k_scores,  cudaFuncAttributeMaxDynamicSharedMemorySize, SM_TOTAL);
    cudaFuncSetAttribute(k_upd,     cudaFuncAttributeMaxDynamicSharedMemorySize, SM_TOTAL);

    k_convW<<<3072, 256>>>(Wq, Wk, Wv);
    k_convX<<<dim3(LQ / 32, CC / 32, NB), dim3(32, 8)>>>(in1, in2);

    k_proj_qk<<<dim3(LQ / 256, DD / 128, NB * 2), 256, SM_TOTAL>>>(bq, bk);
    k_proj_v <<<dim3(LQ / 256, DD / 128, NB),     256, SM_TOTAL>>>(bv);

    k_transV<<<dim3(DD / 32, LQ / 32, NB), dim3(32, 8)>>>();
    k_vmean1<<<dim3(16, NB), 512>>>();
    k_vmean2<<<NB, 512>>>();

    k_gather_ks<<<dim3(UP, NB), 128>>>(idx);
    k_qks<<<dim3(UP / 256, LQ / 128, NB), 256, SM_TOTAL>>>();
    k_topk<<<NB, 1024>>>();
    k_gather_qr<<<dim3(UP, NB), 128>>>();

    k_scores<<<dim3(LQ / 256, UP / 128, NB), 256, SM_TOTAL>>>();
    k_softmax<<<dim3(UP, NB), 256>>>();
    k_upd<<<dim3(DD / 256, UP / 128, NB * 2), 256, SM_TOTAL>>>();

    k_output<<<dim3(LQ, NB), 128>>>(out);
}

// round 12
// speedup vs baseline: 2.5359x; 1.0005x over previous
#include <cuda_runtime.h>
#include <cuda_bf16.h>
#include <math_constants.h>
#include <cstdint>
#include <mma.h>

using namespace nvcuda;

#define NB 16
#define LQ 4096          // L
#define DD 512           // D
#define CC 512           // 2*Cin
#define UU 450           // top-k count
#define UP 512           // padded U
#define PER_BATCH (LQ*DD)

typedef __nv_bfloat16 bf16;

// ---------------- device scratch ----------------
__device__ float g_v[(size_t)NB*PER_BATCH];     // proj-V flat [o][4096] == v[l][d]
__device__ float g_S[(size_t)NB*PER_BATCH];     // scores [u][4096] (fp32)
__device__ float g_updA[(size_t)NB*UP*DD];      // upd partial K half 0
__device__ float g_updB[(size_t)NB*UP*DD];      // upd partial K half 1
__device__ int   g_topk[NB*UP];
__device__ int   g_ulookup[NB*LQ];              // l -> u or -1
__device__ float2 g_Mpart[NB*LQ*2];             // qks fused max/sum partials (2 N-tiles)
__device__ float g_smaxp[NB*UP*16];             // scores fused row-max partials (16 N-tiles)
__device__ float g_vpart[NB*16*DD];
__device__ float g_vmean[NB*DD];
__device__ float g_denom[NB*UP];

__device__ __align__(16) bf16 g_Whi[3*DD*CC],            g_Wlo[3*DD*CC];
__device__ __align__(16) bf16 g_XThi[(size_t)NB*LQ*CC],  g_XTlo[(size_t)NB*LQ*CC];  // [s][c]
__device__ __align__(16) bf16 g_Qhi[(size_t)NB*LQ*DD],   g_Qlo[(size_t)NB*LQ*DD];   // flat: [o][4096] == q[l][d]
__device__ __align__(16) bf16 g_Khi[(size_t)NB*LQ*DD],   g_Klo[(size_t)NB*LQ*DD];   // flat
__device__ __align__(16) bf16 g_KShi[(size_t)NB*UP*DD],  g_KSlo[(size_t)NB*UP*DD];  // [s][d]
__device__ __align__(16) bf16 g_QRhi[(size_t)NB*UP*DD],  g_QRlo[(size_t)NB*UP*DD];  // [u][d]
__device__ __align__(16) bf16 g_SEhi[(size_t)NB*UP*LQ],  g_SElo[(size_t)NB*UP*LQ];  // [u][l]
__device__ __align__(16) bf16 g_VThi[(size_t)NB*DD*LQ],  g_VTlo[(size_t)NB*DD*LQ];  // [d][l]

// ---------------- helpers ----------------
__device__ __forceinline__ uint32_t smem_u32(const void* p) {
    uint32_t a;
    asm("{ .reg .u64 t; cvta.to.shared.u64 t, %1; cvt.u32.u64 %0, t; }" : "=r"(a) : "l"(p));
    return a;
}
__device__ __forceinline__ void cpa16(uint32_t dst, const void* src) {
    asm volatile("cp.async.cg.shared.global [%0], [%1], 16;" :: "r"(dst), "l"(src));
}
__device__ __forceinline__ void cp_commit() { asm volatile("cp.async.commit_group;" ::: "memory"); }
template<int N> __device__ __forceinline__ void cp_wait() {
    asm volatile("cp.async.wait_group %0;" :: "n"(N) : "memory");
}
__device__ __forceinline__ bf16 hi_of(float x) { return __float2bfloat16(x); }
__device__ __forceinline__ bf16 lo_of(float x, bf16 h) { return __float2bfloat16(x - __bfloat162float(h)); }

// ============================================================================
// wmma GEMM: CTA tile 128(M) x 256(N), BK=32, 8 warps (2M x 4N), warp 64x64,
// double-buffered cp.async. A [Mtot][lda] K-major hi/lo, B [Ntot][lda] hi/lo.
// NPROD=3: Ah*Bh + Ah*Bl + Al*Bh.  NPROD=2: Ah*Bh + Al*Bh (B hi only, Blo unloaded).
// KEXT = K extent of this pass; lda = row stride (supports K-split).
// EPI: 0 row-bias -> bf16 split | 1 row-bias -> fp32
//      2 qks: NO C write; masked (col<UU) row max/sum partials -> part(float2)
//      3 scores: alpha fp32 + row-max partials -> part(float)
//      4 plain fp32 (upd partial)
// ============================================================================
#define SA 48                     // smem row stride in halfs (96B)
#define ARR_A (128*SA*2)          // 12288 B
#define ARR_B (256*SA*2)          // 24576 B
#define STAGE (2*ARR_A + 2*ARR_B) // 73728 B
#define SM_TOTAL (2*STAGE)        // 147456 B (C-stage 128*260*4=133120 reuses)

template<int EPI, int NPROD>
__device__ __forceinline__ void gemm_wmma(
    const bf16* __restrict__ Ahi, const bf16* __restrict__ Alo,
    const bf16* __restrict__ Bhi, const bf16* __restrict__ Blo,
    int KEXT, int lda,
    float* __restrict__ C, bf16* __restrict__ Chi, bf16* __restrict__ Clo, int ldc,
    const float* __restrict__ aux, float alpha, float* __restrict__ part)
{
    extern __shared__ char sm[];
    const uint32_t smb = smem_u32(sm);
    const int tid = threadIdx.x, w = tid >> 5;
    const int mw = w >> 2, nw = w & 3;           // 2M x 4N warp grid
    const int m0 = blockIdx.y * 128, n0 = blockIdx.x * 256;
    const int NS = KEXT >> 5;

    wmma::fragment<wmma::accumulator, 16, 16, 16, float> fc[4][4];
    #pragma unroll
    for (int i = 0; i < 4; i++)
        #pragma unroll
        for (int j = 0; j < 4; j++) wmma::fill_fragment(fc[i][j], 0.f);

    auto load_stage = [&](int s, int bufb) {
        const int k0 = s << 5;
        const uint32_t base = smb + bufb * STAGE;
        #pragma unroll
        for (int q = 0; q < 2; q++) {
            const bf16* src = q ? Alo : Ahi;
            const uint32_t dst = base + q * ARR_A;
            #pragma unroll
            for (int c0 = 0; c0 < 512; c0 += 256) {
                int c = c0 + tid;
                int row = c >> 2, col = c & 3;
                cpa16(dst + row * 96 + col * 16,
                      src + (size_t)(m0 + row) * lda + k0 + col * 8);
            }
        }
        #pragma unroll
        for (int q = 0; q < 2; q++) {
            if (NPROD == 2 && q == 1) break;     // skip Blo entirely
            const bf16* src = q ? Blo : Bhi;
            const uint32_t dst = base + 2 * ARR_A + q * ARR_B;
            #pragma unroll
            for (int c0 = 0; c0 < 1024; c0 += 256) {
                int c = c0 + tid;
                int row = c >> 2, col = c & 3;
                cpa16(dst + row * 96 + col * 16,
                      src + (size_t)(n0 + row) * lda + k0 + col * 8);
            }
        }
        cp_commit();
    };

    load_stage(0, 0);

    for (int s = 0; s < NS; s++) {
        const int b = s & 1;
        if (s + 1 < NS) { load_stage(s + 1, b ^ 1); cp_wait<1>(); }
        else            { cp_wait<0>(); }
        __syncthreads();

        const bf16* sAh = (const bf16*)(sm + b * STAGE);
        const bf16* sAl = (const bf16*)(sm + b * STAGE + ARR_A);
        const bf16* sBh = (const bf16*)(sm + b * STAGE + 2 * ARR_A);
        const bf16* sBl = (const bf16*)(sm + b * STAGE + 2 * ARR_A + ARR_B);

        #pragma unroll
        for (int ks = 0; ks < 2; ks++) {
            wmma::fragment<wmma::matrix_a, 16, 16, 16, bf16, wmma::row_major> fah[4], fal[4];
            #pragma unroll
            for (int i = 0; i < 4; i++) {
                const int r = mw * 64 + i * 16;
                wmma::load_matrix_sync(fah[i], sAh + r * SA + ks * 16, SA);
                wmma::load_matrix_sync(fal[i], sAl + r * SA + ks * 16, SA);
            }
            #pragma unroll
            for (int j = 0; j < 4; j++) {
                wmma::fragment<wmma::matrix_b, 16, 16, 16, bf16, wmma::col_major> fbh, fbl;
                const int n = nw * 64 + j * 16;
                wmma::load_matrix_sync(fbh, sBh + n * SA + ks * 16, SA);
                if (NPROD == 3)
                    wmma::load_matrix_sync(fbl, sBl + n * SA + ks * 16, SA);
                #pragma unroll
                for (int i = 0; i < 4; i++) {
                    wmma::mma_sync(fc[i][j], fah[i], fbh, fc[i][j]);
                    if (NPROD == 3)
                        wmma::mma_sync(fc[i][j], fah[i], fbl, fc[i][j]);
                    wmma::mma_sync(fc[i][j], fal[i], fbh, fc[i][j]);
                }
            }
        }
        __syncthreads();
    }

    // ---- epilogue via smem C-stage (known layout), 128 x 260 fp32 ----
    float* csm = (float*)sm;
    #pragma unroll
    for (int i = 0; i < 4; i++)
        #pragma unroll
        for (int j = 0; j < 4; j++)
            wmma::store_matrix_sync(csm + (mw*64 + i*16) * 260 + nw*64 + j*16,
                                    fc[i][j], 260, wmma::mem_row_major);
    __syncthreads();

    const int r = tid >> 1, gm = m0 + r;
    const int cb0 = (tid & 1) * 128;
    const float* src = csm + r * 260 + cb0;

    if (EPI == 0) {                       // row bias -> bf16 hi/lo split
        const float add = aux[gm];
        #pragma unroll
        for (int g = 0; g < 4; g++) {
            ushort hs[32], ls[32];
            #pragma unroll
            for (int c = 0; c < 32; c++) {
                float v = src[g * 32 + c] + add;
                bf16 h = hi_of(v);
                hs[c] = __bfloat16_as_ushort(h);
                ls[c] = __bfloat16_as_ushort(lo_of(v, h));
            }
            bf16* ph = Chi + (size_t)gm * ldc + n0 + cb0 + g * 32;
            bf16* pl = Clo + (size_t)gm * ldc + n0 + cb0 + g * 32;
            #pragma unroll
            for (int j = 0; j < 4; j++) {
                *(uint4*)(ph + j * 8) = *(uint4*)&hs[j * 8];
                *(uint4*)(pl + j * 8) = *(uint4*)&ls[j * 8];
            }
        }
    } else if (EPI == 2) {                // qks: masked row max/sum, no C write
        float mx = -CUDART_INF_F, smv = 0.f;
        #pragma unroll 8
        for (int c = 0; c < 128; c++) {
            int scol = n0 + cb0 + c;
            if (scol < UU) { float v = src[c]; mx = fmaxf(mx, v); smv += v; }
        }
        float mx2 = fmaxf(mx, __shfl_xor_sync(0xffffffffu, mx, 1));
        float sm2 = smv + __shfl_xor_sync(0xffffffffu, smv, 1);
        if ((tid & 1) == 0)
            ((float2*)part)[gm * 2 + blockIdx.x] = make_float2(mx2, sm2);
    } else {
        float add = 0.f, mul = 1.f;
        if (EPI == 1) add = aux[gm];
        if (EPI == 3) mul = alpha;
        float* pc = C + (size_t)gm * ldc + n0 + cb0;
        float mx = -CUDART_INF_F;
        #pragma unroll
        for (int j = 0; j < 32; j++) {
            float4 v = *(const float4*)(src + j * 4);
            v.x = v.x * mul + add; v.y = v.y * mul + add;
            v.z = v.z * mul + add; v.w = v.w * mul + add;
            if (EPI == 3) mx = fmaxf(mx, fmaxf(fmaxf(v.x, v.y), fmaxf(v.z, v.w)));
            *(float4*)(pc + j * 4) = v;
        }
        if (EPI == 3) {
            float mx2 = fmaxf(mx, __shfl_xor_sync(0xffffffffu, mx, 1));
            if ((tid & 1) == 0) part[gm * 16 + blockIdx.x] = mx2;
        }
    }
}

// ---------------- GEMM wrappers (1 CTA/SM) ----------------
__global__ __launch_bounds__(256, 1) void k_proj_qk(const float* __restrict__ bq,
                                                    const float* __restrict__ bk)
{
    int z = blockIdx.z, mi = z >> 4, b = z & 15;
    gemm_wmma<0, 3>(g_Whi + (size_t)mi*DD*CC, g_Wlo + (size_t)mi*DD*CC,
                    g_XThi + (size_t)b*LQ*CC, g_XTlo + (size_t)b*LQ*CC, CC, CC,
                    nullptr,
                    (mi ? g_Khi : g_Qhi) + (size_t)b*PER_BATCH,
                    (mi ? g_Klo : g_Qlo) + (size_t)b*PER_BATCH, LQ,
                    mi ? bk : bq, 1.f, nullptr);
}
__global__ __launch_bounds__(256, 1) void k_proj_v(const float* __restrict__ bv)
{
    int b = blockIdx.z;
    gemm_wmma<1, 3>(g_Whi + (size_t)2*DD*CC, g_Wlo + (size_t)2*DD*CC,
                    g_XThi + (size_t)b*LQ*CC, g_XTlo + (size_t)b*LQ*CC, CC, CC,
                    g_v + (size_t)b*PER_BATCH, nullptr, nullptr, LQ,
                    bv, 1.f, nullptr);
}
// QKs fused: only max/sum partials, no matrix output (3-product: feeds top-k)
__global__ __launch_bounds__(256, 1) void k_qks()
{
    int b = blockIdx.z;
    gemm_wmma<2, 3>(g_Qhi + (size_t)b*PER_BATCH, g_Qlo + (size_t)b*PER_BATCH,
                    g_KShi + (size_t)b*UP*DD, g_KSlo + (size_t)b*UP*DD, DD, DD,
                    nullptr, nullptr, nullptr, UP, nullptr, 1.f,
                    (float*)(g_Mpart + (size_t)b*LQ*2));
}
// scores: 2-product (QR split x K_hi) — logit error ~4e-4, inside budget
__global__ __launch_bounds__(256, 1) void k_scores()
{
    int b = blockIdx.z;
    gemm_wmma<3, 2>(g_QRhi + (size_t)b*UP*DD, g_QRlo + (size_t)b*UP*DD,
                    g_Khi + (size_t)b*PER_BATCH, nullptr, DD, DD,
                    g_S + (size_t)b*PER_BATCH, nullptr, nullptr, LQ, nullptr,
                    0.044194173824159216f, g_smaxp + (size_t)b*UP*16);
}
// upd partial: K split in halves; z = half*16 + b
__global__ __launch_bounds__(256, 1) void k_upd()
{
    int z = blockIdx.z, h = z >> 4, b = z & 15;
    const size_t koff = (size_t)h * 2048;
    float* dst = (h ? g_updB : g_updA) + (size_t)b*UP*DD;
    gemm_wmma<4, 3>(g_SEhi + (size_t)b*UP*LQ + koff, g_SElo + (size_t)b*UP*LQ + koff,
                    g_VThi + (size_t)b*DD*LQ + koff, g_VTlo + (size_t)b*DD*LQ + koff,
                    2048, LQ,
                    dst, nullptr, nullptr, DD, nullptr, 1.f, nullptr);
}

// ---------------- conversions ----------------
__global__ void k_convW(const float* __restrict__ Wq, const float* __restrict__ Wk,
                        const float* __restrict__ Wv)
{
    int i = blockIdx.x * 256 + threadIdx.x;
    int mi = i >> 18, r = i & 262143;
    const float* W = (mi == 0) ? Wq : (mi == 1) ? Wk : Wv;
    float x = W[r];
    bf16 h = hi_of(x);
    g_Whi[i] = h; g_Wlo[i] = lo_of(x, h);
}

__global__ void k_convX(const float* __restrict__ in1, const float* __restrict__ in2)
{
    __shared__ float t[32][33];
    int b = blockIdx.z, s0 = blockIdx.x * 32, c0 = blockIdx.y * 32;
    const float* src = (c0 < 256) ? (in1 + ((size_t)b * 256 + c0) * LQ)
                                  : (in2 + ((size_t)b * 256 + (c0 - 256)) * LQ);
    for (int i = threadIdx.y; i < 32; i += 8)
        t[i][threadIdx.x] = src[(size_t)i * LQ + s0 + threadIdx.x];
    __syncthreads();
    for (int i = threadIdx.y; i < 32; i += 8) {
        float x = t[threadIdx.x][i];
        bf16 h = hi_of(x);
        size_t off = ((size_t)b * LQ + s0 + i) * CC + c0 + threadIdx.x;
        g_XThi[off] = h; g_XTlo[off] = lo_of(x, h);
    }
}

__global__ void k_transV()
{
    __shared__ float t[32][33];
    int b = blockIdx.z, d0 = blockIdx.x * 32, l0 = blockIdx.y * 32;
    const float* src = g_v + (size_t)b * PER_BATCH;
    for (int i = threadIdx.y; i < 32; i += 8)
        t[i][threadIdx.x] = src[(size_t)(l0 + i) * DD + d0 + threadIdx.x];
    __syncthreads();
    for (int i = threadIdx.y; i < 32; i += 8) {
        float x = t[threadIdx.x][i];
        bf16 h = hi_of(x);
        size_t off = ((size_t)b * DD + d0 + i) * LQ + l0 + threadIdx.x;
        g_VThi[off] = h; g_VTlo[off] = lo_of(x, h);
    }
}

// ---------------- gathers ----------------
__global__ void k_gather_ks(const int* __restrict__ idx)
{
    int b = blockIdx.y, s = blockIdx.x, t = threadIdx.x;
    size_t drow = ((size_t)b * UP + s) * DD;
    uint2* dh = (uint2*)(g_KShi + drow);
    uint2* dl = (uint2*)(g_KSlo + drow);
    if (s < UU) {
        size_t srow = ((size_t)b * LQ + idx[s]) * DD;
        dh[t] = ((const uint2*)(g_Khi + srow))[t];
        dl[t] = ((const uint2*)(g_Klo + srow))[t];
    } else {
        dh[t] = make_uint2(0, 0); dl[t] = make_uint2(0, 0);
    }
}
__global__ void k_gather_qr()
{
    int b = blockIdx.y, u = blockIdx.x, t = threadIdx.x;
    size_t drow = ((size_t)b * UP + u) * DD;
    uint2* dh = (uint2*)(g_QRhi + drow);
    uint2* dl = (uint2*)(g_QRlo + drow);
    if (u < UU) {
        size_t srow = ((size_t)b * LQ + g_topk[b * UP + u]) * DD;
        dh[t] = ((const uint2*)(g_Qhi + srow))[t];
        dl[t] = ((const uint2*)(g_Qlo + srow))[t];
    } else {
        dh[t] = make_uint2(0, 0); dl[t] = make_uint2(0, 0);
    }
}

// ---------------- top-k (M from qks partials) + inverse lookup ----------------
__global__ __launch_bounds__(1024) void k_topk()
{
    __shared__ float sv[LQ];
    __shared__ int   si[LQ];
    int b = blockIdx.x;
    for (int i = threadIdx.x; i < LQ; i += 1024) {
        float2 p0 = g_Mpart[(size_t)(b * LQ + i) * 2 + 0];
        float2 p1 = g_Mpart[(size_t)(b * LQ + i) * 2 + 1];
        sv[i] = fmaxf(p0.x, p1.x) - (p0.y + p1.y) * (1.0f / LQ);
        si[i] = i;
        g_ulookup[b * LQ + i] = -1;
    }
    __syncthreads();
    for (int k = 2; k <= LQ; k <<= 1) {
        for (int j = k >> 1; j > 0; j >>= 1) {
            for (int t = threadIdx.x; t < LQ / 2; t += 1024) {
                int i = ((t & ~(j - 1)) << 1) | (t & (j - 1));
                int ixj = i | j;
                bool desc = ((i & k) == 0);
                float a = sv[i], c = sv[ixj];
                bool sw = desc ? (a < c) : (a > c);
                if (sw) { sv[i] = c; sv[ixj] = a; int ti = si[i]; si[i] = si[ixj]; si[ixj] = ti; }
            }
            __syncthreads();
        }
    }
    for (int u = threadIdx.x; u < UU; u += 1024) {
        g_topk[b * UP + u] = si[u];
        g_ulookup[b * LQ + si[u]] = u;
    }
}

// ---------------- softmax (single pass; max from scores partials) ----------------
__global__ __launch_bounds__(256) void k_softmax()
{
    int b = blockIdx.y, u = blockIdx.x, t = threadIdx.x;
    size_t off = (size_t)b * PER_BATCH + (size_t)u * LQ;
    bf16* eh = g_SEhi + off;
    bf16* el = g_SElo + off;
    if (u >= UU) {
        for (int l = t; l < LQ; l += 256) { eh[l] = __ushort_as_bfloat16(0); el[l] = __ushort_as_bfloat16(0); }
        if (t == 0) g_denom[b * UP + u] = 1.f;
        return;
    }
    const float* mp = g_smaxp + ((size_t)b * UP + u) * 16;
    float mx = -CUDART_INF_F;
    #pragma unroll
    for (int i = 0; i < 16; i++) mx = fmaxf(mx, mp[i]);

    const float* row = g_S + off;
    __shared__ float red[256];
    float sm = 0.f;
    for (int l = t; l < LQ; l += 256) {
        float e = expf(row[l] - mx);
        bf16 h = hi_of(e);
        eh[l] = h; el[l] = lo_of(e, h);
        sm += e;
    }
    red[t] = sm; __syncthreads();
    for (int o = 128; o; o >>= 1) { if (t < o) red[t] += red[t + o]; __syncthreads(); }
    if (t == 0) g_denom[b * UP + u] = red[0];
}

// ---------------- V column means ----------------
__global__ void k_vmean1()
{
    int b = blockIdx.y, c = blockIdx.x;
    const float* V = g_v + (size_t)b * PER_BATCH + (size_t)c * 256 * DD;
    int d = threadIdx.x;
    float acc = 0.f;
    #pragma unroll 4
    for (int l = 0; l < 256; l++) acc += V[l * DD + d];
    g_vpart[((size_t)b * 16 + c) * DD + d] = acc;
}
__global__ void k_vmean2()
{
    int b = blockIdx.x, d = threadIdx.x;
    float acc = 0.f;
    #pragma unroll
    for (int c = 0; c < 16; c++) acc += g_vpart[((size_t)b * 16 + c) * DD + d];
    g_vmean[b * DD + d] = acc * (1.0f / LQ);
}

// ---------------- fused output: vmean broadcast or (updA+updB)/denom ----------------
__global__ void k_output(float* __restrict__ out)
{
    int b = blockIdx.y, l = blockIdx.x, t = threadIdx.x;
    int u = g_ulookup[b * LQ + l];
    float4 r;
    if (u >= 0) {
        float inv = 1.f / g_denom[b * UP + u];
        float4 a = ((const float4*)(g_updA + ((size_t)b * UP + u) * DD))[t];
        float4 c = ((const float4*)(g_updB + ((size_t)b * UP + u) * DD))[t];
        r = make_float4((a.x + c.x) * inv, (a.y + c.y) * inv,
                        (a.z + c.z) * inv, (a.w + c.w) * inv);
    } else {
        r = ((const float4*)(g_vmean + (size_t)b * DD))[t];
    }
    ((float4*)(out + (size_t)b * PER_BATCH + (size_t)l * DD))[t] = r;
}

// ---------------- launch ----------------
extern "C" void kernel_launch(void* const* d_in, const int* in_sizes, int n_in,
                              void* d_out, int out_size)
{
    const float* in1 = (const float*)d_in[0];
    const float* in2 = (const float*)d_in[1];
    const float* Wq  = (const float*)d_in[2];
    const float* bq  = (const float*)d_in[3];
    const float* Wk  = (const float*)d_in[4];
    const float* bk  = (const float*)d_in[5];
    const float* Wv  = (const float*)d_in[6];
    const float* bv  = (const float*)d_in[7];
    const int*   idx = (const int*)d_in[8];
    float* out = (float*)d_out;

    cudaFuncSetAttribute(k_proj_qk, cudaFuncAttributeMaxDynamicSharedMemorySize, SM_TOTAL);
    cudaFuncSetAttribute(k_proj_v,  cudaFuncAttributeMaxDynamicSharedMemorySize, SM_TOTAL);
    cudaFuncSetAttribute(k_qks,     cudaFuncAttributeMaxDynamicSharedMemorySize, SM_TOTAL);
    cudaFuncSetAttribute(k_scores,  cudaFuncAttributeMaxDynamicSharedMemorySize, SM_TOTAL);
    cudaFuncSetAttribute(k_upd,     cudaFuncAttributeMaxDynamicSharedMemorySize, SM_TOTAL);

    k_convW<<<3072, 256>>>(Wq, Wk, Wv);
    k_convX<<<dim3(LQ / 32, CC / 32, NB), dim3(32, 8)>>>(in1, in2);

    k_proj_qk<<<dim3(LQ / 256, DD / 128, NB * 2), 256, SM_TOTAL>>>(bq, bk);
    k_proj_v <<<dim3(LQ / 256, DD / 128, NB),     256, SM_TOTAL>>>(bv);

    k_transV<<<dim3(DD / 32, LQ / 32, NB), dim3(32, 8)>>>();
    k_vmean1<<<dim3(16, NB), 512>>>();
    k_vmean2<<<NB, 512>>>();

    k_gather_ks<<<dim3(UP, NB), 128>>>(idx);
    k_qks<<<dim3(UP / 256, LQ / 128, NB), 256, SM_TOTAL>>>();
    k_topk<<<NB, 1024>>>();
    k_gather_qr<<<dim3(UP, NB), 128>>>();

    k_scores<<<dim3(LQ / 256, UP / 128, NB), 256, SM_TOTAL>>>();
    k_softmax<<<dim3(UP, NB), 256>>>();
    k_upd<<<dim3(DD / 256, UP / 128, NB * 2), 256, SM_TOTAL>>>();

    k_output<<<dim3(LQ, NB), 128>>>(out);
}